// round 5
// baseline (speedup 1.0000x reference)
#include <cuda_runtime.h>
#include <cuda_bf16.h>
#include <math.h>
#include <stdint.h>

#define DMODEL 768
#define NHEAD  12
#define DH     64
#define TAU    300.0f
#define INV_TAU (1.0f / 300.0f)
#define NEGV   (-1e9f)
#define SCALE  0.125f   /* 1/sqrt(64) */

#define MAXM (64 * 512)
#define WSZ  (DMODEL * DMODEL)

__device__ float g_Q[MAXM * DMODEL];
__device__ float g_K[MAXM * DMODEL];
__device__ float g_V[MAXM * DMODEL];
__device__ float g_O[MAXM * DMODEL];
// bf16 hi/lo split scratch: tokens (then reused for attn-out), 4 weight mats
__device__ __nv_bfloat16 g_th[MAXM * DMODEL];
__device__ __nv_bfloat16 g_tl[MAXM * DMODEL];
__device__ __nv_bfloat16 g_wh[4 * WSZ];
__device__ __nv_bfloat16 g_wl[4 * WSZ];

// ===========================================================================
// mma.sync / ldmatrix helpers (HMMA path on sm_103a)
// ===========================================================================
__device__ __forceinline__ uint32_t smem_u32(const void* p) {
    uint32_t a;
    asm("{ .reg .u64 t; cvta.to.shared.u64 t, %1; cvt.u32.u64 %0, t; }"
        : "=r"(a) : "l"(p));
    return a;
}

__device__ __forceinline__ void ldsm4(uint32_t* r, uint32_t addr) {
    asm volatile("ldmatrix.sync.aligned.m8n8.x4.shared.b16 {%0,%1,%2,%3}, [%4];"
                 : "=r"(r[0]), "=r"(r[1]), "=r"(r[2]), "=r"(r[3]) : "r"(addr));
}

__device__ __forceinline__ void mma16816(float* c, const uint32_t* a,
                                         const uint32_t* b) {
    asm volatile(
        "mma.sync.aligned.m16n8k16.row.col.f32.bf16.bf16.f32 "
        "{%0,%1,%2,%3}, {%4,%5,%6,%7}, {%8,%9}, {%0,%1,%2,%3};"
        : "+f"(c[0]), "+f"(c[1]), "+f"(c[2]), "+f"(c[3])
        : "r"(a[0]), "r"(a[1]), "r"(a[2]), "r"(a[3]), "r"(b[0]), "r"(b[1]));
}

__device__ __forceinline__ void split4(float4 v, uint2& h, uint2& l) {
    __nv_bfloat16 h0 = __float2bfloat16_rn(v.x);
    __nv_bfloat16 h1 = __float2bfloat16_rn(v.y);
    __nv_bfloat16 h2 = __float2bfloat16_rn(v.z);
    __nv_bfloat16 h3 = __float2bfloat16_rn(v.w);
    __nv_bfloat16 l0 = __float2bfloat16_rn(v.x - __bfloat162float(h0));
    __nv_bfloat16 l1 = __float2bfloat16_rn(v.y - __bfloat162float(h1));
    __nv_bfloat16 l2 = __float2bfloat16_rn(v.z - __bfloat162float(h2));
    __nv_bfloat16 l3 = __float2bfloat16_rn(v.w - __bfloat162float(h3));
    h.x = (uint32_t)__bfloat16_as_ushort(h0) | ((uint32_t)__bfloat16_as_ushort(h1) << 16);
    h.y = (uint32_t)__bfloat16_as_ushort(h2) | ((uint32_t)__bfloat16_as_ushort(h3) << 16);
    l.x = (uint32_t)__bfloat16_as_ushort(l0) | ((uint32_t)__bfloat16_as_ushort(l1) << 16);
    l.y = (uint32_t)__bfloat16_as_ushort(l2) | ((uint32_t)__bfloat16_as_ushort(l3) << 16);
}

__device__ __forceinline__ uint32_t pack_bf16(float a, float b) {
    __nv_bfloat162 t = __floats2bfloat162_rn(a, b);
    return *(uint32_t*)&t;
}
__device__ __forceinline__ void split2(float a, float b, uint32_t& h, uint32_t& l) {
    __nv_bfloat16 ha = __float2bfloat16_rn(a);
    __nv_bfloat16 hb = __float2bfloat16_rn(b);
    float la = a - __bfloat162float(ha);
    float lb = b - __bfloat162float(hb);
    h = (uint32_t)__bfloat16_as_ushort(ha) | ((uint32_t)__bfloat16_as_ushort(hb) << 16);
    l = pack_bf16(la, lb);
}

// ===========================================================================
// elementwise f32 -> bf16 hi/lo split
// ===========================================================================
__global__ __launch_bounds__(256) void split_f32(
    const float* __restrict__ X, __nv_bfloat16* __restrict__ Xh,
    __nv_bfloat16* __restrict__ Xl, int n4)
{
    int i = blockIdx.x * blockDim.x + threadIdx.x;
    if (i < n4) {
        float4 v = ((const float4*)X)[i];
        uint2 h, l;
        split4(v, h, l);
        ((uint2*)Xh)[i] = h;
        ((uint2*)Xl)[i] = l;
    }
}

// ===========================================================================
// HMMA GEMM on pre-split bf16 inputs: C = A @ W^T + bias, opt * mask.
// CTA 128x128, BK=32, 256 threads. Split terms issued as separate sweeps
// over all 16 accumulators (RAW distance 16).
// ===========================================================================
#define GBM 128
#define GBN 128
#define GBK 32
#define GPITCH 40   /* bf16 elems per smem row (80 bytes) */

__global__ __launch_bounds__(256, 1) void gemm_tc(
    const __nv_bfloat16* __restrict__ Ahg, const __nv_bfloat16* __restrict__ Alg,
    const __nv_bfloat16* __restrict__ Whg, const __nv_bfloat16* __restrict__ Wlg,
    const float* __restrict__ bias, const float* __restrict__ maskp,
    float* __restrict__ C, int M, int N, int K)
{
    __shared__ __nv_bfloat16 Ah[GBM * GPITCH], Al[GBM * GPITCH];
    __shared__ __nv_bfloat16 Bh[GBN * GPITCH], Bl[GBN * GPITCH];
    __shared__ float bias_s[GBN];

    const int t = threadIdx.x;
    const int wid = t >> 5, lane = t & 31;
    const int n0 = blockIdx.x * GBN;
    const int m0 = blockIdx.y * GBM;

    if (t < GBN) bias_s[t] = bias[n0 + t];

    // loader: thread t handles row r of (hi|lo per `half`) for both A and B
    const int r = t & 127, half = t >> 7;
    const __nv_bfloat16* Asrc = (half ? Alg : Ahg) + (size_t)(m0 + r) * K;
    const __nv_bfloat16* Wsrc = (half ? Wlg : Whg) + (size_t)(n0 + r) * K;
    __nv_bfloat16* As_d = half ? Al : Ah;
    __nv_bfloat16* Bs_d = half ? Bl : Bh;

    uint4 pa[2], pb[2];
    const int NITER = K / GBK;
#pragma unroll
    for (int j = 0; j < 2; j++) {
        pa[j] = *(const uint4*)(Asrc + j * 16);
        pb[j] = *(const uint4*)(Wsrc + j * 16);
    }
    uint4 pa2[2], pb2[2];
#pragma unroll
    for (int j = 0; j < 2; j++) {
        pa2[j] = *(const uint4*)(Asrc + j * 16 + 8);
        pb2[j] = *(const uint4*)(Wsrc + j * 16 + 8);
    }

    const int wm = wid >> 2;
    const int wn = wid & 3;
    const uint32_t ah_s = smem_u32(Ah), al_s = smem_u32(Al);
    const uint32_t bh_s = smem_u32(Bh), bl_s = smem_u32(Bl);
    const int a_row = lane & 15;
    const int a_chk = (lane >> 4) & 1;
    const int b_n   = (lane & 7) + ((lane >> 4) & 1) * 8;
    const int b_chk = (lane >> 3) & 1;

    float acc[4][4][4];
#pragma unroll
    for (int mi = 0; mi < 4; mi++)
#pragma unroll
        for (int ni = 0; ni < 4; ni++)
#pragma unroll
            for (int j = 0; j < 4; j++) acc[mi][ni][j] = 0.0f;

    for (int it = 0; it < NITER; it++) {
        // row r: 32 bf16 = 4 x uint4 (two held in pa, two in pa2)
        *(uint4*)&As_d[r * GPITCH + 0]  = pa[0];
        *(uint4*)&As_d[r * GPITCH + 8]  = pa2[0];
        *(uint4*)&As_d[r * GPITCH + 16] = pa[1];
        *(uint4*)&As_d[r * GPITCH + 24] = pa2[1];
        *(uint4*)&Bs_d[r * GPITCH + 0]  = pb[0];
        *(uint4*)&Bs_d[r * GPITCH + 8]  = pb2[0];
        *(uint4*)&Bs_d[r * GPITCH + 16] = pb[1];
        *(uint4*)&Bs_d[r * GPITCH + 24] = pb2[1];
        __syncthreads();

        if (it + 1 < NITER) {
            const __nv_bfloat16* An = Asrc + (it + 1) * GBK;
            const __nv_bfloat16* Wn = Wsrc + (it + 1) * GBK;
#pragma unroll
            for (int j = 0; j < 2; j++) {
                pa[j]  = *(const uint4*)(An + j * 16);
                pb[j]  = *(const uint4*)(Wn + j * 16);
                pa2[j] = *(const uint4*)(An + j * 16 + 8);
                pb2[j] = *(const uint4*)(Wn + j * 16 + 8);
            }
        }

#pragma unroll
        for (int s = 0; s < 2; s++) {
            uint32_t bhf[8], blf[8];
#pragma unroll
            for (int nt = 0; nt < 2; nt++) {
                uint32_t boff = (uint32_t)(wn * 32 + nt * 16 + b_n) * 80
                              + s * 32 + b_chk * 16;
                ldsm4(bhf + nt * 4, bh_s + boff);
                ldsm4(blf + nt * 4, bl_s + boff);
            }
            uint32_t ahf[4][4], alf[4][4];
#pragma unroll
            for (int mi = 0; mi < 4; mi++) {
                uint32_t aoff = (uint32_t)(wm * 64 + mi * 16 + a_row) * 80
                              + s * 32 + a_chk * 16;
                ldsm4(ahf[mi], ah_s + aoff);
                ldsm4(alf[mi], al_s + aoff);
            }
            // term sweeps: same-acc RAW distance = 16 MMAs
#pragma unroll
            for (int mi = 0; mi < 4; mi++)
#pragma unroll
                for (int ni = 0; ni < 4; ni++)
                    mma16816(acc[mi][ni], ahf[mi], bhf + ni * 2);
#pragma unroll
            for (int mi = 0; mi < 4; mi++)
#pragma unroll
                for (int ni = 0; ni < 4; ni++)
                    mma16816(acc[mi][ni], ahf[mi], blf + ni * 2);
#pragma unroll
            for (int mi = 0; mi < 4; mi++)
#pragma unroll
                for (int ni = 0; ni < 4; ni++)
                    mma16816(acc[mi][ni], alf[mi], bhf + ni * 2);
        }
        __syncthreads();
    }

    const int r0 = lane >> 2;
    const int c0 = (lane & 3) * 2;
#pragma unroll
    for (int mi = 0; mi < 4; mi++) {
        int mA = m0 + wm * 64 + mi * 16 + r0;
        int mB = mA + 8;
        float mkA = maskp ? maskp[mA] : 1.0f;
        float mkB = maskp ? maskp[mB] : 1.0f;
#pragma unroll
        for (int ni = 0; ni < 4; ni++) {
            int n = wn * 32 + ni * 8 + c0;
            float b0 = bias_s[n], b1 = bias_s[n + 1];
            float2 vA, vB;
            vA.x = (acc[mi][ni][0] + b0) * mkA;
            vA.y = (acc[mi][ni][1] + b1) * mkA;
            vB.x = (acc[mi][ni][2] + b0) * mkB;
            vB.y = (acc[mi][ni][3] + b1) * mkB;
            *(float2*)&C[(size_t)mA * N + n0 + n] = vA;
            *(float2*)&C[(size_t)mB * N + n0 + n] = vB;
        }
    }
}

// ===========================================================================
// Tensor-core flash attention (R4 validated mappings; MMA loops reordered
// so split terms sweep all 8 accumulators -> RAW distance 8).
// ===========================================================================
#define APITCH 72
#define A_QH 0
#define A_QL 18432
#define A_KH 36864
#define A_KL 46080
#define A_VH 55296
#define A_VL 64512
#define A_TK 73728
#define A_MK 73984
#define A_SMEM_TOTAL 74240

__global__ __launch_bounds__(256, 1) void attn_tc(
    const float* __restrict__ Q, const float* __restrict__ K,
    const float* __restrict__ V, const float* __restrict__ ts,
    const float* __restrict__ maskp, float* __restrict__ O, int L)
{
    extern __shared__ char smem[];
    __nv_bfloat16* Qh = (__nv_bfloat16*)(smem + A_QH);
    __nv_bfloat16* Ql = (__nv_bfloat16*)(smem + A_QL);
    __nv_bfloat16* Kh = (__nv_bfloat16*)(smem + A_KH);
    __nv_bfloat16* Kl = (__nv_bfloat16*)(smem + A_KL);
    __nv_bfloat16* Vh = (__nv_bfloat16*)(smem + A_VH);   // [d][key]
    __nv_bfloat16* Vl = (__nv_bfloat16*)(smem + A_VL);
    float* tks = (float*)(smem + A_TK);
    float* mks = (float*)(smem + A_MK);

    const int t = threadIdx.x, w = t >> 5, lane = t & 31;
    const int q0 = blockIdx.x * 128, h = blockIdx.y, n = blockIdx.z;
    const size_t base = (size_t)n * L * DMODEL + (size_t)h * DH;

    for (int idx = t; idx < 128 * 16; idx += 256) {
        int row = idx >> 4, q4 = idx & 15;
        float4 v = *(const float4*)(Q + base + (size_t)(q0 + row) * DMODEL + q4 * 4);
        v.x *= SCALE; v.y *= SCALE; v.z *= SCALE; v.w *= SCALE;
        uint2 hh, ll;
        split4(v, hh, ll);
        *(uint2*)&Qh[row * APITCH + q4 * 4] = hh;
        *(uint2*)&Ql[row * APITCH + q4 * 4] = ll;
    }
    __syncthreads();

    const int a_row = lane & 15, a_chk = (lane >> 4) & 1;
    const uint32_t qh_s = smem_u32(Qh), ql_s = smem_u32(Ql);
    uint32_t qhf[4][4], qlf[4][4];
#pragma unroll
    for (int ks = 0; ks < 4; ks++) {
        uint32_t aoff = (uint32_t)(w * 16 + a_row) * 144 + ks * 32 + a_chk * 16;
        ldsm4(qhf[ks], qh_s + aoff);
        ldsm4(qlf[ks], ql_s + aoff);
    }

    const int r0 = lane >> 2, c2 = (lane & 3) * 2;
    const float tq0 = ts[n * L + q0 + w * 16 + r0];
    const float tq1 = ts[n * L + q0 + w * 16 + r0 + 8];

    float o[8][4];
#pragma unroll
    for (int i = 0; i < 8; i++)
#pragma unroll
        for (int j = 0; j < 4; j++) o[i][j] = 0.0f;
    float m0 = -1e30f, m1 = -1e30f, l0 = 0.0f, l1 = 0.0f;

    const uint32_t kh_s = smem_u32(Kh), kl_s = smem_u32(Kl);
    const uint32_t vh_s = smem_u32(Vh), vl_s = smem_u32(Vl);
    const int b_n = (lane & 7) + ((lane >> 4) & 1) * 8;
    const int b_chk = (lane >> 3) & 1;

    const int nchunk = L / 64;
    for (int c = 0; c < nchunk; c++) {
        const int k0 = c * 64;
        __syncthreads();
        for (int idx = t; idx < 64 * 16; idx += 256) {
            int row = idx >> 4, q4 = idx & 15;
            float4 v = *(const float4*)(K + base + (size_t)(k0 + row) * DMODEL + q4 * 4);
            uint2 hh, ll;
            split4(v, hh, ll);
            *(uint2*)&Kh[row * APITCH + q4 * 4] = hh;
            *(uint2*)&Kl[row * APITCH + q4 * 4] = ll;
        }
        {
            const int d = t & 63, kg = t >> 6;
            uint32_t hbuf[8], lbuf[8];
#pragma unroll
            for (int i = 0; i < 8; i++) {
                float va = V[base + (size_t)(k0 + kg * 16 + 2 * i)     * DMODEL + d];
                float vb = V[base + (size_t)(k0 + kg * 16 + 2 * i + 1) * DMODEL + d];
                split2(va, vb, hbuf[i], lbuf[i]);
            }
#pragma unroll
            for (int i = 0; i < 4; i++) {
                uint2 hh = make_uint2(hbuf[2 * i], hbuf[2 * i + 1]);
                uint2 ll = make_uint2(lbuf[2 * i], lbuf[2 * i + 1]);
                *(uint2*)&Vh[d * APITCH + kg * 16 + i * 4] = hh;
                *(uint2*)&Vl[d * APITCH + kg * 16 + i * 4] = ll;
            }
        }
        if (t < 64) {
            tks[t] = ts[n * L + k0 + t];
            mks[t] = maskp[n * L + k0 + t];
        }
        __syncthreads();

        // ---- S = Q K^T : per k-step, hoist K frags then 3 term sweeps ----
        float S[8][4];
#pragma unroll
        for (int i = 0; i < 8; i++)
#pragma unroll
            for (int j = 0; j < 4; j++) S[i][j] = 0.0f;
#pragma unroll
        for (int ks = 0; ks < 4; ks++) {
            uint32_t khf[16], klf[16];
#pragma unroll
            for (int g = 0; g < 4; g++) {
                uint32_t boff = (uint32_t)(g * 16 + b_n) * 144 + ks * 32 + b_chk * 16;
                ldsm4(khf + g * 4, kh_s + boff);
                ldsm4(klf + g * 4, kl_s + boff);
            }
#pragma unroll
            for (int g = 0; g < 4; g++)
#pragma unroll
                for (int ni = 0; ni < 2; ni++)
                    mma16816(S[g * 2 + ni], qhf[ks], khf + g * 4 + ni * 2);
#pragma unroll
            for (int g = 0; g < 4; g++)
#pragma unroll
                for (int ni = 0; ni < 2; ni++)
                    mma16816(S[g * 2 + ni], qhf[ks], klf + g * 4 + ni * 2);
#pragma unroll
            for (int g = 0; g < 4; g++)
#pragma unroll
                for (int ni = 0; ni < 2; ni++)
                    mma16816(S[g * 2 + ni], qlf[ks], khf + g * 4 + ni * 2);
        }

        // ---- bias + mask + online softmax ----
        float cm0 = -1e30f, cm1 = -1e30f;
#pragma unroll
        for (int nt = 0; nt < 8; nt++) {
#pragma unroll
            for (int j = 0; j < 2; j++) {
                int key = nt * 8 + c2 + j;
                float tk = tks[key];
                bool ok = mks[key] > 0.0f;
                float bA = -fabsf(tq0 - tk) * INV_TAU;
                float bB = -fabsf(tq1 - tk) * INV_TAU;
                S[nt][j]     = ok ? S[nt][j]     + bA : NEGV;
                S[nt][j + 2] = ok ? S[nt][j + 2] + bB : NEGV;
                cm0 = fmaxf(cm0, S[nt][j]);
                cm1 = fmaxf(cm1, S[nt][j + 2]);
            }
        }
#pragma unroll
        for (int off = 1; off <= 2; off <<= 1) {
            cm0 = fmaxf(cm0, __shfl_xor_sync(0xffffffffu, cm0, off));
            cm1 = fmaxf(cm1, __shfl_xor_sync(0xffffffffu, cm1, off));
        }
        float nm0 = fmaxf(m0, cm0), nm1 = fmaxf(m1, cm1);
        float cr0 = __expf(m0 - nm0), cr1 = __expf(m1 - nm1);
        m0 = nm0; m1 = nm1;

        float ps0 = 0.0f, ps1 = 0.0f;
#pragma unroll
        for (int nt = 0; nt < 8; nt++) {
            float p00 = __expf(S[nt][0] - nm0);
            float p01 = __expf(S[nt][1] - nm0);
            float p10 = __expf(S[nt][2] - nm1);
            float p11 = __expf(S[nt][3] - nm1);
            ps0 += p00 + p01; ps1 += p10 + p11;
            S[nt][0] = p00; S[nt][1] = p01; S[nt][2] = p10; S[nt][3] = p11;
        }
#pragma unroll
        for (int off = 1; off <= 2; off <<= 1) {
            ps0 += __shfl_xor_sync(0xffffffffu, ps0, off);
            ps1 += __shfl_xor_sync(0xffffffffu, ps1, off);
        }
        l0 = l0 * cr0 + ps0;
        l1 = l1 * cr1 + ps1;

#pragma unroll
        for (int i = 0; i < 8; i++) {
            o[i][0] *= cr0; o[i][1] *= cr0;
            o[i][2] *= cr1; o[i][3] *= cr1;
        }

        // ---- O += P V : hoist V frags per kt, then 3 term sweeps ----
#pragma unroll
        for (int kt = 0; kt < 4; kt++) {
            uint32_t pah[4], pal[4];
            split2(S[2 * kt][0],     S[2 * kt][1],     pah[0], pal[0]);
            split2(S[2 * kt][2],     S[2 * kt][3],     pah[1], pal[1]);
            split2(S[2 * kt + 1][0], S[2 * kt + 1][1], pah[2], pal[2]);
            split2(S[2 * kt + 1][2], S[2 * kt + 1][3], pah[3], pal[3]);
            uint32_t vhf[16], vlf[16];
#pragma unroll
            for (int g = 0; g < 4; g++) {
                uint32_t boff = (uint32_t)(g * 16 + b_n) * 144 + kt * 32 + b_chk * 16;
                ldsm4(vhf + g * 4, vh_s + boff);
                ldsm4(vlf + g * 4, vl_s + boff);
            }
#pragma unroll
            for (int g = 0; g < 4; g++)
#pragma unroll
                for (int ni = 0; ni < 2; ni++)
                    mma16816(o[g * 2 + ni], pah, vhf + g * 4 + ni * 2);
#pragma unroll
            for (int g = 0; g < 4; g++)
#pragma unroll
                for (int ni = 0; ni < 2; ni++)
                    mma16816(o[g * 2 + ni], pal, vhf + g * 4 + ni * 2);
#pragma unroll
            for (int g = 0; g < 4; g++)
#pragma unroll
                for (int ni = 0; ni < 2; ni++)
                    mma16816(o[g * 2 + ni], pah, vlf + g * 4 + ni * 2);
        }
    }

    const float inv0 = 1.0f / l0, inv1 = 1.0f / l1;
    const int gr0 = q0 + w * 16 + r0, gr1 = gr0 + 8;
#pragma unroll
    for (int ntd = 0; ntd < 8; ntd++) {
        int d = ntd * 8 + c2;
        float2 vA = make_float2(o[ntd][0] * inv0, o[ntd][1] * inv0);
        float2 vB = make_float2(o[ntd][2] * inv1, o[ntd][3] * inv1);
        *(float2*)&O[base + (size_t)gr0 * DMODEL + d] = vA;
        *(float2*)&O[base + (size_t)gr1 * DMODEL + d] = vB;
    }
}

// ---------------------------------------------------------------------------
// Readout pooling: one block per (head, batch). X = masked projected output.
// ---------------------------------------------------------------------------
__global__ __launch_bounds__(256) void pool_kernel(
    const float* __restrict__ X, const float* __restrict__ readout,
    const float* __restrict__ maskp, float* __restrict__ out, int L)
{
    __shared__ float s[512];
    __shared__ float qsh[64];
    __shared__ float red[8];
    __shared__ float part[8][64];
    const int h = blockIdx.x, n = blockIdx.y;
    const int t = threadIdx.x, w = t >> 5, lane = t & 31;
    if (t < 64) qsh[t] = readout[h * DH + t] * SCALE;
    __syncthreads();
    const size_t base = (size_t)n * L * DMODEL + (size_t)h * DH;

    for (int k = w; k < L; k += 8) {
        float d = X[base + (size_t)k * DMODEL + lane] * qsh[lane]
                + X[base + (size_t)k * DMODEL + lane + 32] * qsh[lane + 32];
#pragma unroll
        for (int o = 16; o > 0; o >>= 1) d += __shfl_xor_sync(0xffffffffu, d, o);
        if (lane == 0) s[k] = (maskp[n * L + k] > 0.f) ? d : NEGV;
    }
    __syncthreads();

    float lm = -1e30f;
    for (int k = t; k < L; k += 256) lm = fmaxf(lm, s[k]);
#pragma unroll
    for (int o = 16; o > 0; o >>= 1) lm = fmaxf(lm, __shfl_xor_sync(0xffffffffu, lm, o));
    if (lane == 0) red[w] = lm;
    __syncthreads();
    float gm = red[0];
#pragma unroll
    for (int i = 1; i < 8; i++) gm = fmaxf(gm, red[i]);
    __syncthreads();
    float ls = 0.f;
    for (int k = t; k < L; k += 256) { float p = expf(s[k] - gm); s[k] = p; ls += p; }
#pragma unroll
    for (int o = 16; o > 0; o >>= 1) ls += __shfl_xor_sync(0xffffffffu, ls, o);
    if (lane == 0) red[w] = ls;
    __syncthreads();
    float gs = 0.f;
#pragma unroll
    for (int i = 0; i < 8; i++) gs += red[i];
    float inv = 1.0f / gs;

    const int kb = w * (L / 8), ke = kb + (L / 8);
    float a0 = 0.f, a1 = 0.f;
    for (int k = kb; k < ke; k++) {
        float p = s[k];
        a0 = fmaf(p, X[base + (size_t)k * DMODEL + lane], a0);
        a1 = fmaf(p, X[base + (size_t)k * DMODEL + lane + 32], a1);
    }
    part[w][lane]      = a0;
    part[w][lane + 32] = a1;
    __syncthreads();
    if (t < 64) {
        float sum = 0.f;
#pragma unroll
        for (int i = 0; i < 8; i++) sum += part[i][t];
        out[(size_t)n * DMODEL + h * DH + t] = sum * inv;
    }
}

// ---------------------------------------------------------------------------
extern "C" void kernel_launch(void* const* d_in, const int* in_sizes, int n_in,
                              void* d_out, int out_size)
{
    const float* tokens  = (const float*)d_in[0];
    const float* ts      = (const float*)d_in[1];
    const float* maskp   = (const float*)d_in[2];
    const float* Wq      = (const float*)d_in[3];
    const float* bq      = (const float*)d_in[4];
    const float* Wk      = (const float*)d_in[5];
    const float* bk      = (const float*)d_in[6];
    const float* Wv      = (const float*)d_in[7];
    const float* bv      = (const float*)d_in[8];
    const float* Wo      = (const float*)d_in[9];
    const float* bo      = (const float*)d_in[10];
    const float* readout = (const float*)d_in[11];
    float* out = (float*)d_out;
    (void)n_in;

    const int M  = in_sizes[0] / DMODEL;   // N*L = 32768
    const int Nb = out_size / DMODEL;      // 64
    const int L  = M / Nb;                 // 512

    float *gQ, *gK, *gV, *gO;
    __nv_bfloat16 *gth, *gtl, *gwh, *gwl;
    cudaGetSymbolAddress((void**)&gQ, g_Q);
    cudaGetSymbolAddress((void**)&gK, g_K);
    cudaGetSymbolAddress((void**)&gV, g_V);
    cudaGetSymbolAddress((void**)&gO, g_O);
    cudaGetSymbolAddress((void**)&gth, g_th);
    cudaGetSymbolAddress((void**)&gtl, g_tl);
    cudaGetSymbolAddress((void**)&gwh, g_wh);
    cudaGetSymbolAddress((void**)&gwl, g_wl);

    // ---- pre-split inputs to bf16 hi/lo ----
    const int tok4 = M * DMODEL / 4;
    split_f32<<<(tok4 + 255) / 256, 256>>>(tokens, gth, gtl, tok4);
    const int w4 = WSZ / 4;
    split_f32<<<(w4 + 255) / 256, 256>>>(Wq, gwh + 0 * WSZ, gwl + 0 * WSZ, w4);
    split_f32<<<(w4 + 255) / 256, 256>>>(Wk, gwh + 1 * WSZ, gwl + 1 * WSZ, w4);
    split_f32<<<(w4 + 255) / 256, 256>>>(Wv, gwh + 2 * WSZ, gwl + 2 * WSZ, w4);
    split_f32<<<(w4 + 255) / 256, 256>>>(Wo, gwh + 3 * WSZ, gwl + 3 * WSZ, w4);

    dim3 gg(DMODEL / GBN, M / GBM);
    gemm_tc<<<gg, 256>>>(gth, gtl, gwh + 0 * WSZ, gwl + 0 * WSZ, bq, nullptr, gQ, M, DMODEL, DMODEL);
    gemm_tc<<<gg, 256>>>(gth, gtl, gwh + 1 * WSZ, gwl + 1 * WSZ, bk, nullptr, gK, M, DMODEL, DMODEL);
    gemm_tc<<<gg, 256>>>(gth, gtl, gwh + 2 * WSZ, gwl + 2 * WSZ, bv, nullptr, gV, M, DMODEL, DMODEL);

    cudaFuncSetAttribute(attn_tc, cudaFuncAttributeMaxDynamicSharedMemorySize,
                         A_SMEM_TOTAL);
    dim3 ag(L / 128, NHEAD, Nb);
    attn_tc<<<ag, 256, A_SMEM_TOTAL>>>(gQ, gK, gV, ts, maskp, gO, L);

    // split attention output (reuses token split buffers), then out-proj
    split_f32<<<(tok4 + 255) / 256, 256>>>(gO, gth, gtl, tok4);
    gemm_tc<<<gg, 256>>>(gth, gtl, gwh + 3 * WSZ, gwl + 3 * WSZ, bo, maskp, gQ, M, DMODEL, DMODEL);

    dim3 pg(NHEAD, Nb);
    pool_kernel<<<pg, 256>>>(gQ, readout, maskp, out, L);
}

// round 6
// speedup vs baseline: 1.1267x; 1.1267x over previous
#include <cuda_runtime.h>
#include <cuda_bf16.h>
#include <math.h>
#include <stdint.h>

#define DMODEL 768
#define NHEAD  12
#define DH     64
#define TAU    300.0f
#define INV_TAU (1.0f / 300.0f)
#define NEGV   (-1e9f)
#define SCALE  0.125f   /* 1/sqrt(64) */

#define MAXM (64 * 512)
#define WSZ  (DMODEL * DMODEL)

__device__ float g_Q[MAXM * DMODEL];
__device__ float g_K[MAXM * DMODEL];
__device__ float g_V[MAXM * DMODEL];
__device__ float g_O[MAXM * DMODEL];
// bf16 hi/lo split scratch: tokens (then reused for attn-out), 4 weight mats
__device__ __nv_bfloat16 g_th[MAXM * DMODEL];
__device__ __nv_bfloat16 g_tl[MAXM * DMODEL];
__device__ __nv_bfloat16 g_wh[4 * WSZ];
__device__ __nv_bfloat16 g_wl[4 * WSZ];

// ===========================================================================
// helpers
// ===========================================================================
__device__ __forceinline__ uint32_t smem_u32(const void* p) {
    uint32_t a;
    asm("{ .reg .u64 t; cvta.to.shared.u64 t, %1; cvt.u32.u64 %0, t; }"
        : "=r"(a) : "l"(p));
    return a;
}

__device__ __forceinline__ void ldsm4(uint32_t* r, uint32_t addr) {
    asm volatile("ldmatrix.sync.aligned.m8n8.x4.shared.b16 {%0,%1,%2,%3}, [%4];"
                 : "=r"(r[0]), "=r"(r[1]), "=r"(r[2]), "=r"(r[3]) : "r"(addr));
}

__device__ __forceinline__ void mma16816(float* c, const uint32_t* a,
                                         const uint32_t* b) {
    asm volatile(
        "mma.sync.aligned.m16n8k16.row.col.f32.bf16.bf16.f32 "
        "{%0,%1,%2,%3}, {%4,%5,%6,%7}, {%8,%9}, {%0,%1,%2,%3};"
        : "+f"(c[0]), "+f"(c[1]), "+f"(c[2]), "+f"(c[3])
        : "r"(a[0]), "r"(a[1]), "r"(a[2]), "r"(a[3]), "r"(b[0]), "r"(b[1]));
}

__device__ __forceinline__ void cp16(uint32_t dst, const void* src) {
    asm volatile("cp.async.cg.shared.global [%0], [%1], 16;"
                 :: "r"(dst), "l"(src));
}

__device__ __forceinline__ void split4(float4 v, uint2& h, uint2& l) {
    __nv_bfloat16 h0 = __float2bfloat16_rn(v.x);
    __nv_bfloat16 h1 = __float2bfloat16_rn(v.y);
    __nv_bfloat16 h2 = __float2bfloat16_rn(v.z);
    __nv_bfloat16 h3 = __float2bfloat16_rn(v.w);
    __nv_bfloat16 l0 = __float2bfloat16_rn(v.x - __bfloat162float(h0));
    __nv_bfloat16 l1 = __float2bfloat16_rn(v.y - __bfloat162float(h1));
    __nv_bfloat16 l2 = __float2bfloat16_rn(v.z - __bfloat162float(h2));
    __nv_bfloat16 l3 = __float2bfloat16_rn(v.w - __bfloat162float(h3));
    h.x = (uint32_t)__bfloat16_as_ushort(h0) | ((uint32_t)__bfloat16_as_ushort(h1) << 16);
    h.y = (uint32_t)__bfloat16_as_ushort(h2) | ((uint32_t)__bfloat16_as_ushort(h3) << 16);
    l.x = (uint32_t)__bfloat16_as_ushort(l0) | ((uint32_t)__bfloat16_as_ushort(l1) << 16);
    l.y = (uint32_t)__bfloat16_as_ushort(l2) | ((uint32_t)__bfloat16_as_ushort(l3) << 16);
}

__device__ __forceinline__ uint32_t pack_bf16(float a, float b) {
    __nv_bfloat162 t = __floats2bfloat162_rn(a, b);
    return *(uint32_t*)&t;
}
__device__ __forceinline__ void split2(float a, float b, uint32_t& h, uint32_t& l) {
    __nv_bfloat16 ha = __float2bfloat16_rn(a);
    __nv_bfloat16 hb = __float2bfloat16_rn(b);
    float la = a - __bfloat162float(ha);
    float lb = b - __bfloat162float(hb);
    h = (uint32_t)__bfloat16_as_ushort(ha) | ((uint32_t)__bfloat16_as_ushort(hb) << 16);
    l = pack_bf16(la, lb);
}

// ===========================================================================
// elementwise f32 -> bf16 hi/lo split
// ===========================================================================
__global__ __launch_bounds__(256) void split_f32(
    const float* __restrict__ X, __nv_bfloat16* __restrict__ Xh,
    __nv_bfloat16* __restrict__ Xl, int n4)
{
    int i = blockIdx.x * blockDim.x + threadIdx.x;
    if (i < n4) {
        float4 v = ((const float4*)X)[i];
        uint2 h, l;
        split4(v, h, l);
        ((uint2*)Xh)[i] = h;
        ((uint2*)Xl)[i] = l;
    }
}

// ===========================================================================
// HMMA GEMM on pre-split bf16 inputs, cp.async 2-stage pipeline.
// C = A @ W^T + bias, opt * mask. CTA 128x128, BK=32, 256 threads.
// Smem pitch 80B/row -> conflict-free ldmatrix.
// ===========================================================================
#define GBM 128
#define GBN 128
#define GBK 32
// per-stage byte offsets in dynamic smem
#define G_AH 0
#define G_AL 10240
#define G_BH 20480
#define G_BL 30720
#define G_STAGE 40960
#define G_BIAS  81920
#define G_SMEM  (81920 + 512)

__global__ __launch_bounds__(256, 1) void gemm_tc(
    const __nv_bfloat16* __restrict__ Ahg, const __nv_bfloat16* __restrict__ Alg,
    const __nv_bfloat16* __restrict__ Whg, const __nv_bfloat16* __restrict__ Wlg,
    const float* __restrict__ bias, const float* __restrict__ maskp,
    float* __restrict__ C, int M, int N, int K)
{
    extern __shared__ char gsm[];
    const uint32_t sbase = smem_u32(gsm);
    float* bias_s = (float*)(gsm + G_BIAS);

    const int t = threadIdx.x;
    const int wid = t >> 5, lane = t & 31;
    const int n0 = blockIdx.x * GBN;
    const int m0 = blockIdx.y * GBM;

    if (t < GBN) bias_s[t] = bias[n0 + t];

    // ---- async loader mapping: 2 threads per 64B row, 16B chunks ----
    const int lr = t >> 1;             // row 0..127
    const int lcp = (t & 1) * 2;       // chunk pair 0 or 2
    const __nv_bfloat16* srcAh = Ahg + (size_t)(m0 + lr) * K + lcp * 8;
    const __nv_bfloat16* srcAl = Alg + (size_t)(m0 + lr) * K + lcp * 8;
    const __nv_bfloat16* srcBh = Whg + (size_t)(n0 + lr) * K + lcp * 8;
    const __nv_bfloat16* srcBl = Wlg + (size_t)(n0 + lr) * K + lcp * 8;
    const uint32_t dst_row = sbase + (uint32_t)lr * 80 + (uint32_t)lcp * 16;

    const int NITER = K / GBK;   // 24

#define G_ISSUE(bufi, kc)                                                     \
    do {                                                                      \
        uint32_t d = dst_row + (bufi) * G_STAGE;                              \
        cp16(d + G_AH,      srcAh + (kc));                                    \
        cp16(d + G_AH + 16, srcAh + (kc) + 8);                                \
        cp16(d + G_AL,      srcAl + (kc));                                    \
        cp16(d + G_AL + 16, srcAl + (kc) + 8);                                \
        cp16(d + G_BH,      srcBh + (kc));                                    \
        cp16(d + G_BH + 16, srcBh + (kc) + 8);                                \
        cp16(d + G_BL,      srcBl + (kc));                                    \
        cp16(d + G_BL + 16, srcBl + (kc) + 8);                                \
    } while (0)

    // prologue: stage 0
    G_ISSUE(0, 0);
    asm volatile("cp.async.commit_group;" ::: "memory");

    const int wm = wid >> 2;
    const int wn = wid & 3;
    const int a_row = lane & 15;
    const int a_chk = (lane >> 4) & 1;
    const int b_n   = (lane & 7) + ((lane >> 4) & 1) * 8;
    const int b_chk = (lane >> 3) & 1;

    float acc[4][4][4];
#pragma unroll
    for (int mi = 0; mi < 4; mi++)
#pragma unroll
        for (int ni = 0; ni < 4; ni++)
#pragma unroll
            for (int j = 0; j < 4; j++) acc[mi][ni][j] = 0.0f;

    for (int it = 0; it < NITER; it++) {
        const int buf = it & 1;
        if (it + 1 < NITER) {
            G_ISSUE(buf ^ 1, (it + 1) * GBK);
            asm volatile("cp.async.commit_group;" ::: "memory");
            asm volatile("cp.async.wait_group 1;" ::: "memory");
        } else {
            asm volatile("cp.async.wait_group 0;" ::: "memory");
        }
        __syncthreads();

        const uint32_t st = sbase + buf * G_STAGE;
        const uint32_t ah_s = st + G_AH, al_s = st + G_AL;
        const uint32_t bh_s = st + G_BH, bl_s = st + G_BL;

#pragma unroll
        for (int s = 0; s < 2; s++) {
            uint32_t bhf[8], blf[8];
#pragma unroll
            for (int nt = 0; nt < 2; nt++) {
                uint32_t boff = (uint32_t)(wn * 32 + nt * 16 + b_n) * 80
                              + s * 32 + b_chk * 16;
                ldsm4(bhf + nt * 4, bh_s + boff);
                ldsm4(blf + nt * 4, bl_s + boff);
            }
#pragma unroll
            for (int mi = 0; mi < 4; mi++) {
                uint32_t aoff = (uint32_t)(wm * 64 + mi * 16 + a_row) * 80
                              + s * 32 + a_chk * 16;
                uint32_t ahf[4], alf[4];
                ldsm4(ahf, ah_s + aoff);
                ldsm4(alf, al_s + aoff);
#pragma unroll
                for (int ni = 0; ni < 4; ni++) {
                    mma16816(acc[mi][ni], ahf, bhf + ni * 2);
                    mma16816(acc[mi][ni], ahf, blf + ni * 2);
                    mma16816(acc[mi][ni], alf, bhf + ni * 2);
                }
            }
        }
        __syncthreads();
    }

    const int r0 = lane >> 2;
    const int c0 = (lane & 3) * 2;
#pragma unroll
    for (int mi = 0; mi < 4; mi++) {
        int mA = m0 + wm * 64 + mi * 16 + r0;
        int mB = mA + 8;
        float mkA = maskp ? maskp[mA] : 1.0f;
        float mkB = maskp ? maskp[mB] : 1.0f;
#pragma unroll
        for (int ni = 0; ni < 4; ni++) {
            int n = wn * 32 + ni * 8 + c0;
            float b0 = bias_s[n], b1 = bias_s[n + 1];
            float2 vA, vB;
            vA.x = (acc[mi][ni][0] + b0) * mkA;
            vA.y = (acc[mi][ni][1] + b1) * mkA;
            vB.x = (acc[mi][ni][2] + b0) * mkB;
            vB.y = (acc[mi][ni][3] + b1) * mkB;
            *(float2*)&C[(size_t)mA * N + n0 + n] = vA;
            *(float2*)&C[(size_t)mB * N + n0 + n] = vB;
        }
    }
}

// ===========================================================================
// Tensor-core flash attention (R4 version, verbatim — known 1.03ms).
// ===========================================================================
#define APITCH 72
#define A_QH 0
#define A_QL 18432
#define A_KH 36864
#define A_KL 46080
#define A_VH 55296
#define A_VL 64512
#define A_TK 73728
#define A_MK 73984
#define A_SMEM_TOTAL 74240

__global__ __launch_bounds__(256, 1) void attn_tc(
    const float* __restrict__ Q, const float* __restrict__ K,
    const float* __restrict__ V, const float* __restrict__ ts,
    const float* __restrict__ maskp, float* __restrict__ O, int L)
{
    extern __shared__ char smem[];
    __nv_bfloat16* Qh = (__nv_bfloat16*)(smem + A_QH);
    __nv_bfloat16* Ql = (__nv_bfloat16*)(smem + A_QL);
    __nv_bfloat16* Kh = (__nv_bfloat16*)(smem + A_KH);
    __nv_bfloat16* Kl = (__nv_bfloat16*)(smem + A_KL);
    __nv_bfloat16* Vh = (__nv_bfloat16*)(smem + A_VH);   // [d][key]
    __nv_bfloat16* Vl = (__nv_bfloat16*)(smem + A_VL);
    float* tks = (float*)(smem + A_TK);
    float* mks = (float*)(smem + A_MK);

    const int t = threadIdx.x, w = t >> 5, lane = t & 31;
    const int q0 = blockIdx.x * 128, h = blockIdx.y, n = blockIdx.z;
    const size_t base = (size_t)n * L * DMODEL + (size_t)h * DH;

    for (int idx = t; idx < 128 * 16; idx += 256) {
        int row = idx >> 4, q4 = idx & 15;
        float4 v = *(const float4*)(Q + base + (size_t)(q0 + row) * DMODEL + q4 * 4);
        v.x *= SCALE; v.y *= SCALE; v.z *= SCALE; v.w *= SCALE;
        uint2 hh, ll;
        split4(v, hh, ll);
        *(uint2*)&Qh[row * APITCH + q4 * 4] = hh;
        *(uint2*)&Ql[row * APITCH + q4 * 4] = ll;
    }
    __syncthreads();

    const int a_row = lane & 15, a_chk = (lane >> 4) & 1;
    const uint32_t qh_s = smem_u32(Qh), ql_s = smem_u32(Ql);
    uint32_t qhf[4][4], qlf[4][4];
#pragma unroll
    for (int ks = 0; ks < 4; ks++) {
        uint32_t aoff = (uint32_t)(w * 16 + a_row) * 144 + ks * 32 + a_chk * 16;
        ldsm4(qhf[ks], qh_s + aoff);
        ldsm4(qlf[ks], ql_s + aoff);
    }

    const int r0 = lane >> 2, c2 = (lane & 3) * 2;
    const float tq0 = ts[n * L + q0 + w * 16 + r0];
    const float tq1 = ts[n * L + q0 + w * 16 + r0 + 8];

    float o[8][4];
#pragma unroll
    for (int i = 0; i < 8; i++)
#pragma unroll
        for (int j = 0; j < 4; j++) o[i][j] = 0.0f;
    float m0 = -1e30f, m1 = -1e30f, l0 = 0.0f, l1 = 0.0f;

    const uint32_t kh_s = smem_u32(Kh), kl_s = smem_u32(Kl);
    const uint32_t vh_s = smem_u32(Vh), vl_s = smem_u32(Vl);
    const int b_n = (lane & 7) + ((lane >> 4) & 1) * 8;
    const int b_chk = (lane >> 3) & 1;

    const int nchunk = L / 64;
    for (int c = 0; c < nchunk; c++) {
        const int k0 = c * 64;
        __syncthreads();
        for (int idx = t; idx < 64 * 16; idx += 256) {
            int row = idx >> 4, q4 = idx & 15;
            float4 v = *(const float4*)(K + base + (size_t)(k0 + row) * DMODEL + q4 * 4);
            uint2 hh, ll;
            split4(v, hh, ll);
            *(uint2*)&Kh[row * APITCH + q4 * 4] = hh;
            *(uint2*)&Kl[row * APITCH + q4 * 4] = ll;
        }
        {
            const int d = t & 63, kg = t >> 6;
            uint32_t hbuf[8], lbuf[8];
#pragma unroll
            for (int i = 0; i < 8; i++) {
                float va = V[base + (size_t)(k0 + kg * 16 + 2 * i)     * DMODEL + d];
                float vb = V[base + (size_t)(k0 + kg * 16 + 2 * i + 1) * DMODEL + d];
                split2(va, vb, hbuf[i], lbuf[i]);
            }
#pragma unroll
            for (int i = 0; i < 4; i++) {
                uint2 hh = make_uint2(hbuf[2 * i], hbuf[2 * i + 1]);
                uint2 ll = make_uint2(lbuf[2 * i], lbuf[2 * i + 1]);
                *(uint2*)&Vh[d * APITCH + kg * 16 + i * 4] = hh;
                *(uint2*)&Vl[d * APITCH + kg * 16 + i * 4] = ll;
            }
        }
        if (t < 64) {
            tks[t] = ts[n * L + k0 + t];
            mks[t] = maskp[n * L + k0 + t];
        }
        __syncthreads();

        // ---- S = Q K^T (3-term split) ----
        float S[8][4];
#pragma unroll
        for (int i = 0; i < 8; i++)
#pragma unroll
            for (int j = 0; j < 4; j++) S[i][j] = 0.0f;
#pragma unroll
        for (int ks = 0; ks < 4; ks++) {
#pragma unroll
            for (int g = 0; g < 4; g++) {
                uint32_t boff = (uint32_t)(g * 16 + b_n) * 144 + ks * 32 + b_chk * 16;
                uint32_t bh[4], bl[4];
                ldsm4(bh, kh_s + boff);
                ldsm4(bl, kl_s + boff);
#pragma unroll
                for (int ni = 0; ni < 2; ni++) {
                    mma16816(S[g * 2 + ni], qhf[ks], bh + ni * 2);
                    mma16816(S[g * 2 + ni], qhf[ks], bl + ni * 2);
                    mma16816(S[g * 2 + ni], qlf[ks], bh + ni * 2);
                }
            }
        }

        // ---- bias + mask + online softmax ----
        float cm0 = -1e30f, cm1 = -1e30f;
#pragma unroll
        for (int nt = 0; nt < 8; nt++) {
#pragma unroll
            for (int j = 0; j < 2; j++) {
                int key = nt * 8 + c2 + j;
                float tk = tks[key];
                bool ok = mks[key] > 0.0f;
                float bA = -fabsf(tq0 - tk) * INV_TAU;
                float bB = -fabsf(tq1 - tk) * INV_TAU;
                S[nt][j]     = ok ? S[nt][j]     + bA : NEGV;
                S[nt][j + 2] = ok ? S[nt][j + 2] + bB : NEGV;
                cm0 = fmaxf(cm0, S[nt][j]);
                cm1 = fmaxf(cm1, S[nt][j + 2]);
            }
        }
#pragma unroll
        for (int off = 1; off <= 2; off <<= 1) {
            cm0 = fmaxf(cm0, __shfl_xor_sync(0xffffffffu, cm0, off));
            cm1 = fmaxf(cm1, __shfl_xor_sync(0xffffffffu, cm1, off));
        }
        float nm0 = fmaxf(m0, cm0), nm1 = fmaxf(m1, cm1);
        float cr0 = __expf(m0 - nm0), cr1 = __expf(m1 - nm1);
        m0 = nm0; m1 = nm1;

        float ps0 = 0.0f, ps1 = 0.0f;
#pragma unroll
        for (int nt = 0; nt < 8; nt++) {
            float p00 = __expf(S[nt][0] - nm0);
            float p01 = __expf(S[nt][1] - nm0);
            float p10 = __expf(S[nt][2] - nm1);
            float p11 = __expf(S[nt][3] - nm1);
            ps0 += p00 + p01; ps1 += p10 + p11;
            S[nt][0] = p00; S[nt][1] = p01; S[nt][2] = p10; S[nt][3] = p11;
        }
#pragma unroll
        for (int off = 1; off <= 2; off <<= 1) {
            ps0 += __shfl_xor_sync(0xffffffffu, ps0, off);
            ps1 += __shfl_xor_sync(0xffffffffu, ps1, off);
        }
        l0 = l0 * cr0 + ps0;
        l1 = l1 * cr1 + ps1;

#pragma unroll
        for (int i = 0; i < 8; i++) {
            o[i][0] *= cr0; o[i][1] *= cr0;
            o[i][2] *= cr1; o[i][3] *= cr1;
        }

        // ---- O += P V (3-term split) ----
#pragma unroll
        for (int kt = 0; kt < 4; kt++) {
            uint32_t pah[4], pal[4];
            split2(S[2 * kt][0],     S[2 * kt][1],     pah[0], pal[0]);
            split2(S[2 * kt][2],     S[2 * kt][3],     pah[1], pal[1]);
            split2(S[2 * kt + 1][0], S[2 * kt + 1][1], pah[2], pal[2]);
            split2(S[2 * kt + 1][2], S[2 * kt + 1][3], pah[3], pal[3]);
#pragma unroll
            for (int g = 0; g < 4; g++) {
                uint32_t boff = (uint32_t)(g * 16 + b_n) * 144 + kt * 32 + b_chk * 16;
                uint32_t bh[4], bl[4];
                ldsm4(bh, vh_s + boff);
                ldsm4(bl, vl_s + boff);
#pragma unroll
                for (int ni = 0; ni < 2; ni++) {
                    mma16816(o[g * 2 + ni], pah, bh + ni * 2);
                    mma16816(o[g * 2 + ni], pal, bh + ni * 2);
                    mma16816(o[g * 2 + ni], pah, bl + ni * 2);
                }
            }
        }
    }

    const float inv0 = 1.0f / l0, inv1 = 1.0f / l1;
    const int gr0 = q0 + w * 16 + r0, gr1 = gr0 + 8;
#pragma unroll
    for (int ntd = 0; ntd < 8; ntd++) {
        int d = ntd * 8 + c2;
        float2 vA = make_float2(o[ntd][0] * inv0, o[ntd][1] * inv0);
        float2 vB = make_float2(o[ntd][2] * inv1, o[ntd][3] * inv1);
        *(float2*)&O[base + (size_t)gr0 * DMODEL + d] = vA;
        *(float2*)&O[base + (size_t)gr1 * DMODEL + d] = vB;
    }
}

// ---------------------------------------------------------------------------
// Readout pooling: one block per (head, batch). X = masked projected output.
// ---------------------------------------------------------------------------
__global__ __launch_bounds__(256) void pool_kernel(
    const float* __restrict__ X, const float* __restrict__ readout,
    const float* __restrict__ maskp, float* __restrict__ out, int L)
{
    __shared__ float s[512];
    __shared__ float qsh[64];
    __shared__ float red[8];
    __shared__ float part[8][64];
    const int h = blockIdx.x, n = blockIdx.y;
    const int t = threadIdx.x, w = t >> 5, lane = t & 31;
    if (t < 64) qsh[t] = readout[h * DH + t] * SCALE;
    __syncthreads();
    const size_t base = (size_t)n * L * DMODEL + (size_t)h * DH;

    for (int k = w; k < L; k += 8) {
        float d = X[base + (size_t)k * DMODEL + lane] * qsh[lane]
                + X[base + (size_t)k * DMODEL + lane + 32] * qsh[lane + 32];
#pragma unroll
        for (int o = 16; o > 0; o >>= 1) d += __shfl_xor_sync(0xffffffffu, d, o);
        if (lane == 0) s[k] = (maskp[n * L + k] > 0.f) ? d : NEGV;
    }
    __syncthreads();

    float lm = -1e30f;
    for (int k = t; k < L; k += 256) lm = fmaxf(lm, s[k]);
#pragma unroll
    for (int o = 16; o > 0; o >>= 1) lm = fmaxf(lm, __shfl_xor_sync(0xffffffffu, lm, o));
    if (lane == 0) red[w] = lm;
    __syncthreads();
    float gm = red[0];
#pragma unroll
    for (int i = 1; i < 8; i++) gm = fmaxf(gm, red[i]);
    __syncthreads();
    float ls = 0.f;
    for (int k = t; k < L; k += 256) { float p = expf(s[k] - gm); s[k] = p; ls += p; }
#pragma unroll
    for (int o = 16; o > 0; o >>= 1) ls += __shfl_xor_sync(0xffffffffu, ls, o);
    if (lane == 0) red[w] = ls;
    __syncthreads();
    float gs = 0.f;
#pragma unroll
    for (int i = 0; i < 8; i++) gs += red[i];
    float inv = 1.0f / gs;

    const int kb = w * (L / 8), ke = kb + (L / 8);
    float a0 = 0.f, a1 = 0.f;
    for (int k = kb; k < ke; k++) {
        float p = s[k];
        a0 = fmaf(p, X[base + (size_t)k * DMODEL + lane], a0);
        a1 = fmaf(p, X[base + (size_t)k * DMODEL + lane + 32], a1);
    }
    part[w][lane]      = a0;
    part[w][lane + 32] = a1;
    __syncthreads();
    if (t < 64) {
        float sum = 0.f;
#pragma unroll
        for (int i = 0; i < 8; i++) sum += part[i][t];
        out[(size_t)n * DMODEL + h * DH + t] = sum * inv;
    }
}

// ---------------------------------------------------------------------------
extern "C" void kernel_launch(void* const* d_in, const int* in_sizes, int n_in,
                              void* d_out, int out_size)
{
    const float* tokens  = (const float*)d_in[0];
    const float* ts      = (const float*)d_in[1];
    const float* maskp   = (const float*)d_in[2];
    const float* Wq      = (const float*)d_in[3];
    const float* bq      = (const float*)d_in[4];
    const float* Wk      = (const float*)d_in[5];
    const float* bk      = (const float*)d_in[6];
    const float* Wv      = (const float*)d_in[7];
    const float* bv      = (const float*)d_in[8];
    const float* Wo      = (const float*)d_in[9];
    const float* bo      = (const float*)d_in[10];
    const float* readout = (const float*)d_in[11];
    float* out = (float*)d_out;
    (void)n_in;

    const int M  = in_sizes[0] / DMODEL;   // N*L = 32768
    const int Nb = out_size / DMODEL;      // 64
    const int L  = M / Nb;                 // 512

    float *gQ, *gK, *gV, *gO;
    __nv_bfloat16 *gth, *gtl, *gwh, *gwl;
    cudaGetSymbolAddress((void**)&gQ, g_Q);
    cudaGetSymbolAddress((void**)&gK, g_K);
    cudaGetSymbolAddress((void**)&gV, g_V);
    cudaGetSymbolAddress((void**)&gO, g_O);
    cudaGetSymbolAddress((void**)&gth, g_th);
    cudaGetSymbolAddress((void**)&gtl, g_tl);
    cudaGetSymbolAddress((void**)&gwh, g_wh);
    cudaGetSymbolAddress((void**)&gwl, g_wl);

    // ---- pre-split inputs to bf16 hi/lo ----
    const int tok4 = M * DMODEL / 4;
    split_f32<<<(tok4 + 255) / 256, 256>>>(tokens, gth, gtl, tok4);
    const int w4 = WSZ / 4;
    split_f32<<<(w4 + 255) / 256, 256>>>(Wq, gwh + 0 * WSZ, gwl + 0 * WSZ, w4);
    split_f32<<<(w4 + 255) / 256, 256>>>(Wk, gwh + 1 * WSZ, gwl + 1 * WSZ, w4);
    split_f32<<<(w4 + 255) / 256, 256>>>(Wv, gwh + 2 * WSZ, gwl + 2 * WSZ, w4);
    split_f32<<<(w4 + 255) / 256, 256>>>(Wo, gwh + 3 * WSZ, gwl + 3 * WSZ, w4);

    cudaFuncSetAttribute(gemm_tc, cudaFuncAttributeMaxDynamicSharedMemorySize, G_SMEM);
    dim3 gg(DMODEL / GBN, M / GBM);
    gemm_tc<<<gg, 256, G_SMEM>>>(gth, gtl, gwh + 0 * WSZ, gwl + 0 * WSZ, bq, nullptr, gQ, M, DMODEL, DMODEL);
    gemm_tc<<<gg, 256, G_SMEM>>>(gth, gtl, gwh + 1 * WSZ, gwl + 1 * WSZ, bk, nullptr, gK, M, DMODEL, DMODEL);
    gemm_tc<<<gg, 256, G_SMEM>>>(gth, gtl, gwh + 2 * WSZ, gwl + 2 * WSZ, bv, nullptr, gV, M, DMODEL, DMODEL);

    cudaFuncSetAttribute(attn_tc, cudaFuncAttributeMaxDynamicSharedMemorySize,
                         A_SMEM_TOTAL);
    dim3 ag(L / 128, NHEAD, Nb);
    attn_tc<<<ag, 256, A_SMEM_TOTAL>>>(gQ, gK, gV, ts, maskp, gO, L);

    // split attention output (reuses token split buffers), then out-proj
    split_f32<<<(tok4 + 255) / 256, 256>>>(gO, gth, gtl, tok4);
    gemm_tc<<<gg, 256, G_SMEM>>>(gth, gtl, gwh + 3 * WSZ, gwl + 3 * WSZ, bo, maskp, gQ, M, DMODEL, DMODEL);

    dim3 pg(NHEAD, Nb);
    pool_kernel<<<pg, 256>>>(gQ, readout, maskp, out, L);
}

// round 7
// speedup vs baseline: 1.3649x; 1.2114x over previous
#include <cuda_runtime.h>
#include <cuda_bf16.h>
#include <math.h>
#include <stdint.h>

#define DMODEL 768
#define NHEAD  12
#define DH     64
#define TAU    300.0f
#define INV_TAU (1.0f / 300.0f)
#define NEGV   (-1e9f)
#define SCALE  0.125f   /* 1/sqrt(64) */

#define MAXM (64 * 512)
#define WSZ  (DMODEL * DMODEL)

// fp32 scratch: final projected+masked output (pool input)
__device__ float g_P[MAXM * DMODEL];
// bf16 hi/lo split scratch
__device__ __nv_bfloat16 g_th[MAXM * DMODEL];   // tokens split -> then attn-out split
__device__ __nv_bfloat16 g_tl[MAXM * DMODEL];
__device__ __nv_bfloat16 g_qh[MAXM * DMODEL];
__device__ __nv_bfloat16 g_ql[MAXM * DMODEL];
__device__ __nv_bfloat16 g_kh[MAXM * DMODEL];
__device__ __nv_bfloat16 g_kl[MAXM * DMODEL];
__device__ __nv_bfloat16 g_vh[MAXM * DMODEL];
__device__ __nv_bfloat16 g_vl[MAXM * DMODEL];
__device__ __nv_bfloat16 g_wh[4 * WSZ];
__device__ __nv_bfloat16 g_wl[4 * WSZ];

// ===========================================================================
// helpers
// ===========================================================================
__device__ __forceinline__ uint32_t smem_u32(const void* p) {
    uint32_t a;
    asm("{ .reg .u64 t; cvta.to.shared.u64 t, %1; cvt.u32.u64 %0, t; }"
        : "=r"(a) : "l"(p));
    return a;
}

__device__ __forceinline__ void ldsm4(uint32_t* r, uint32_t addr) {
    asm volatile("ldmatrix.sync.aligned.m8n8.x4.shared.b16 {%0,%1,%2,%3}, [%4];"
                 : "=r"(r[0]), "=r"(r[1]), "=r"(r[2]), "=r"(r[3]) : "r"(addr));
}
__device__ __forceinline__ void ldsm4t(uint32_t* r, uint32_t addr) {
    asm volatile("ldmatrix.sync.aligned.m8n8.x4.trans.shared.b16 {%0,%1,%2,%3}, [%4];"
                 : "=r"(r[0]), "=r"(r[1]), "=r"(r[2]), "=r"(r[3]) : "r"(addr));
}

__device__ __forceinline__ void mma16816(float* c, const uint32_t* a,
                                         const uint32_t* b) {
    asm volatile(
        "mma.sync.aligned.m16n8k16.row.col.f32.bf16.bf16.f32 "
        "{%0,%1,%2,%3}, {%4,%5,%6,%7}, {%8,%9}, {%0,%1,%2,%3};"
        : "+f"(c[0]), "+f"(c[1]), "+f"(c[2]), "+f"(c[3])
        : "r"(a[0]), "r"(a[1]), "r"(a[2]), "r"(a[3]), "r"(b[0]), "r"(b[1]));
}

__device__ __forceinline__ void cp16(uint32_t dst, const void* src) {
    asm volatile("cp.async.cg.shared.global [%0], [%1], 16;"
                 :: "r"(dst), "l"(src));
}

__device__ __forceinline__ void split4(float4 v, uint2& h, uint2& l) {
    __nv_bfloat16 h0 = __float2bfloat16_rn(v.x);
    __nv_bfloat16 h1 = __float2bfloat16_rn(v.y);
    __nv_bfloat16 h2 = __float2bfloat16_rn(v.z);
    __nv_bfloat16 h3 = __float2bfloat16_rn(v.w);
    __nv_bfloat16 l0 = __float2bfloat16_rn(v.x - __bfloat162float(h0));
    __nv_bfloat16 l1 = __float2bfloat16_rn(v.y - __bfloat162float(h1));
    __nv_bfloat16 l2 = __float2bfloat16_rn(v.z - __bfloat162float(h2));
    __nv_bfloat16 l3 = __float2bfloat16_rn(v.w - __bfloat162float(h3));
    h.x = (uint32_t)__bfloat16_as_ushort(h0) | ((uint32_t)__bfloat16_as_ushort(h1) << 16);
    h.y = (uint32_t)__bfloat16_as_ushort(h2) | ((uint32_t)__bfloat16_as_ushort(h3) << 16);
    l.x = (uint32_t)__bfloat16_as_ushort(l0) | ((uint32_t)__bfloat16_as_ushort(l1) << 16);
    l.y = (uint32_t)__bfloat16_as_ushort(l2) | ((uint32_t)__bfloat16_as_ushort(l3) << 16);
}

__device__ __forceinline__ uint32_t pack_bf16(float a, float b) {
    __nv_bfloat162 t = __floats2bfloat162_rn(a, b);
    return *(uint32_t*)&t;
}
__device__ __forceinline__ void split2(float a, float b, uint32_t& h, uint32_t& l) {
    __nv_bfloat16 ha = __float2bfloat16_rn(a);
    __nv_bfloat16 hb = __float2bfloat16_rn(b);
    float la = a - __bfloat162float(ha);
    float lb = b - __bfloat162float(hb);
    h = (uint32_t)__bfloat16_as_ushort(ha) | ((uint32_t)__bfloat16_as_ushort(hb) << 16);
    l = pack_bf16(la, lb);
}

// ===========================================================================
// elementwise f32 -> bf16 hi/lo split
// ===========================================================================
__global__ __launch_bounds__(256) void split_f32(
    const float* __restrict__ X, __nv_bfloat16* __restrict__ Xh,
    __nv_bfloat16* __restrict__ Xl, int n4)
{
    int i = blockIdx.x * blockDim.x + threadIdx.x;
    if (i < n4) {
        float4 v = ((const float4*)X)[i];
        uint2 h, l;
        split4(v, h, l);
        ((uint2*)Xh)[i] = h;
        ((uint2*)Xl)[i] = l;
    }
}

// ===========================================================================
// HMMA GEMM mainloop (cp.async 2-stage, pre-split bf16 inputs). Two kernels
// differing only in epilogue: fp32-out (+mask) and bf16-split-out (*oscale).
// ===========================================================================
#define GBM 128
#define GBN 128
#define GBK 32
#define G_AH 0
#define G_AL 10240
#define G_BH 20480
#define G_BL 30720
#define G_STAGE 40960
#define G_BIAS  81920
#define G_SMEM  (81920 + 512)

#define GEMM_PROLOG                                                           \
    extern __shared__ char gsm[];                                             \
    const uint32_t sbase = smem_u32(gsm);                                     \
    float* bias_s = (float*)(gsm + G_BIAS);                                   \
    const int t = threadIdx.x;                                                \
    const int wid = t >> 5, lane = t & 31;                                    \
    const int n0 = blockIdx.x * GBN;                                          \
    const int m0 = blockIdx.y * GBM;                                          \
    if (t < GBN) bias_s[t] = bias[n0 + t];                                    \
    const int lr = t >> 1;                                                    \
    const int lcp = (t & 1) * 2;                                              \
    const __nv_bfloat16* srcAh = Ahg + (size_t)(m0 + lr) * K + lcp * 8;       \
    const __nv_bfloat16* srcAl = Alg + (size_t)(m0 + lr) * K + lcp * 8;       \
    const __nv_bfloat16* srcBh = Whg + (size_t)(n0 + lr) * K + lcp * 8;       \
    const __nv_bfloat16* srcBl = Wlg + (size_t)(n0 + lr) * K + lcp * 8;       \
    const uint32_t dst_row = sbase + (uint32_t)lr * 80 + (uint32_t)lcp * 16;  \
    const int NITER = K / GBK;

#define G_ISSUE(bufi, kc)                                                     \
    do {                                                                      \
        uint32_t d = dst_row + (bufi) * G_STAGE;                              \
        cp16(d + G_AH,      srcAh + (kc));                                    \
        cp16(d + G_AH + 16, srcAh + (kc) + 8);                                \
        cp16(d + G_AL,      srcAl + (kc));                                    \
        cp16(d + G_AL + 16, srcAl + (kc) + 8);                                \
        cp16(d + G_BH,      srcBh + (kc));                                    \
        cp16(d + G_BH + 16, srcBh + (kc) + 8);                                \
        cp16(d + G_BL,      srcBl + (kc));                                    \
        cp16(d + G_BL + 16, srcBl + (kc) + 8);                                \
    } while (0)

#define GEMM_MAINLOOP                                                         \
    G_ISSUE(0, 0);                                                            \
    asm volatile("cp.async.commit_group;" ::: "memory");                      \
    const int wm = wid >> 2;                                                  \
    const int wn = wid & 3;                                                   \
    const int a_row = lane & 15;                                              \
    const int a_chk = (lane >> 4) & 1;                                        \
    const int b_n   = (lane & 7) + ((lane >> 4) & 1) * 8;                     \
    const int b_chk = (lane >> 3) & 1;                                        \
    float acc[4][4][4];                                                       \
    _Pragma("unroll")                                                         \
    for (int mi = 0; mi < 4; mi++)                                            \
        _Pragma("unroll")                                                     \
        for (int ni = 0; ni < 4; ni++)                                        \
            _Pragma("unroll")                                                 \
            for (int j = 0; j < 4; j++) acc[mi][ni][j] = 0.0f;                \
    for (int it = 0; it < NITER; it++) {                                      \
        const int buf = it & 1;                                               \
        if (it + 1 < NITER) {                                                 \
            G_ISSUE(buf ^ 1, (it + 1) * GBK);                                 \
            asm volatile("cp.async.commit_group;" ::: "memory");              \
            asm volatile("cp.async.wait_group 1;" ::: "memory");              \
        } else {                                                              \
            asm volatile("cp.async.wait_group 0;" ::: "memory");              \
        }                                                                     \
        __syncthreads();                                                      \
        const uint32_t st = sbase + buf * G_STAGE;                            \
        const uint32_t ah_s = st + G_AH, al_s = st + G_AL;                    \
        const uint32_t bh_s = st + G_BH, bl_s = st + G_BL;                    \
        _Pragma("unroll")                                                     \
        for (int s = 0; s < 2; s++) {                                         \
            uint32_t bhf[8], blf[8];                                          \
            _Pragma("unroll")                                                 \
            for (int nt = 0; nt < 2; nt++) {                                  \
                uint32_t boff = (uint32_t)(wn * 32 + nt * 16 + b_n) * 80      \
                              + s * 32 + b_chk * 16;                          \
                ldsm4(bhf + nt * 4, bh_s + boff);                             \
                ldsm4(blf + nt * 4, bl_s + boff);                             \
            }                                                                 \
            _Pragma("unroll")                                                 \
            for (int mi = 0; mi < 4; mi++) {                                  \
                uint32_t aoff = (uint32_t)(wm * 64 + mi * 16 + a_row) * 80    \
                              + s * 32 + a_chk * 16;                          \
                uint32_t ahf[4], alf[4];                                      \
                ldsm4(ahf, ah_s + aoff);                                      \
                ldsm4(alf, al_s + aoff);                                      \
                _Pragma("unroll")                                             \
                for (int ni = 0; ni < 4; ni++) {                              \
                    mma16816(acc[mi][ni], ahf, bhf + ni * 2);                 \
                    mma16816(acc[mi][ni], ahf, blf + ni * 2);                 \
                    mma16816(acc[mi][ni], alf, bhf + ni * 2);                 \
                }                                                             \
            }                                                                 \
        }                                                                     \
        __syncthreads();                                                      \
    }

// fp32 output with mask (Wo projection)
__global__ __launch_bounds__(256, 1) void gemm_tc(
    const __nv_bfloat16* __restrict__ Ahg, const __nv_bfloat16* __restrict__ Alg,
    const __nv_bfloat16* __restrict__ Whg, const __nv_bfloat16* __restrict__ Wlg,
    const float* __restrict__ bias, const float* __restrict__ maskp,
    float* __restrict__ C, int M, int N, int K)
{
    GEMM_PROLOG
    GEMM_MAINLOOP

    const int r0 = lane >> 2;
    const int c0 = (lane & 3) * 2;
#pragma unroll
    for (int mi = 0; mi < 4; mi++) {
        int mA = m0 + wm * 64 + mi * 16 + r0;
        int mB = mA + 8;
        float mkA = maskp ? maskp[mA] : 1.0f;
        float mkB = maskp ? maskp[mB] : 1.0f;
#pragma unroll
        for (int ni = 0; ni < 4; ni++) {
            int n = wn * 32 + ni * 8 + c0;
            float b0 = bias_s[n], b1 = bias_s[n + 1];
            float2 vA, vB;
            vA.x = (acc[mi][ni][0] + b0) * mkA;
            vA.y = (acc[mi][ni][1] + b1) * mkA;
            vB.x = (acc[mi][ni][2] + b0) * mkB;
            vB.y = (acc[mi][ni][3] + b1) * mkB;
            *(float2*)&C[(size_t)mA * N + n0 + n] = vA;
            *(float2*)&C[(size_t)mB * N + n0 + n] = vB;
        }
    }
}

// bf16 hi/lo split output with output scale (Q/K/V projections)
__global__ __launch_bounds__(256, 1) void gemm_tc_split(
    const __nv_bfloat16* __restrict__ Ahg, const __nv_bfloat16* __restrict__ Alg,
    const __nv_bfloat16* __restrict__ Whg, const __nv_bfloat16* __restrict__ Wlg,
    const float* __restrict__ bias, float oscale,
    __nv_bfloat16* __restrict__ Ch, __nv_bfloat16* __restrict__ Cl,
    int M, int N, int K)
{
    GEMM_PROLOG
    GEMM_MAINLOOP

    const int r0 = lane >> 2;
    const int c0 = (lane & 3) * 2;
#pragma unroll
    for (int mi = 0; mi < 4; mi++) {
        int mA = m0 + wm * 64 + mi * 16 + r0;
        int mB = mA + 8;
#pragma unroll
        for (int ni = 0; ni < 4; ni++) {
            int n = wn * 32 + ni * 8 + c0;
            float b0 = bias_s[n], b1 = bias_s[n + 1];
            uint32_t h, l;
            split2((acc[mi][ni][0] + b0) * oscale, (acc[mi][ni][1] + b1) * oscale, h, l);
            *(uint32_t*)&Ch[(size_t)mA * N + n0 + n] = h;
            *(uint32_t*)&Cl[(size_t)mA * N + n0 + n] = l;
            split2((acc[mi][ni][2] + b0) * oscale, (acc[mi][ni][3] + b1) * oscale, h, l);
            *(uint32_t*)&Ch[(size_t)mB * N + n0 + n] = h;
            *(uint32_t*)&Cl[(size_t)mB * N + n0 + n] = l;
        }
    }
}

// ===========================================================================
// Tensor-core flash attention on pre-split bf16 Q/K/V. cp.async double-
// buffered K/V chunks; V kept [key][d] and fragmented via ldmatrix.trans.
// Emits split bf16 output (hi/lo) for the Wo GEMM.
// ===========================================================================
#define APITCH 72          /* bf16 elems per smem row (144 B) */
#define A_QHO 0
#define A_QLO 18432
#define A_BUF0 36864
#define A_KHO 0
#define A_KLO 9216
#define A_VHO 18432
#define A_VLO 27648
#define A_TKO 36864
#define A_MKO 37120
#define A_BUFSZ 37888
#define A_SMEM_TOTAL (A_BUF0 + 2 * A_BUFSZ)   /* 112640 */

__global__ __launch_bounds__(256, 1) void attn_tc(
    const __nv_bfloat16* __restrict__ Qh_g, const __nv_bfloat16* __restrict__ Ql_g,
    const __nv_bfloat16* __restrict__ Kh_g, const __nv_bfloat16* __restrict__ Kl_g,
    const __nv_bfloat16* __restrict__ Vh_g, const __nv_bfloat16* __restrict__ Vl_g,
    const float* __restrict__ ts, const float* __restrict__ maskp,
    __nv_bfloat16* __restrict__ Oh_g, __nv_bfloat16* __restrict__ Ol_g, int L)
{
    extern __shared__ char smem[];
    const uint32_t sbase = smem_u32(smem);

    const int t = threadIdx.x, w = t >> 5, lane = t & 31;
    const int q0 = blockIdx.x * 128, h = blockIdx.y, n = blockIdx.z;
    const size_t base = (size_t)n * L * DMODEL + (size_t)h * DH;
    const int nchunk = L / 64;

#define A_ISSUE(bufi, cc)                                                     \
    do {                                                                      \
        const uint32_t bb = sbase + A_BUF0 + (bufi) * A_BUFSZ;                \
        const int kk0 = (cc) * 64;                                            \
        _Pragma("unroll")                                                     \
        for (int idx = t; idx < 512; idx += 256) {                            \
            int row = idx >> 3, ch = idx & 7;                                 \
            size_t g = base + (size_t)(kk0 + row) * DMODEL + ch * 8;          \
            uint32_t doff = (uint32_t)row * 144 + ch * 16;                    \
            cp16(bb + A_KHO + doff, Kh_g + g);                                \
            cp16(bb + A_KLO + doff, Kl_g + g);                                \
            cp16(bb + A_VHO + doff, Vh_g + g);                                \
            cp16(bb + A_VLO + doff, Vl_g + g);                                \
        }                                                                     \
        if (t < 16)                                                           \
            cp16(bb + A_TKO + t * 16, ts + n * L + kk0 + t * 4);              \
        else if (t < 32)                                                      \
            cp16(bb + A_MKO + (t - 16) * 16, maskp + n * L + kk0 + (t - 16) * 4); \
    } while (0)

    // prologue: stream chunk 0 while loading Q
    A_ISSUE(0, 0);
    asm volatile("cp.async.commit_group;" ::: "memory");

    // ---- Q smem load (pre-scaled, pre-split) ----
    {
        __nv_bfloat16* Qh = (__nv_bfloat16*)(smem + A_QHO);
        __nv_bfloat16* Ql = (__nv_bfloat16*)(smem + A_QLO);
#pragma unroll
        for (int idx = t; idx < 1024; idx += 256) {
            int row = idx >> 3, ch = idx & 7;
            size_t g = base + (size_t)(q0 + row) * DMODEL + ch * 8;
            *(uint4*)&Qh[row * APITCH + ch * 8] = *(const uint4*)(Qh_g + g);
            *(uint4*)&Ql[row * APITCH + ch * 8] = *(const uint4*)(Ql_g + g);
        }
    }
    __syncthreads();

    // ---- preload Q fragments ----
    const int a_row = lane & 15, a_chk = (lane >> 4) & 1;
    uint32_t qhf[4][4], qlf[4][4];
#pragma unroll
    for (int ks = 0; ks < 4; ks++) {
        uint32_t aoff = (uint32_t)(w * 16 + a_row) * 144 + ks * 32 + a_chk * 16;
        ldsm4(qhf[ks], sbase + A_QHO + aoff);
        ldsm4(qlf[ks], sbase + A_QLO + aoff);
    }

    const int r0 = lane >> 2, c2 = (lane & 3) * 2;
    const float tq0 = ts[n * L + q0 + w * 16 + r0];
    const float tq1 = ts[n * L + q0 + w * 16 + r0 + 8];

    float o[8][4];
#pragma unroll
    for (int i = 0; i < 8; i++)
#pragma unroll
        for (int j = 0; j < 4; j++) o[i][j] = 0.0f;
    float m0 = -1e30f, m1 = -1e30f, l0 = 0.0f, l1 = 0.0f;

    const int b_n = (lane & 7) + ((lane >> 4) & 1) * 8;
    const int b_chk = (lane >> 3) & 1;
    const int v_row = lane & 15;          // key row within k16
    const int v_col = (lane >> 4) * 8;    // d offset within d16 group

    for (int c = 0; c < nchunk; c++) {
        const int buf = c & 1;
        if (c + 1 < nchunk) {
            A_ISSUE(buf ^ 1, c + 1);
            asm volatile("cp.async.commit_group;" ::: "memory");
            asm volatile("cp.async.wait_group 1;" ::: "memory");
        } else {
            asm volatile("cp.async.wait_group 0;" ::: "memory");
        }
        __syncthreads();

        const uint32_t bb = sbase + A_BUF0 + buf * A_BUFSZ;
        const uint32_t kh_s = bb + A_KHO, kl_s = bb + A_KLO;
        const uint32_t vh_s = bb + A_VHO, vl_s = bb + A_VLO;
        const float* tks = (const float*)(smem + A_BUF0 + buf * A_BUFSZ + A_TKO);
        const float* mks = (const float*)(smem + A_BUF0 + buf * A_BUFSZ + A_MKO);

        // ---- S = Q K^T (3-term split) ----
        float S[8][4];
#pragma unroll
        for (int i = 0; i < 8; i++)
#pragma unroll
            for (int j = 0; j < 4; j++) S[i][j] = 0.0f;
#pragma unroll
        for (int ks = 0; ks < 4; ks++) {
#pragma unroll
            for (int g = 0; g < 4; g++) {
                uint32_t boff = (uint32_t)(g * 16 + b_n) * 144 + ks * 32 + b_chk * 16;
                uint32_t bh[4], bl[4];
                ldsm4(bh, kh_s + boff);
                ldsm4(bl, kl_s + boff);
#pragma unroll
                for (int ni = 0; ni < 2; ni++) {
                    mma16816(S[g * 2 + ni], qhf[ks], bh + ni * 2);
                    mma16816(S[g * 2 + ni], qhf[ks], bl + ni * 2);
                    mma16816(S[g * 2 + ni], qlf[ks], bh + ni * 2);
                }
            }
        }

        // ---- bias + mask + online softmax ----
        float cm0 = -1e30f, cm1 = -1e30f;
#pragma unroll
        for (int nt = 0; nt < 8; nt++) {
#pragma unroll
            for (int j = 0; j < 2; j++) {
                int key = nt * 8 + c2 + j;
                float tk = tks[key];
                bool ok = mks[key] > 0.0f;
                float bA = -fabsf(tq0 - tk) * INV_TAU;
                float bB = -fabsf(tq1 - tk) * INV_TAU;
                S[nt][j]     = ok ? S[nt][j]     + bA : NEGV;
                S[nt][j + 2] = ok ? S[nt][j + 2] + bB : NEGV;
                cm0 = fmaxf(cm0, S[nt][j]);
                cm1 = fmaxf(cm1, S[nt][j + 2]);
            }
        }
#pragma unroll
        for (int off = 1; off <= 2; off <<= 1) {
            cm0 = fmaxf(cm0, __shfl_xor_sync(0xffffffffu, cm0, off));
            cm1 = fmaxf(cm1, __shfl_xor_sync(0xffffffffu, cm1, off));
        }
        float nm0 = fmaxf(m0, cm0), nm1 = fmaxf(m1, cm1);
        float cr0 = __expf(m0 - nm0), cr1 = __expf(m1 - nm1);
        m0 = nm0; m1 = nm1;

        float ps0 = 0.0f, ps1 = 0.0f;
#pragma unroll
        for (int nt = 0; nt < 8; nt++) {
            float p00 = __expf(S[nt][0] - nm0);
            float p01 = __expf(S[nt][1] - nm0);
            float p10 = __expf(S[nt][2] - nm1);
            float p11 = __expf(S[nt][3] - nm1);
            ps0 += p00 + p01; ps1 += p10 + p11;
            S[nt][0] = p00; S[nt][1] = p01; S[nt][2] = p10; S[nt][3] = p11;
        }
#pragma unroll
        for (int off = 1; off <= 2; off <<= 1) {
            ps0 += __shfl_xor_sync(0xffffffffu, ps0, off);
            ps1 += __shfl_xor_sync(0xffffffffu, ps1, off);
        }
        l0 = l0 * cr0 + ps0;
        l1 = l1 * cr1 + ps1;

#pragma unroll
        for (int i = 0; i < 8; i++) {
            o[i][0] *= cr0; o[i][1] *= cr0;
            o[i][2] *= cr1; o[i][3] *= cr1;
        }

        // ---- O += P V : V frags via ldmatrix.trans on [key][d] ----
#pragma unroll
        for (int kt = 0; kt < 4; kt++) {
            uint32_t pah[4], pal[4];
            split2(S[2 * kt][0],     S[2 * kt][1],     pah[0], pal[0]);
            split2(S[2 * kt][2],     S[2 * kt][3],     pah[1], pal[1]);
            split2(S[2 * kt + 1][0], S[2 * kt + 1][1], pah[2], pal[2]);
            split2(S[2 * kt + 1][2], S[2 * kt + 1][3], pah[3], pal[3]);
#pragma unroll
            for (int g = 0; g < 4; g++) {
                // rows kt*16 + (lane&15); cols g*16 + (lane>>4)*8
                uint32_t voff = (uint32_t)(kt * 16 + v_row) * 144
                              + (uint32_t)(g * 16 + v_col) * 2;
                uint32_t bh[4], bl[4];
                ldsm4t(bh, vh_s + voff);
                ldsm4t(bl, vl_s + voff);
#pragma unroll
                for (int ni = 0; ni < 2; ni++) {
                    mma16816(o[g * 2 + ni], pah, bh + ni * 2);
                    mma16816(o[g * 2 + ni], pal, bh + ni * 2);
                    mma16816(o[g * 2 + ni], pah, bl + ni * 2);
                }
            }
        }
        __syncthreads();
    }

    // ---- normalize + split-store ----
    const float inv0 = 1.0f / l0, inv1 = 1.0f / l1;
    const int gr0 = q0 + w * 16 + r0, gr1 = gr0 + 8;
#pragma unroll
    for (int ntd = 0; ntd < 8; ntd++) {
        int d = ntd * 8 + c2;
        uint32_t hh, ll;
        split2(o[ntd][0] * inv0, o[ntd][1] * inv0, hh, ll);
        *(uint32_t*)&Oh_g[base + (size_t)gr0 * DMODEL + d] = hh;
        *(uint32_t*)&Ol_g[base + (size_t)gr0 * DMODEL + d] = ll;
        split2(o[ntd][2] * inv1, o[ntd][3] * inv1, hh, ll);
        *(uint32_t*)&Oh_g[base + (size_t)gr1 * DMODEL + d] = hh;
        *(uint32_t*)&Ol_g[base + (size_t)gr1 * DMODEL + d] = ll;
    }
}

// ---------------------------------------------------------------------------
// Readout pooling: one block per (head, batch). X = masked projected output.
// ---------------------------------------------------------------------------
__global__ __launch_bounds__(256) void pool_kernel(
    const float* __restrict__ X, const float* __restrict__ readout,
    const float* __restrict__ maskp, float* __restrict__ out, int L)
{
    __shared__ float s[512];
    __shared__ float qsh[64];
    __shared__ float red[8];
    __shared__ float part[8][64];
    const int h = blockIdx.x, n = blockIdx.y;
    const int t = threadIdx.x, w = t >> 5, lane = t & 31;
    if (t < 64) qsh[t] = readout[h * DH + t] * SCALE;
    __syncthreads();
    const size_t base = (size_t)n * L * DMODEL + (size_t)h * DH;

    for (int k = w; k < L; k += 8) {
        float d = X[base + (size_t)k * DMODEL + lane] * qsh[lane]
                + X[base + (size_t)k * DMODEL + lane + 32] * qsh[lane + 32];
#pragma unroll
        for (int o = 16; o > 0; o >>= 1) d += __shfl_xor_sync(0xffffffffu, d, o);
        if (lane == 0) s[k] = (maskp[n * L + k] > 0.f) ? d : NEGV;
    }
    __syncthreads();

    float lm = -1e30f;
    for (int k = t; k < L; k += 256) lm = fmaxf(lm, s[k]);
#pragma unroll
    for (int o = 16; o > 0; o >>= 1) lm = fmaxf(lm, __shfl_xor_sync(0xffffffffu, lm, o));
    if (lane == 0) red[w] = lm;
    __syncthreads();
    float gm = red[0];
#pragma unroll
    for (int i = 1; i < 8; i++) gm = fmaxf(gm, red[i]);
    __syncthreads();
    float ls = 0.f;
    for (int k = t; k < L; k += 256) { float p = expf(s[k] - gm); s[k] = p; ls += p; }
#pragma unroll
    for (int o = 16; o > 0; o >>= 1) ls += __shfl_xor_sync(0xffffffffu, ls, o);
    if (lane == 0) red[w] = ls;
    __syncthreads();
    float gs = 0.f;
#pragma unroll
    for (int i = 0; i < 8; i++) gs += red[i];
    float inv = 1.0f / gs;

    const int kb = w * (L / 8), ke = kb + (L / 8);
    float a0 = 0.f, a1 = 0.f;
    for (int k = kb; k < ke; k++) {
        float p = s[k];
        a0 = fmaf(p, X[base + (size_t)k * DMODEL + lane], a0);
        a1 = fmaf(p, X[base + (size_t)k * DMODEL + lane + 32], a1);
    }
    part[w][lane]      = a0;
    part[w][lane + 32] = a1;
    __syncthreads();
    if (t < 64) {
        float sum = 0.f;
#pragma unroll
        for (int i = 0; i < 8; i++) sum += part[i][t];
        out[(size_t)n * DMODEL + h * DH + t] = sum * inv;
    }
}

// ---------------------------------------------------------------------------
extern "C" void kernel_launch(void* const* d_in, const int* in_sizes, int n_in,
                              void* d_out, int out_size)
{
    const float* tokens  = (const float*)d_in[0];
    const float* ts      = (const float*)d_in[1];
    const float* maskp   = (const float*)d_in[2];
    const float* Wq      = (const float*)d_in[3];
    const float* bq      = (const float*)d_in[4];
    const float* Wk      = (const float*)d_in[5];
    const float* bk      = (const float*)d_in[6];
    const float* Wv      = (const float*)d_in[7];
    const float* bv      = (const float*)d_in[8];
    const float* Wo      = (const float*)d_in[9];
    const float* bo      = (const float*)d_in[10];
    const float* readout = (const float*)d_in[11];
    float* out = (float*)d_out;
    (void)n_in;

    const int M  = in_sizes[0] / DMODEL;   // N*L = 32768
    const int Nb = out_size / DMODEL;      // 64
    const int L  = M / Nb;                 // 512

    float* gP;
    __nv_bfloat16 *gth, *gtl, *gwh, *gwl, *gqh, *gql, *gkh, *gkl, *gvh, *gvl;
    cudaGetSymbolAddress((void**)&gP, g_P);
    cudaGetSymbolAddress((void**)&gth, g_th);
    cudaGetSymbolAddress((void**)&gtl, g_tl);
    cudaGetSymbolAddress((void**)&gwh, g_wh);
    cudaGetSymbolAddress((void**)&gwl, g_wl);
    cudaGetSymbolAddress((void**)&gqh, g_qh);
    cudaGetSymbolAddress((void**)&gql, g_ql);
    cudaGetSymbolAddress((void**)&gkh, g_kh);
    cudaGetSymbolAddress((void**)&gkl, g_kl);
    cudaGetSymbolAddress((void**)&gvh, g_vh);
    cudaGetSymbolAddress((void**)&gvl, g_vl);

    // ---- pre-split inputs to bf16 hi/lo ----
    const int tok4 = M * DMODEL / 4;
    split_f32<<<(tok4 + 255) / 256, 256>>>(tokens, gth, gtl, tok4);
    const int w4 = WSZ / 4;
    split_f32<<<(w4 + 255) / 256, 256>>>(Wq, gwh + 0 * WSZ, gwl + 0 * WSZ, w4);
    split_f32<<<(w4 + 255) / 256, 256>>>(Wk, gwh + 1 * WSZ, gwl + 1 * WSZ, w4);
    split_f32<<<(w4 + 255) / 256, 256>>>(Wv, gwh + 2 * WSZ, gwl + 2 * WSZ, w4);
    split_f32<<<(w4 + 255) / 256, 256>>>(Wo, gwh + 3 * WSZ, gwl + 3 * WSZ, w4);

    cudaFuncSetAttribute(gemm_tc, cudaFuncAttributeMaxDynamicSharedMemorySize, G_SMEM);
    cudaFuncSetAttribute(gemm_tc_split, cudaFuncAttributeMaxDynamicSharedMemorySize, G_SMEM);
    dim3 gg(DMODEL / GBN, M / GBM);
    gemm_tc_split<<<gg, 256, G_SMEM>>>(gth, gtl, gwh + 0 * WSZ, gwl + 0 * WSZ, bq,
                                       SCALE, gqh, gql, M, DMODEL, DMODEL);
    gemm_tc_split<<<gg, 256, G_SMEM>>>(gth, gtl, gwh + 1 * WSZ, gwl + 1 * WSZ, bk,
                                       1.0f, gkh, gkl, M, DMODEL, DMODEL);
    gemm_tc_split<<<gg, 256, G_SMEM>>>(gth, gtl, gwh + 2 * WSZ, gwl + 2 * WSZ, bv,
                                       1.0f, gvh, gvl, M, DMODEL, DMODEL);

    cudaFuncSetAttribute(attn_tc, cudaFuncAttributeMaxDynamicSharedMemorySize,
                         A_SMEM_TOTAL);
    dim3 ag(L / 128, NHEAD, Nb);
    // attention writes split bf16 output into the token-split buffers (free now)
    attn_tc<<<ag, 256, A_SMEM_TOTAL>>>(gqh, gql, gkh, gkl, gvh, gvl, ts, maskp,
                                       gth, gtl, L);

    gemm_tc<<<gg, 256, G_SMEM>>>(gth, gtl, gwh + 3 * WSZ, gwl + 3 * WSZ, bo, maskp,
                                 gP, M, DMODEL, DMODEL);

    dim3 pg(NHEAD, Nb);
    pool_kernel<<<pg, 256>>>(gP, readout, maskp, out, L);
}

// round 8
// speedup vs baseline: 1.5696x; 1.1499x over previous
#include <cuda_runtime.h>
#include <cuda_bf16.h>
#include <math.h>
#include <stdint.h>

#define DMODEL 768
#define NHEAD  12
#define DH     64
#define TAU    300.0f
#define INV_TAU (1.0f / 300.0f)
#define NEGV   (-1e9f)
#define SCALE  0.125f   /* 1/sqrt(64) */

#define MAXM (64 * 512)
#define WSZ  (DMODEL * DMODEL)

// fp32 scratch: final projected+masked output (pool input)
__device__ float g_P[MAXM * DMODEL];
// bf16 hi/lo split scratch
__device__ __nv_bfloat16 g_th[MAXM * DMODEL];   // tokens split -> then attn-out split
__device__ __nv_bfloat16 g_tl[MAXM * DMODEL];
__device__ __nv_bfloat16 g_qh[MAXM * DMODEL];
__device__ __nv_bfloat16 g_ql[MAXM * DMODEL];
__device__ __nv_bfloat16 g_kh[MAXM * DMODEL];
__device__ __nv_bfloat16 g_kl[MAXM * DMODEL];
__device__ __nv_bfloat16 g_vh[MAXM * DMODEL];
__device__ __nv_bfloat16 g_vl[MAXM * DMODEL];
__device__ __nv_bfloat16 g_wh[4 * WSZ];
__device__ __nv_bfloat16 g_wl[4 * WSZ];

// ===========================================================================
// helpers
// ===========================================================================
__device__ __forceinline__ uint32_t smem_u32(const void* p) {
    uint32_t a;
    asm("{ .reg .u64 t; cvta.to.shared.u64 t, %1; cvt.u32.u64 %0, t; }"
        : "=r"(a) : "l"(p));
    return a;
}

__device__ __forceinline__ void ldsm4(uint32_t* r, uint32_t addr) {
    asm volatile("ldmatrix.sync.aligned.m8n8.x4.shared.b16 {%0,%1,%2,%3}, [%4];"
                 : "=r"(r[0]), "=r"(r[1]), "=r"(r[2]), "=r"(r[3]) : "r"(addr));
}
__device__ __forceinline__ void ldsm4t(uint32_t* r, uint32_t addr) {
    asm volatile("ldmatrix.sync.aligned.m8n8.x4.trans.shared.b16 {%0,%1,%2,%3}, [%4];"
                 : "=r"(r[0]), "=r"(r[1]), "=r"(r[2]), "=r"(r[3]) : "r"(addr));
}

__device__ __forceinline__ void mma16816(float* c, const uint32_t* a,
                                         const uint32_t* b) {
    asm volatile(
        "mma.sync.aligned.m16n8k16.row.col.f32.bf16.bf16.f32 "
        "{%0,%1,%2,%3}, {%4,%5,%6,%7}, {%8,%9}, {%0,%1,%2,%3};"
        : "+f"(c[0]), "+f"(c[1]), "+f"(c[2]), "+f"(c[3])
        : "r"(a[0]), "r"(a[1]), "r"(a[2]), "r"(a[3]), "r"(b[0]), "r"(b[1]));
}

__device__ __forceinline__ void cp16(uint32_t dst, const void* src) {
    asm volatile("cp.async.cg.shared.global [%0], [%1], 16;"
                 :: "r"(dst), "l"(src));
}

__device__ __forceinline__ void split4(float4 v, uint2& h, uint2& l) {
    __nv_bfloat16 h0 = __float2bfloat16_rn(v.x);
    __nv_bfloat16 h1 = __float2bfloat16_rn(v.y);
    __nv_bfloat16 h2 = __float2bfloat16_rn(v.z);
    __nv_bfloat16 h3 = __float2bfloat16_rn(v.w);
    __nv_bfloat16 l0 = __float2bfloat16_rn(v.x - __bfloat162float(h0));
    __nv_bfloat16 l1 = __float2bfloat16_rn(v.y - __bfloat162float(h1));
    __nv_bfloat16 l2 = __float2bfloat16_rn(v.z - __bfloat162float(h2));
    __nv_bfloat16 l3 = __float2bfloat16_rn(v.w - __bfloat162float(h3));
    h.x = (uint32_t)__bfloat16_as_ushort(h0) | ((uint32_t)__bfloat16_as_ushort(h1) << 16);
    h.y = (uint32_t)__bfloat16_as_ushort(h2) | ((uint32_t)__bfloat16_as_ushort(h3) << 16);
    l.x = (uint32_t)__bfloat16_as_ushort(l0) | ((uint32_t)__bfloat16_as_ushort(l1) << 16);
    l.y = (uint32_t)__bfloat16_as_ushort(l2) | ((uint32_t)__bfloat16_as_ushort(l3) << 16);
}

__device__ __forceinline__ uint32_t pack_bf16(float a, float b) {
    __nv_bfloat162 t = __floats2bfloat162_rn(a, b);
    return *(uint32_t*)&t;
}
__device__ __forceinline__ void split2(float a, float b, uint32_t& h, uint32_t& l) {
    __nv_bfloat16 ha = __float2bfloat16_rn(a);
    __nv_bfloat16 hb = __float2bfloat16_rn(b);
    float la = a - __bfloat162float(ha);
    float lb = b - __bfloat162float(hb);
    h = (uint32_t)__bfloat16_as_ushort(ha) | ((uint32_t)__bfloat16_as_ushort(hb) << 16);
    l = pack_bf16(la, lb);
}

// ===========================================================================
// elementwise f32 -> bf16 hi/lo split
// ===========================================================================
__global__ __launch_bounds__(256) void split_f32(
    const float* __restrict__ X, __nv_bfloat16* __restrict__ Xh,
    __nv_bfloat16* __restrict__ Xl, int n4)
{
    int i = blockIdx.x * blockDim.x + threadIdx.x;
    if (i < n4) {
        float4 v = ((const float4*)X)[i];
        uint2 h, l;
        split4(v, h, l);
        ((uint2*)Xh)[i] = h;
        ((uint2*)Xl)[i] = l;
    }
}

// ===========================================================================
// HMMA GEMM mainloop (cp.async 2-stage, pre-split bf16 inputs). Two kernels
// differing only in epilogue. __launch_bounds__(256, 2): 2 CTAs/SM
// (2 x 82KB smem = 165KB < 227KB; regs capped at 128).
// ===========================================================================
#define GBM 128
#define GBN 128
#define GBK 32
#define G_AH 0
#define G_AL 10240
#define G_BH 20480
#define G_BL 30720
#define G_STAGE 40960
#define G_BIAS  81920
#define G_SMEM  (81920 + 512)

#define GEMM_PROLOG                                                           \
    extern __shared__ char gsm[];                                             \
    const uint32_t sbase = smem_u32(gsm);                                     \
    float* bias_s = (float*)(gsm + G_BIAS);                                   \
    const int t = threadIdx.x;                                                \
    const int wid = t >> 5, lane = t & 31;                                    \
    const int n0 = blockIdx.x * GBN;                                          \
    const int m0 = blockIdx.y * GBM;                                          \
    if (t < GBN) bias_s[t] = bias[n0 + t];                                    \
    const int lr = t >> 1;                                                    \
    const int lcp = (t & 1) * 2;                                              \
    const __nv_bfloat16* srcAh = Ahg + (size_t)(m0 + lr) * K + lcp * 8;       \
    const __nv_bfloat16* srcAl = Alg + (size_t)(m0 + lr) * K + lcp * 8;       \
    const __nv_bfloat16* srcBh = Whg + (size_t)(n0 + lr) * K + lcp * 8;       \
    const __nv_bfloat16* srcBl = Wlg + (size_t)(n0 + lr) * K + lcp * 8;       \
    const uint32_t dst_row = sbase + (uint32_t)lr * 80 + (uint32_t)lcp * 16;  \
    const int NITER = K / GBK;

#define G_ISSUE(bufi, kc)                                                     \
    do {                                                                      \
        uint32_t d = dst_row + (bufi) * G_STAGE;                              \
        cp16(d + G_AH,      srcAh + (kc));                                    \
        cp16(d + G_AH + 16, srcAh + (kc) + 8);                                \
        cp16(d + G_AL,      srcAl + (kc));                                    \
        cp16(d + G_AL + 16, srcAl + (kc) + 8);                                \
        cp16(d + G_BH,      srcBh + (kc));                                    \
        cp16(d + G_BH + 16, srcBh + (kc) + 8);                                \
        cp16(d + G_BL,      srcBl + (kc));                                    \
        cp16(d + G_BL + 16, srcBl + (kc) + 8);                                \
    } while (0)

#define GEMM_MAINLOOP                                                         \
    G_ISSUE(0, 0);                                                            \
    asm volatile("cp.async.commit_group;" ::: "memory");                      \
    const int wm = wid >> 2;                                                  \
    const int wn = wid & 3;                                                   \
    const int a_row = lane & 15;                                              \
    const int a_chk = (lane >> 4) & 1;                                        \
    const int b_n   = (lane & 7) + ((lane >> 4) & 1) * 8;                     \
    const int b_chk = (lane >> 3) & 1;                                        \
    float acc[4][4][4];                                                       \
    _Pragma("unroll")                                                         \
    for (int mi = 0; mi < 4; mi++)                                            \
        _Pragma("unroll")                                                     \
        for (int ni = 0; ni < 4; ni++)                                        \
            _Pragma("unroll")                                                 \
            for (int j = 0; j < 4; j++) acc[mi][ni][j] = 0.0f;                \
    for (int it = 0; it < NITER; it++) {                                      \
        const int buf = it & 1;                                               \
        if (it + 1 < NITER) {                                                 \
            G_ISSUE(buf ^ 1, (it + 1) * GBK);                                 \
            asm volatile("cp.async.commit_group;" ::: "memory");              \
            asm volatile("cp.async.wait_group 1;" ::: "memory");              \
        } else {                                                              \
            asm volatile("cp.async.wait_group 0;" ::: "memory");              \
        }                                                                     \
        __syncthreads();                                                      \
        const uint32_t st = sbase + buf * G_STAGE;                            \
        const uint32_t ah_s = st + G_AH, al_s = st + G_AL;                    \
        const uint32_t bh_s = st + G_BH, bl_s = st + G_BL;                    \
        _Pragma("unroll")                                                     \
        for (int s = 0; s < 2; s++) {                                         \
            uint32_t bhf[8], blf[8];                                          \
            _Pragma("unroll")                                                 \
            for (int nt = 0; nt < 2; nt++) {                                  \
                uint32_t boff = (uint32_t)(wn * 32 + nt * 16 + b_n) * 80      \
                              + s * 32 + b_chk * 16;                          \
                ldsm4(bhf + nt * 4, bh_s + boff);                             \
                ldsm4(blf + nt * 4, bl_s + boff);                             \
            }                                                                 \
            _Pragma("unroll")                                                 \
            for (int mi = 0; mi < 4; mi++) {                                  \
                uint32_t aoff = (uint32_t)(wm * 64 + mi * 16 + a_row) * 80    \
                              + s * 32 + a_chk * 16;                          \
                uint32_t ahf[4], alf[4];                                      \
                ldsm4(ahf, ah_s + aoff);                                      \
                ldsm4(alf, al_s + aoff);                                      \
                _Pragma("unroll")                                             \
                for (int ni = 0; ni < 4; ni++) {                              \
                    mma16816(acc[mi][ni], ahf, bhf + ni * 2);                 \
                    mma16816(acc[mi][ni], ahf, blf + ni * 2);                 \
                    mma16816(acc[mi][ni], alf, bhf + ni * 2);                 \
                }                                                             \
            }                                                                 \
        }                                                                     \
        __syncthreads();                                                      \
    }

// fp32 output with mask (Wo projection)
__global__ __launch_bounds__(256, 2) void gemm_tc(
    const __nv_bfloat16* __restrict__ Ahg, const __nv_bfloat16* __restrict__ Alg,
    const __nv_bfloat16* __restrict__ Whg, const __nv_bfloat16* __restrict__ Wlg,
    const float* __restrict__ bias, const float* __restrict__ maskp,
    float* __restrict__ C, int M, int N, int K)
{
    GEMM_PROLOG
    GEMM_MAINLOOP

    const int r0 = lane >> 2;
    const int c0 = (lane & 3) * 2;
#pragma unroll
    for (int mi = 0; mi < 4; mi++) {
        int mA = m0 + wm * 64 + mi * 16 + r0;
        int mB = mA + 8;
        float mkA = maskp ? maskp[mA] : 1.0f;
        float mkB = maskp ? maskp[mB] : 1.0f;
#pragma unroll
        for (int ni = 0; ni < 4; ni++) {
            int n = wn * 32 + ni * 8 + c0;
            float b0 = bias_s[n], b1 = bias_s[n + 1];
            float2 vA, vB;
            vA.x = (acc[mi][ni][0] + b0) * mkA;
            vA.y = (acc[mi][ni][1] + b1) * mkA;
            vB.x = (acc[mi][ni][2] + b0) * mkB;
            vB.y = (acc[mi][ni][3] + b1) * mkB;
            *(float2*)&C[(size_t)mA * N + n0 + n] = vA;
            *(float2*)&C[(size_t)mB * N + n0 + n] = vB;
        }
    }
}

// bf16 hi/lo split output with output scale (Q/K/V projections)
__global__ __launch_bounds__(256, 2) void gemm_tc_split(
    const __nv_bfloat16* __restrict__ Ahg, const __nv_bfloat16* __restrict__ Alg,
    const __nv_bfloat16* __restrict__ Whg, const __nv_bfloat16* __restrict__ Wlg,
    const float* __restrict__ bias, float oscale,
    __nv_bfloat16* __restrict__ Ch, __nv_bfloat16* __restrict__ Cl,
    int M, int N, int K)
{
    GEMM_PROLOG
    GEMM_MAINLOOP

    const int r0 = lane >> 2;
    const int c0 = (lane & 3) * 2;
#pragma unroll
    for (int mi = 0; mi < 4; mi++) {
        int mA = m0 + wm * 64 + mi * 16 + r0;
        int mB = mA + 8;
#pragma unroll
        for (int ni = 0; ni < 4; ni++) {
            int n = wn * 32 + ni * 8 + c0;
            float b0 = bias_s[n], b1 = bias_s[n + 1];
            uint32_t h, l;
            split2((acc[mi][ni][0] + b0) * oscale, (acc[mi][ni][1] + b1) * oscale, h, l);
            *(uint32_t*)&Ch[(size_t)mA * N + n0 + n] = h;
            *(uint32_t*)&Cl[(size_t)mA * N + n0 + n] = l;
            split2((acc[mi][ni][2] + b0) * oscale, (acc[mi][ni][3] + b1) * oscale, h, l);
            *(uint32_t*)&Ch[(size_t)mB * N + n0 + n] = h;
            *(uint32_t*)&Cl[(size_t)mB * N + n0 + n] = l;
        }
    }
}

// ===========================================================================
// Tensor-core flash attention on pre-split bf16 Q/K/V (R7, validated).
// ===========================================================================
#define APITCH 72          /* bf16 elems per smem row (144 B) */
#define A_QHO 0
#define A_QLO 18432
#define A_BUF0 36864
#define A_KHO 0
#define A_KLO 9216
#define A_VHO 18432
#define A_VLO 27648
#define A_TKO 36864
#define A_MKO 37120
#define A_BUFSZ 37888
#define A_SMEM_TOTAL (A_BUF0 + 2 * A_BUFSZ)   /* 112640 */

__global__ __launch_bounds__(256, 1) void attn_tc(
    const __nv_bfloat16* __restrict__ Qh_g, const __nv_bfloat16* __restrict__ Ql_g,
    const __nv_bfloat16* __restrict__ Kh_g, const __nv_bfloat16* __restrict__ Kl_g,
    const __nv_bfloat16* __restrict__ Vh_g, const __nv_bfloat16* __restrict__ Vl_g,
    const float* __restrict__ ts, const float* __restrict__ maskp,
    __nv_bfloat16* __restrict__ Oh_g, __nv_bfloat16* __restrict__ Ol_g, int L)
{
    extern __shared__ char smem[];
    const uint32_t sbase = smem_u32(smem);

    const int t = threadIdx.x, w = t >> 5, lane = t & 31;
    const int q0 = blockIdx.x * 128, h = blockIdx.y, n = blockIdx.z;
    const size_t base = (size_t)n * L * DMODEL + (size_t)h * DH;
    const int nchunk = L / 64;

#define A_ISSUE(bufi, cc)                                                     \
    do {                                                                      \
        const uint32_t bb = sbase + A_BUF0 + (bufi) * A_BUFSZ;                \
        const int kk0 = (cc) * 64;                                            \
        _Pragma("unroll")                                                     \
        for (int idx = t; idx < 512; idx += 256) {                            \
            int row = idx >> 3, ch = idx & 7;                                 \
            size_t g = base + (size_t)(kk0 + row) * DMODEL + ch * 8;          \
            uint32_t doff = (uint32_t)row * 144 + ch * 16;                    \
            cp16(bb + A_KHO + doff, Kh_g + g);                                \
            cp16(bb + A_KLO + doff, Kl_g + g);                                \
            cp16(bb + A_VHO + doff, Vh_g + g);                                \
            cp16(bb + A_VLO + doff, Vl_g + g);                                \
        }                                                                     \
        if (t < 16)                                                           \
            cp16(bb + A_TKO + t * 16, ts + n * L + kk0 + t * 4);              \
        else if (t < 32)                                                      \
            cp16(bb + A_MKO + (t - 16) * 16, maskp + n * L + kk0 + (t - 16) * 4); \
    } while (0)

    // prologue: stream chunk 0 while loading Q
    A_ISSUE(0, 0);
    asm volatile("cp.async.commit_group;" ::: "memory");

    // ---- Q smem load (pre-scaled, pre-split) ----
    {
        __nv_bfloat16* Qh = (__nv_bfloat16*)(smem + A_QHO);
        __nv_bfloat16* Ql = (__nv_bfloat16*)(smem + A_QLO);
#pragma unroll
        for (int idx = t; idx < 1024; idx += 256) {
            int row = idx >> 3, ch = idx & 7;
            size_t g = base + (size_t)(q0 + row) * DMODEL + ch * 8;
            *(uint4*)&Qh[row * APITCH + ch * 8] = *(const uint4*)(Qh_g + g);
            *(uint4*)&Ql[row * APITCH + ch * 8] = *(const uint4*)(Ql_g + g);
        }
    }
    __syncthreads();

    // ---- preload Q fragments ----
    const int a_row = lane & 15, a_chk = (lane >> 4) & 1;
    uint32_t qhf[4][4], qlf[4][4];
#pragma unroll
    for (int ks = 0; ks < 4; ks++) {
        uint32_t aoff = (uint32_t)(w * 16 + a_row) * 144 + ks * 32 + a_chk * 16;
        ldsm4(qhf[ks], sbase + A_QHO + aoff);
        ldsm4(qlf[ks], sbase + A_QLO + aoff);
    }

    const int r0 = lane >> 2, c2 = (lane & 3) * 2;
    const float tq0 = ts[n * L + q0 + w * 16 + r0];
    const float tq1 = ts[n * L + q0 + w * 16 + r0 + 8];

    float o[8][4];
#pragma unroll
    for (int i = 0; i < 8; i++)
#pragma unroll
        for (int j = 0; j < 4; j++) o[i][j] = 0.0f;
    float m0 = -1e30f, m1 = -1e30f, l0 = 0.0f, l1 = 0.0f;

    const int b_n = (lane & 7) + ((lane >> 4) & 1) * 8;
    const int b_chk = (lane >> 3) & 1;
    const int v_row = lane & 15;          // key row within k16
    const int v_col = (lane >> 4) * 8;    // d offset within d16 group

    for (int c = 0; c < nchunk; c++) {
        const int buf = c & 1;
        if (c + 1 < nchunk) {
            A_ISSUE(buf ^ 1, c + 1);
            asm volatile("cp.async.commit_group;" ::: "memory");
            asm volatile("cp.async.wait_group 1;" ::: "memory");
        } else {
            asm volatile("cp.async.wait_group 0;" ::: "memory");
        }
        __syncthreads();

        const uint32_t bb = sbase + A_BUF0 + buf * A_BUFSZ;
        const uint32_t kh_s = bb + A_KHO, kl_s = bb + A_KLO;
        const uint32_t vh_s = bb + A_VHO, vl_s = bb + A_VLO;
        const float* tks = (const float*)(smem + A_BUF0 + buf * A_BUFSZ + A_TKO);
        const float* mks = (const float*)(smem + A_BUF0 + buf * A_BUFSZ + A_MKO);

        // ---- S = Q K^T (3-term split) ----
        float S[8][4];
#pragma unroll
        for (int i = 0; i < 8; i++)
#pragma unroll
            for (int j = 0; j < 4; j++) S[i][j] = 0.0f;
#pragma unroll
        for (int ks = 0; ks < 4; ks++) {
#pragma unroll
            for (int g = 0; g < 4; g++) {
                uint32_t boff = (uint32_t)(g * 16 + b_n) * 144 + ks * 32 + b_chk * 16;
                uint32_t bh[4], bl[4];
                ldsm4(bh, kh_s + boff);
                ldsm4(bl, kl_s + boff);
#pragma unroll
                for (int ni = 0; ni < 2; ni++) {
                    mma16816(S[g * 2 + ni], qhf[ks], bh + ni * 2);
                    mma16816(S[g * 2 + ni], qhf[ks], bl + ni * 2);
                    mma16816(S[g * 2 + ni], qlf[ks], bh + ni * 2);
                }
            }
        }

        // ---- bias + mask + online softmax ----
        float cm0 = -1e30f, cm1 = -1e30f;
#pragma unroll
        for (int nt = 0; nt < 8; nt++) {
#pragma unroll
            for (int j = 0; j < 2; j++) {
                int key = nt * 8 + c2 + j;
                float tk = tks[key];
                bool ok = mks[key] > 0.0f;
                float bA = -fabsf(tq0 - tk) * INV_TAU;
                float bB = -fabsf(tq1 - tk) * INV_TAU;
                S[nt][j]     = ok ? S[nt][j]     + bA : NEGV;
                S[nt][j + 2] = ok ? S[nt][j + 2] + bB : NEGV;
                cm0 = fmaxf(cm0, S[nt][j]);
                cm1 = fmaxf(cm1, S[nt][j + 2]);
            }
        }
#pragma unroll
        for (int off = 1; off <= 2; off <<= 1) {
            cm0 = fmaxf(cm0, __shfl_xor_sync(0xffffffffu, cm0, off));
            cm1 = fmaxf(cm1, __shfl_xor_sync(0xffffffffu, cm1, off));
        }
        float nm0 = fmaxf(m0, cm0), nm1 = fmaxf(m1, cm1);
        float cr0 = __expf(m0 - nm0), cr1 = __expf(m1 - nm1);
        m0 = nm0; m1 = nm1;

        float ps0 = 0.0f, ps1 = 0.0f;
#pragma unroll
        for (int nt = 0; nt < 8; nt++) {
            float p00 = __expf(S[nt][0] - nm0);
            float p01 = __expf(S[nt][1] - nm0);
            float p10 = __expf(S[nt][2] - nm1);
            float p11 = __expf(S[nt][3] - nm1);
            ps0 += p00 + p01; ps1 += p10 + p11;
            S[nt][0] = p00; S[nt][1] = p01; S[nt][2] = p10; S[nt][3] = p11;
        }
#pragma unroll
        for (int off = 1; off <= 2; off <<= 1) {
            ps0 += __shfl_xor_sync(0xffffffffu, ps0, off);
            ps1 += __shfl_xor_sync(0xffffffffu, ps1, off);
        }
        l0 = l0 * cr0 + ps0;
        l1 = l1 * cr1 + ps1;

#pragma unroll
        for (int i = 0; i < 8; i++) {
            o[i][0] *= cr0; o[i][1] *= cr0;
            o[i][2] *= cr1; o[i][3] *= cr1;
        }

        // ---- O += P V : V frags via ldmatrix.trans on [key][d] ----
#pragma unroll
        for (int kt = 0; kt < 4; kt++) {
            uint32_t pah[4], pal[4];
            split2(S[2 * kt][0],     S[2 * kt][1],     pah[0], pal[0]);
            split2(S[2 * kt][2],     S[2 * kt][3],     pah[1], pal[1]);
            split2(S[2 * kt + 1][0], S[2 * kt + 1][1], pah[2], pal[2]);
            split2(S[2 * kt + 1][2], S[2 * kt + 1][3], pah[3], pal[3]);
#pragma unroll
            for (int g = 0; g < 4; g++) {
                uint32_t voff = (uint32_t)(kt * 16 + v_row) * 144
                              + (uint32_t)(g * 16 + v_col) * 2;
                uint32_t bh[4], bl[4];
                ldsm4t(bh, vh_s + voff);
                ldsm4t(bl, vl_s + voff);
#pragma unroll
                for (int ni = 0; ni < 2; ni++) {
                    mma16816(o[g * 2 + ni], pah, bh + ni * 2);
                    mma16816(o[g * 2 + ni], pal, bh + ni * 2);
                    mma16816(o[g * 2 + ni], pah, bl + ni * 2);
                }
            }
        }
        __syncthreads();
    }

    // ---- normalize + split-store ----
    const float inv0 = 1.0f / l0, inv1 = 1.0f / l1;
    const int gr0 = q0 + w * 16 + r0, gr1 = gr0 + 8;
#pragma unroll
    for (int ntd = 0; ntd < 8; ntd++) {
        int d = ntd * 8 + c2;
        uint32_t hh, ll;
        split2(o[ntd][0] * inv0, o[ntd][1] * inv0, hh, ll);
        *(uint32_t*)&Oh_g[base + (size_t)gr0 * DMODEL + d] = hh;
        *(uint32_t*)&Ol_g[base + (size_t)gr0 * DMODEL + d] = ll;
        split2(o[ntd][2] * inv1, o[ntd][3] * inv1, hh, ll);
        *(uint32_t*)&Oh_g[base + (size_t)gr1 * DMODEL + d] = hh;
        *(uint32_t*)&Ol_g[base + (size_t)gr1 * DMODEL + d] = ll;
    }
}

// ---------------------------------------------------------------------------
// Readout pooling: one block per (head, batch). X = masked projected output.
// ---------------------------------------------------------------------------
__global__ __launch_bounds__(256) void pool_kernel(
    const float* __restrict__ X, const float* __restrict__ readout,
    const float* __restrict__ maskp, float* __restrict__ out, int L)
{
    __shared__ float s[512];
    __shared__ float qsh[64];
    __shared__ float red[8];
    __shared__ float part[8][64];
    const int h = blockIdx.x, n = blockIdx.y;
    const int t = threadIdx.x, w = t >> 5, lane = t & 31;
    if (t < 64) qsh[t] = readout[h * DH + t] * SCALE;
    __syncthreads();
    const size_t base = (size_t)n * L * DMODEL + (size_t)h * DH;

    for (int k = w; k < L; k += 8) {
        float d = X[base + (size_t)k * DMODEL + lane] * qsh[lane]
                + X[base + (size_t)k * DMODEL + lane + 32] * qsh[lane + 32];
#pragma unroll
        for (int o = 16; o > 0; o >>= 1) d += __shfl_xor_sync(0xffffffffu, d, o);
        if (lane == 0) s[k] = (maskp[n * L + k] > 0.f) ? d : NEGV;
    }
    __syncthreads();

    float lm = -1e30f;
    for (int k = t; k < L; k += 256) lm = fmaxf(lm, s[k]);
#pragma unroll
    for (int o = 16; o > 0; o >>= 1) lm = fmaxf(lm, __shfl_xor_sync(0xffffffffu, lm, o));
    if (lane == 0) red[w] = lm;
    __syncthreads();
    float gm = red[0];
#pragma unroll
    for (int i = 1; i < 8; i++) gm = fmaxf(gm, red[i]);
    __syncthreads();
    float ls = 0.f;
    for (int k = t; k < L; k += 256) { float p = expf(s[k] - gm); s[k] = p; ls += p; }
#pragma unroll
    for (int o = 16; o > 0; o >>= 1) ls += __shfl_xor_sync(0xffffffffu, ls, o);
    if (lane == 0) red[w] = ls;
    __syncthreads();
    float gs = 0.f;
#pragma unroll
    for (int i = 0; i < 8; i++) gs += red[i];
    float inv = 1.0f / gs;

    const int kb = w * (L / 8), ke = kb + (L / 8);
    float a0 = 0.f, a1 = 0.f;
    for (int k = kb; k < ke; k++) {
        float p = s[k];
        a0 = fmaf(p, X[base + (size_t)k * DMODEL + lane], a0);
        a1 = fmaf(p, X[base + (size_t)k * DMODEL + lane + 32], a1);
    }
    part[w][lane]      = a0;
    part[w][lane + 32] = a1;
    __syncthreads();
    if (t < 64) {
        float sum = 0.f;
#pragma unroll
        for (int i = 0; i < 8; i++) sum += part[i][t];
        out[(size_t)n * DMODEL + h * DH + t] = sum * inv;
    }
}

// ---------------------------------------------------------------------------
extern "C" void kernel_launch(void* const* d_in, const int* in_sizes, int n_in,
                              void* d_out, int out_size)
{
    const float* tokens  = (const float*)d_in[0];
    const float* ts      = (const float*)d_in[1];
    const float* maskp   = (const float*)d_in[2];
    const float* Wq      = (const float*)d_in[3];
    const float* bq      = (const float*)d_in[4];
    const float* Wk      = (const float*)d_in[5];
    const float* bk      = (const float*)d_in[6];
    const float* Wv      = (const float*)d_in[7];
    const float* bv      = (const float*)d_in[8];
    const float* Wo      = (const float*)d_in[9];
    const float* bo      = (const float*)d_in[10];
    const float* readout = (const float*)d_in[11];
    float* out = (float*)d_out;
    (void)n_in;

    const int M  = in_sizes[0] / DMODEL;   // N*L = 32768
    const int Nb = out_size / DMODEL;      // 64
    const int L  = M / Nb;                 // 512

    float* gP;
    __nv_bfloat16 *gth, *gtl, *gwh, *gwl, *gqh, *gql, *gkh, *gkl, *gvh, *gvl;
    cudaGetSymbolAddress((void**)&gP, g_P);
    cudaGetSymbolAddress((void**)&gth, g_th);
    cudaGetSymbolAddress((void**)&gtl, g_tl);
    cudaGetSymbolAddress((void**)&gwh, g_wh);
    cudaGetSymbolAddress((void**)&gwl, g_wl);
    cudaGetSymbolAddress((void**)&gqh, g_qh);
    cudaGetSymbolAddress((void**)&gql, g_ql);
    cudaGetSymbolAddress((void**)&gkh, g_kh);
    cudaGetSymbolAddress((void**)&gkl, g_kl);
    cudaGetSymbolAddress((void**)&gvh, g_vh);
    cudaGetSymbolAddress((void**)&gvl, g_vl);

    // ---- pre-split inputs to bf16 hi/lo ----
    const int tok4 = M * DMODEL / 4;
    split_f32<<<(tok4 + 255) / 256, 256>>>(tokens, gth, gtl, tok4);
    const int w4 = WSZ / 4;
    split_f32<<<(w4 + 255) / 256, 256>>>(Wq, gwh + 0 * WSZ, gwl + 0 * WSZ, w4);
    split_f32<<<(w4 + 255) / 256, 256>>>(Wk, gwh + 1 * WSZ, gwl + 1 * WSZ, w4);
    split_f32<<<(w4 + 255) / 256, 256>>>(Wv, gwh + 2 * WSZ, gwl + 2 * WSZ, w4);
    split_f32<<<(w4 + 255) / 256, 256>>>(Wo, gwh + 3 * WSZ, gwl + 3 * WSZ, w4);

    cudaFuncSetAttribute(gemm_tc, cudaFuncAttributeMaxDynamicSharedMemorySize, G_SMEM);
    cudaFuncSetAttribute(gemm_tc_split, cudaFuncAttributeMaxDynamicSharedMemorySize, G_SMEM);
    dim3 gg(DMODEL / GBN, M / GBM);
    gemm_tc_split<<<gg, 256, G_SMEM>>>(gth, gtl, gwh + 0 * WSZ, gwl + 0 * WSZ, bq,
                                       SCALE, gqh, gql, M, DMODEL, DMODEL);
    gemm_tc_split<<<gg, 256, G_SMEM>>>(gth, gtl, gwh + 1 * WSZ, gwl + 1 * WSZ, bk,
                                       1.0f, gkh, gkl, M, DMODEL, DMODEL);
    gemm_tc_split<<<gg, 256, G_SMEM>>>(gth, gtl, gwh + 2 * WSZ, gwl + 2 * WSZ, bv,
                                       1.0f, gvh, gvl, M, DMODEL, DMODEL);

    cudaFuncSetAttribute(attn_tc, cudaFuncAttributeMaxDynamicSharedMemorySize,
                         A_SMEM_TOTAL);
    dim3 ag(L / 128, NHEAD, Nb);
    // attention writes split bf16 output into the token-split buffers (free now)
    attn_tc<<<ag, 256, A_SMEM_TOTAL>>>(gqh, gql, gkh, gkl, gvh, gvl, ts, maskp,
                                       gth, gtl, L);

    gemm_tc<<<gg, 256, G_SMEM>>>(gth, gtl, gwh + 3 * WSZ, gwl + 3 * WSZ, bo, maskp,
                                 gP, M, DMODEL, DMODEL);

    dim3 pg(NHEAD, Nb);
    pool_kernel<<<pg, 256>>>(gP, readout, maskp, out, L);
}

// round 9
// speedup vs baseline: 1.6151x; 1.0290x over previous
#include <cuda_runtime.h>
#include <cuda_bf16.h>
#include <math.h>
#include <stdint.h>

#define DMODEL 768
#define NHEAD  12
#define DH     64
#define TAU    300.0f
#define INV_TAU (1.0f / 300.0f)
#define NEGV   (-1e9f)
#define SCALE  0.125f   /* 1/sqrt(64) */

#define MAXM (64 * 512)
#define WSZ  (DMODEL * DMODEL)

// fp32 scratch: final projected+masked output (pool input)
__device__ float g_P[MAXM * DMODEL];
// bf16 hi/lo split scratch
__device__ __nv_bfloat16 g_th[MAXM * DMODEL];   // tokens split -> then attn-out split
__device__ __nv_bfloat16 g_tl[MAXM * DMODEL];
__device__ __nv_bfloat16 g_qh[MAXM * DMODEL];
__device__ __nv_bfloat16 g_ql[MAXM * DMODEL];
__device__ __nv_bfloat16 g_kh[MAXM * DMODEL];
__device__ __nv_bfloat16 g_kl[MAXM * DMODEL];
__device__ __nv_bfloat16 g_vh[MAXM * DMODEL];
__device__ __nv_bfloat16 g_vl[MAXM * DMODEL];
__device__ __nv_bfloat16 g_wh[4 * WSZ];
__device__ __nv_bfloat16 g_wl[4 * WSZ];

// ===========================================================================
// helpers
// ===========================================================================
__device__ __forceinline__ uint32_t smem_u32(const void* p) {
    uint32_t a;
    asm("{ .reg .u64 t; cvta.to.shared.u64 t, %1; cvt.u32.u64 %0, t; }"
        : "=r"(a) : "l"(p));
    return a;
}

__device__ __forceinline__ void ldsm4(uint32_t* r, uint32_t addr) {
    asm volatile("ldmatrix.sync.aligned.m8n8.x4.shared.b16 {%0,%1,%2,%3}, [%4];"
                 : "=r"(r[0]), "=r"(r[1]), "=r"(r[2]), "=r"(r[3]) : "r"(addr));
}
__device__ __forceinline__ void ldsm4t(uint32_t* r, uint32_t addr) {
    asm volatile("ldmatrix.sync.aligned.m8n8.x4.trans.shared.b16 {%0,%1,%2,%3}, [%4];"
                 : "=r"(r[0]), "=r"(r[1]), "=r"(r[2]), "=r"(r[3]) : "r"(addr));
}

__device__ __forceinline__ void mma16816(float* c, const uint32_t* a,
                                         const uint32_t* b) {
    asm volatile(
        "mma.sync.aligned.m16n8k16.row.col.f32.bf16.bf16.f32 "
        "{%0,%1,%2,%3}, {%4,%5,%6,%7}, {%8,%9}, {%0,%1,%2,%3};"
        : "+f"(c[0]), "+f"(c[1]), "+f"(c[2]), "+f"(c[3])
        : "r"(a[0]), "r"(a[1]), "r"(a[2]), "r"(a[3]), "r"(b[0]), "r"(b[1]));
}

__device__ __forceinline__ void cp16(uint32_t dst, const void* src) {
    asm volatile("cp.async.cg.shared.global [%0], [%1], 16;"
                 :: "r"(dst), "l"(src));
}

__device__ __forceinline__ void split4(float4 v, uint2& h, uint2& l) {
    __nv_bfloat16 h0 = __float2bfloat16_rn(v.x);
    __nv_bfloat16 h1 = __float2bfloat16_rn(v.y);
    __nv_bfloat16 h2 = __float2bfloat16_rn(v.z);
    __nv_bfloat16 h3 = __float2bfloat16_rn(v.w);
    __nv_bfloat16 l0 = __float2bfloat16_rn(v.x - __bfloat162float(h0));
    __nv_bfloat16 l1 = __float2bfloat16_rn(v.y - __bfloat162float(h1));
    __nv_bfloat16 l2 = __float2bfloat16_rn(v.z - __bfloat162float(h2));
    __nv_bfloat16 l3 = __float2bfloat16_rn(v.w - __bfloat162float(h3));
    h.x = (uint32_t)__bfloat16_as_ushort(h0) | ((uint32_t)__bfloat16_as_ushort(h1) << 16);
    h.y = (uint32_t)__bfloat16_as_ushort(h2) | ((uint32_t)__bfloat16_as_ushort(h3) << 16);
    l.x = (uint32_t)__bfloat16_as_ushort(l0) | ((uint32_t)__bfloat16_as_ushort(l1) << 16);
    l.y = (uint32_t)__bfloat16_as_ushort(l2) | ((uint32_t)__bfloat16_as_ushort(l3) << 16);
}

__device__ __forceinline__ uint32_t pack_bf16(float a, float b) {
    __nv_bfloat162 t = __floats2bfloat162_rn(a, b);
    return *(uint32_t*)&t;
}
__device__ __forceinline__ void split2(float a, float b, uint32_t& h, uint32_t& l) {
    __nv_bfloat16 ha = __float2bfloat16_rn(a);
    __nv_bfloat16 hb = __float2bfloat16_rn(b);
    float la = a - __bfloat162float(ha);
    float lb = b - __bfloat162float(hb);
    h = (uint32_t)__bfloat16_as_ushort(ha) | ((uint32_t)__bfloat16_as_ushort(hb) << 16);
    l = pack_bf16(la, lb);
}

// ===========================================================================
// elementwise f32 -> bf16 hi/lo split
// ===========================================================================
__global__ __launch_bounds__(256) void split_f32(
    const float* __restrict__ X, __nv_bfloat16* __restrict__ Xh,
    __nv_bfloat16* __restrict__ Xl, int n4)
{
    int i = blockIdx.x * blockDim.x + threadIdx.x;
    if (i < n4) {
        float4 v = ((const float4*)X)[i];
        uint2 h, l;
        split4(v, h, l);
        ((uint2*)Xh)[i] = h;
        ((uint2*)Xl)[i] = l;
    }
}

// ===========================================================================
// HMMA GEMM mainloop (cp.async 2-stage, pre-split bf16 inputs). Two kernels
// differing only in epilogue. __launch_bounds__(256, 2): 2 CTAs/SM.
// ===========================================================================
#define GBM 128
#define GBN 128
#define GBK 32
#define G_AH 0
#define G_AL 10240
#define G_BH 20480
#define G_BL 30720
#define G_STAGE 40960
#define G_BIAS  81920
#define G_SMEM  (81920 + 512)

#define GEMM_PROLOG                                                           \
    extern __shared__ char gsm[];                                             \
    const uint32_t sbase = smem_u32(gsm);                                     \
    float* bias_s = (float*)(gsm + G_BIAS);                                   \
    const int t = threadIdx.x;                                                \
    const int wid = t >> 5, lane = t & 31;                                    \
    const int n0 = blockIdx.x * GBN;                                          \
    const int m0 = blockIdx.y * GBM;                                          \
    if (t < GBN) bias_s[t] = bias[n0 + t];                                    \
    const int lr = t >> 1;                                                    \
    const int lcp = (t & 1) * 2;                                              \
    const __nv_bfloat16* srcAh = Ahg + (size_t)(m0 + lr) * K + lcp * 8;       \
    const __nv_bfloat16* srcAl = Alg + (size_t)(m0 + lr) * K + lcp * 8;       \
    const __nv_bfloat16* srcBh = Whg + (size_t)(n0 + lr) * K + lcp * 8;       \
    const __nv_bfloat16* srcBl = Wlg + (size_t)(n0 + lr) * K + lcp * 8;       \
    const uint32_t dst_row = sbase + (uint32_t)lr * 80 + (uint32_t)lcp * 16;  \
    const int NITER = K / GBK;

#define G_ISSUE(bufi, kc)                                                     \
    do {                                                                      \
        uint32_t d = dst_row + (bufi) * G_STAGE;                              \
        cp16(d + G_AH,      srcAh + (kc));                                    \
        cp16(d + G_AH + 16, srcAh + (kc) + 8);                                \
        cp16(d + G_AL,      srcAl + (kc));                                    \
        cp16(d + G_AL + 16, srcAl + (kc) + 8);                                \
        cp16(d + G_BH,      srcBh + (kc));                                    \
        cp16(d + G_BH + 16, srcBh + (kc) + 8);                                \
        cp16(d + G_BL,      srcBl + (kc));                                    \
        cp16(d + G_BL + 16, srcBl + (kc) + 8);                                \
    } while (0)

#define GEMM_MAINLOOP                                                         \
    G_ISSUE(0, 0);                                                            \
    asm volatile("cp.async.commit_group;" ::: "memory");                      \
    const int wm = wid >> 2;                                                  \
    const int wn = wid & 3;                                                   \
    const int a_row = lane & 15;                                              \
    const int a_chk = (lane >> 4) & 1;                                        \
    const int b_n   = (lane & 7) + ((lane >> 4) & 1) * 8;                     \
    const int b_chk = (lane >> 3) & 1;                                        \
    float acc[4][4][4];                                                       \
    _Pragma("unroll")                                                         \
    for (int mi = 0; mi < 4; mi++)                                            \
        _Pragma("unroll")                                                     \
        for (int ni = 0; ni < 4; ni++)                                        \
            _Pragma("unroll")                                                 \
            for (int j = 0; j < 4; j++) acc[mi][ni][j] = 0.0f;                \
    for (int it = 0; it < NITER; it++) {                                      \
        const int buf = it & 1;                                               \
        if (it + 1 < NITER) {                                                 \
            G_ISSUE(buf ^ 1, (it + 1) * GBK);                                 \
            asm volatile("cp.async.commit_group;" ::: "memory");              \
            asm volatile("cp.async.wait_group 1;" ::: "memory");              \
        } else {                                                              \
            asm volatile("cp.async.wait_group 0;" ::: "memory");              \
        }                                                                     \
        __syncthreads();                                                      \
        const uint32_t st = sbase + buf * G_STAGE;                            \
        const uint32_t ah_s = st + G_AH, al_s = st + G_AL;                    \
        const uint32_t bh_s = st + G_BH, bl_s = st + G_BL;                    \
        _Pragma("unroll")                                                     \
        for (int s = 0; s < 2; s++) {                                         \
            uint32_t bhf[8], blf[8];                                          \
            _Pragma("unroll")                                                 \
            for (int nt = 0; nt < 2; nt++) {                                  \
                uint32_t boff = (uint32_t)(wn * 32 + nt * 16 + b_n) * 80      \
                              + s * 32 + b_chk * 16;                          \
                ldsm4(bhf + nt * 4, bh_s + boff);                             \
                ldsm4(blf + nt * 4, bl_s + boff);                             \
            }                                                                 \
            _Pragma("unroll")                                                 \
            for (int mi = 0; mi < 4; mi++) {                                  \
                uint32_t aoff = (uint32_t)(wm * 64 + mi * 16 + a_row) * 80    \
                              + s * 32 + a_chk * 16;                          \
                uint32_t ahf[4], alf[4];                                      \
                ldsm4(ahf, ah_s + aoff);                                      \
                ldsm4(alf, al_s + aoff);                                      \
                _Pragma("unroll")                                             \
                for (int ni = 0; ni < 4; ni++) {                              \
                    mma16816(acc[mi][ni], ahf, bhf + ni * 2);                 \
                    mma16816(acc[mi][ni], ahf, blf + ni * 2);                 \
                    mma16816(acc[mi][ni], alf, bhf + ni * 2);                 \
                }                                                             \
            }                                                                 \
        }                                                                     \
        __syncthreads();                                                      \
    }

// fp32 output with mask (Wo projection)
__global__ __launch_bounds__(256, 2) void gemm_tc(
    const __nv_bfloat16* __restrict__ Ahg, const __nv_bfloat16* __restrict__ Alg,
    const __nv_bfloat16* __restrict__ Whg, const __nv_bfloat16* __restrict__ Wlg,
    const float* __restrict__ bias, const float* __restrict__ maskp,
    float* __restrict__ C, int M, int N, int K)
{
    GEMM_PROLOG
    GEMM_MAINLOOP

    const int r0 = lane >> 2;
    const int c0 = (lane & 3) * 2;
#pragma unroll
    for (int mi = 0; mi < 4; mi++) {
        int mA = m0 + wm * 64 + mi * 16 + r0;
        int mB = mA + 8;
        float mkA = maskp ? maskp[mA] : 1.0f;
        float mkB = maskp ? maskp[mB] : 1.0f;
#pragma unroll
        for (int ni = 0; ni < 4; ni++) {
            int n = wn * 32 + ni * 8 + c0;
            float b0 = bias_s[n], b1 = bias_s[n + 1];
            float2 vA, vB;
            vA.x = (acc[mi][ni][0] + b0) * mkA;
            vA.y = (acc[mi][ni][1] + b1) * mkA;
            vB.x = (acc[mi][ni][2] + b0) * mkB;
            vB.y = (acc[mi][ni][3] + b1) * mkB;
            *(float2*)&C[(size_t)mA * N + n0 + n] = vA;
            *(float2*)&C[(size_t)mB * N + n0 + n] = vB;
        }
    }
}

// bf16 hi/lo split output with output scale (Q/K/V projections)
__global__ __launch_bounds__(256, 2) void gemm_tc_split(
    const __nv_bfloat16* __restrict__ Ahg, const __nv_bfloat16* __restrict__ Alg,
    const __nv_bfloat16* __restrict__ Whg, const __nv_bfloat16* __restrict__ Wlg,
    const float* __restrict__ bias, float oscale,
    __nv_bfloat16* __restrict__ Ch, __nv_bfloat16* __restrict__ Cl,
    int M, int N, int K)
{
    GEMM_PROLOG
    GEMM_MAINLOOP

    const int r0 = lane >> 2;
    const int c0 = (lane & 3) * 2;
#pragma unroll
    for (int mi = 0; mi < 4; mi++) {
        int mA = m0 + wm * 64 + mi * 16 + r0;
        int mB = mA + 8;
#pragma unroll
        for (int ni = 0; ni < 4; ni++) {
            int n = wn * 32 + ni * 8 + c0;
            float b0 = bias_s[n], b1 = bias_s[n + 1];
            uint32_t h, l;
            split2((acc[mi][ni][0] + b0) * oscale, (acc[mi][ni][1] + b1) * oscale, h, l);
            *(uint32_t*)&Ch[(size_t)mA * N + n0 + n] = h;
            *(uint32_t*)&Cl[(size_t)mA * N + n0 + n] = l;
            split2((acc[mi][ni][2] + b0) * oscale, (acc[mi][ni][3] + b1) * oscale, h, l);
            *(uint32_t*)&Ch[(size_t)mB * N + n0 + n] = h;
            *(uint32_t*)&Cl[(size_t)mB * N + n0 + n] = l;
        }
    }
}

// ===========================================================================
// Tensor-core flash attention on pre-split bf16 Q/K/V. Occupancy 2
// (2 x 112.6KB smem = 225KB <= 228KB/SM; regs capped at 128 by re-loading
// Q fragments from smem per k-step instead of keeping them resident).
// ===========================================================================
#define APITCH 72          /* bf16 elems per smem row (144 B) */
#define A_QHO 0
#define A_QLO 18432
#define A_BUF0 36864
#define A_KHO 0
#define A_KLO 9216
#define A_VHO 18432
#define A_VLO 27648
#define A_TKO 36864
#define A_MKO 37120
#define A_BUFSZ 37888
#define A_SMEM_TOTAL (A_BUF0 + 2 * A_BUFSZ)   /* 112640 */

__global__ __launch_bounds__(256, 2) void attn_tc(
    const __nv_bfloat16* __restrict__ Qh_g, const __nv_bfloat16* __restrict__ Ql_g,
    const __nv_bfloat16* __restrict__ Kh_g, const __nv_bfloat16* __restrict__ Kl_g,
    const __nv_bfloat16* __restrict__ Vh_g, const __nv_bfloat16* __restrict__ Vl_g,
    const float* __restrict__ ts, const float* __restrict__ maskp,
    __nv_bfloat16* __restrict__ Oh_g, __nv_bfloat16* __restrict__ Ol_g, int L)
{
    extern __shared__ char smem[];
    const uint32_t sbase = smem_u32(smem);

    const int t = threadIdx.x, w = t >> 5, lane = t & 31;
    const int q0 = blockIdx.x * 128, h = blockIdx.y, n = blockIdx.z;
    const size_t base = (size_t)n * L * DMODEL + (size_t)h * DH;
    const int nchunk = L / 64;

#define A_ISSUE(bufi, cc)                                                     \
    do {                                                                      \
        const uint32_t bb = sbase + A_BUF0 + (bufi) * A_BUFSZ;                \
        const int kk0 = (cc) * 64;                                            \
        _Pragma("unroll")                                                     \
        for (int idx = t; idx < 512; idx += 256) {                            \
            int row = idx >> 3, ch = idx & 7;                                 \
            size_t g = base + (size_t)(kk0 + row) * DMODEL + ch * 8;          \
            uint32_t doff = (uint32_t)row * 144 + ch * 16;                    \
            cp16(bb + A_KHO + doff, Kh_g + g);                                \
            cp16(bb + A_KLO + doff, Kl_g + g);                                \
            cp16(bb + A_VHO + doff, Vh_g + g);                                \
            cp16(bb + A_VLO + doff, Vl_g + g);                                \
        }                                                                     \
        if (t < 16)                                                           \
            cp16(bb + A_TKO + t * 16, ts + n * L + kk0 + t * 4);              \
        else if (t < 32)                                                      \
            cp16(bb + A_MKO + (t - 16) * 16, maskp + n * L + kk0 + (t - 16) * 4); \
    } while (0)

    // prologue: stream chunk 0 while loading Q
    A_ISSUE(0, 0);
    asm volatile("cp.async.commit_group;" ::: "memory");

    // ---- Q smem load (pre-scaled, pre-split) ----
    {
        __nv_bfloat16* Qh = (__nv_bfloat16*)(smem + A_QHO);
        __nv_bfloat16* Ql = (__nv_bfloat16*)(smem + A_QLO);
#pragma unroll
        for (int idx = t; idx < 1024; idx += 256) {
            int row = idx >> 3, ch = idx & 7;
            size_t g = base + (size_t)(q0 + row) * DMODEL + ch * 8;
            *(uint4*)&Qh[row * APITCH + ch * 8] = *(const uint4*)(Qh_g + g);
            *(uint4*)&Ql[row * APITCH + ch * 8] = *(const uint4*)(Ql_g + g);
        }
    }
    __syncthreads();

    const int a_row = lane & 15, a_chk = (lane >> 4) & 1;
    const int r0 = lane >> 2, c2 = (lane & 3) * 2;
    const float tq0 = ts[n * L + q0 + w * 16 + r0];
    const float tq1 = ts[n * L + q0 + w * 16 + r0 + 8];

    float o[8][4];
#pragma unroll
    for (int i = 0; i < 8; i++)
#pragma unroll
        for (int j = 0; j < 4; j++) o[i][j] = 0.0f;
    float m0 = -1e30f, m1 = -1e30f, l0 = 0.0f, l1 = 0.0f;

    const int b_n = (lane & 7) + ((lane >> 4) & 1) * 8;
    const int b_chk = (lane >> 3) & 1;
    const int v_row = lane & 15;          // key row within k16
    const int v_col = (lane >> 4) * 8;    // d offset within d16 group

    for (int c = 0; c < nchunk; c++) {
        const int buf = c & 1;
        if (c + 1 < nchunk) {
            A_ISSUE(buf ^ 1, c + 1);
            asm volatile("cp.async.commit_group;" ::: "memory");
            asm volatile("cp.async.wait_group 1;" ::: "memory");
        } else {
            asm volatile("cp.async.wait_group 0;" ::: "memory");
        }
        __syncthreads();

        const uint32_t bb = sbase + A_BUF0 + buf * A_BUFSZ;
        const uint32_t kh_s = bb + A_KHO, kl_s = bb + A_KLO;
        const uint32_t vh_s = bb + A_VHO, vl_s = bb + A_VLO;
        const float* tks = (const float*)(smem + A_BUF0 + buf * A_BUFSZ + A_TKO);
        const float* mks = (const float*)(smem + A_BUF0 + buf * A_BUFSZ + A_MKO);

        // ---- S = Q K^T (3-term split; Q frags re-loaded per k-step) ----
        float S[8][4];
#pragma unroll
        for (int i = 0; i < 8; i++)
#pragma unroll
            for (int j = 0; j < 4; j++) S[i][j] = 0.0f;
#pragma unroll
        for (int ks = 0; ks < 4; ks++) {
            uint32_t qh4[4], ql4[4];
            uint32_t aoff = (uint32_t)(w * 16 + a_row) * 144 + ks * 32 + a_chk * 16;
            ldsm4(qh4, sbase + A_QHO + aoff);
            ldsm4(ql4, sbase + A_QLO + aoff);
#pragma unroll
            for (int g = 0; g < 4; g++) {
                uint32_t boff = (uint32_t)(g * 16 + b_n) * 144 + ks * 32 + b_chk * 16;
                uint32_t bh[4], bl[4];
                ldsm4(bh, kh_s + boff);
                ldsm4(bl, kl_s + boff);
#pragma unroll
                for (int ni = 0; ni < 2; ni++) {
                    mma16816(S[g * 2 + ni], qh4, bh + ni * 2);
                    mma16816(S[g * 2 + ni], qh4, bl + ni * 2);
                    mma16816(S[g * 2 + ni], ql4, bh + ni * 2);
                }
            }
        }

        // ---- bias + mask + online softmax ----
        float cm0 = -1e30f, cm1 = -1e30f;
#pragma unroll
        for (int nt = 0; nt < 8; nt++) {
#pragma unroll
            for (int j = 0; j < 2; j++) {
                int key = nt * 8 + c2 + j;
                float tk = tks[key];
                bool ok = mks[key] > 0.0f;
                float bA = -fabsf(tq0 - tk) * INV_TAU;
                float bB = -fabsf(tq1 - tk) * INV_TAU;
                S[nt][j]     = ok ? S[nt][j]     + bA : NEGV;
                S[nt][j + 2] = ok ? S[nt][j + 2] + bB : NEGV;
                cm0 = fmaxf(cm0, S[nt][j]);
                cm1 = fmaxf(cm1, S[nt][j + 2]);
            }
        }
#pragma unroll
        for (int off = 1; off <= 2; off <<= 1) {
            cm0 = fmaxf(cm0, __shfl_xor_sync(0xffffffffu, cm0, off));
            cm1 = fmaxf(cm1, __shfl_xor_sync(0xffffffffu, cm1, off));
        }
        float nm0 = fmaxf(m0, cm0), nm1 = fmaxf(m1, cm1);
        float cr0 = __expf(m0 - nm0), cr1 = __expf(m1 - nm1);
        m0 = nm0; m1 = nm1;

        float ps0 = 0.0f, ps1 = 0.0f;
#pragma unroll
        for (int nt = 0; nt < 8; nt++) {
            float p00 = __expf(S[nt][0] - nm0);
            float p01 = __expf(S[nt][1] - nm0);
            float p10 = __expf(S[nt][2] - nm1);
            float p11 = __expf(S[nt][3] - nm1);
            ps0 += p00 + p01; ps1 += p10 + p11;
            S[nt][0] = p00; S[nt][1] = p01; S[nt][2] = p10; S[nt][3] = p11;
        }
#pragma unroll
        for (int off = 1; off <= 2; off <<= 1) {
            ps0 += __shfl_xor_sync(0xffffffffu, ps0, off);
            ps1 += __shfl_xor_sync(0xffffffffu, ps1, off);
        }
        l0 = l0 * cr0 + ps0;
        l1 = l1 * cr1 + ps1;

#pragma unroll
        for (int i = 0; i < 8; i++) {
            o[i][0] *= cr0; o[i][1] *= cr0;
            o[i][2] *= cr1; o[i][3] *= cr1;
        }

        // ---- O += P V : V frags via ldmatrix.trans on [key][d] ----
#pragma unroll
        for (int kt = 0; kt < 4; kt++) {
            uint32_t pah[4], pal[4];
            split2(S[2 * kt][0],     S[2 * kt][1],     pah[0], pal[0]);
            split2(S[2 * kt][2],     S[2 * kt][3],     pah[1], pal[1]);
            split2(S[2 * kt + 1][0], S[2 * kt + 1][1], pah[2], pal[2]);
            split2(S[2 * kt + 1][2], S[2 * kt + 1][3], pah[3], pal[3]);
#pragma unroll
            for (int g = 0; g < 4; g++) {
                uint32_t voff = (uint32_t)(kt * 16 + v_row) * 144
                              + (uint32_t)(g * 16 + v_col) * 2;
                uint32_t bh[4], bl[4];
                ldsm4t(bh, vh_s + voff);
                ldsm4t(bl, vl_s + voff);
#pragma unroll
                for (int ni = 0; ni < 2; ni++) {
                    mma16816(o[g * 2 + ni], pah, bh + ni * 2);
                    mma16816(o[g * 2 + ni], pal, bh + ni * 2);
                    mma16816(o[g * 2 + ni], pah, bl + ni * 2);
                }
            }
        }
        __syncthreads();
    }

    // ---- normalize + split-store ----
    const float inv0 = 1.0f / l0, inv1 = 1.0f / l1;
    const int gr0 = q0 + w * 16 + r0, gr1 = gr0 + 8;
#pragma unroll
    for (int ntd = 0; ntd < 8; ntd++) {
        int d = ntd * 8 + c2;
        uint32_t hh, ll;
        split2(o[ntd][0] * inv0, o[ntd][1] * inv0, hh, ll);
        *(uint32_t*)&Oh_g[base + (size_t)gr0 * DMODEL + d] = hh;
        *(uint32_t*)&Ol_g[base + (size_t)gr0 * DMODEL + d] = ll;
        split2(o[ntd][2] * inv1, o[ntd][3] * inv1, hh, ll);
        *(uint32_t*)&Oh_g[base + (size_t)gr1 * DMODEL + d] = hh;
        *(uint32_t*)&Ol_g[base + (size_t)gr1 * DMODEL + d] = ll;
    }
}

// ---------------------------------------------------------------------------
// Readout pooling: one block per (head, batch). X = masked projected output.
// ---------------------------------------------------------------------------
__global__ __launch_bounds__(256) void pool_kernel(
    const float* __restrict__ X, const float* __restrict__ readout,
    const float* __restrict__ maskp, float* __restrict__ out, int L)
{
    __shared__ float s[512];
    __shared__ float qsh[64];
    __shared__ float red[8];
    __shared__ float part[8][64];
    const int h = blockIdx.x, n = blockIdx.y;
    const int t = threadIdx.x, w = t >> 5, lane = t & 31;
    if (t < 64) qsh[t] = readout[h * DH + t] * SCALE;
    __syncthreads();
    const size_t base = (size_t)n * L * DMODEL + (size_t)h * DH;

    for (int k = w; k < L; k += 8) {
        float d = X[base + (size_t)k * DMODEL + lane] * qsh[lane]
                + X[base + (size_t)k * DMODEL + lane + 32] * qsh[lane + 32];
#pragma unroll
        for (int o = 16; o > 0; o >>= 1) d += __shfl_xor_sync(0xffffffffu, d, o);
        if (lane == 0) s[k] = (maskp[n * L + k] > 0.f) ? d : NEGV;
    }
    __syncthreads();

    float lm = -1e30f;
    for (int k = t; k < L; k += 256) lm = fmaxf(lm, s[k]);
#pragma unroll
    for (int o = 16; o > 0; o >>= 1) lm = fmaxf(lm, __shfl_xor_sync(0xffffffffu, lm, o));
    if (lane == 0) red[w] = lm;
    __syncthreads();
    float gm = red[0];
#pragma unroll
    for (int i = 1; i < 8; i++) gm = fmaxf(gm, red[i]);
    __syncthreads();
    float ls = 0.f;
    for (int k = t; k < L; k += 256) { float p = expf(s[k] - gm); s[k] = p; ls += p; }
#pragma unroll
    for (int o = 16; o > 0; o >>= 1) ls += __shfl_xor_sync(0xffffffffu, ls, o);
    if (lane == 0) red[w] = ls;
    __syncthreads();
    float gs = 0.f;
#pragma unroll
    for (int i = 0; i < 8; i++) gs += red[i];
    float inv = 1.0f / gs;

    const int kb = w * (L / 8), ke = kb + (L / 8);
    float a0 = 0.f, a1 = 0.f;
    for (int k = kb; k < ke; k++) {
        float p = s[k];
        a0 = fmaf(p, X[base + (size_t)k * DMODEL + lane], a0);
        a1 = fmaf(p, X[base + (size_t)k * DMODEL + lane + 32], a1);
    }
    part[w][lane]      = a0;
    part[w][lane + 32] = a1;
    __syncthreads();
    if (t < 64) {
        float sum = 0.f;
#pragma unroll
        for (int i = 0; i < 8; i++) sum += part[i][t];
        out[(size_t)n * DMODEL + h * DH + t] = sum * inv;
    }
}

// ---------------------------------------------------------------------------
extern "C" void kernel_launch(void* const* d_in, const int* in_sizes, int n_in,
                              void* d_out, int out_size)
{
    const float* tokens  = (const float*)d_in[0];
    const float* ts      = (const float*)d_in[1];
    const float* maskp   = (const float*)d_in[2];
    const float* Wq      = (const float*)d_in[3];
    const float* bq      = (const float*)d_in[4];
    const float* Wk      = (const float*)d_in[5];
    const float* bk      = (const float*)d_in[6];
    const float* Wv      = (const float*)d_in[7];
    const float* bv      = (const float*)d_in[8];
    const float* Wo      = (const float*)d_in[9];
    const float* bo      = (const float*)d_in[10];
    const float* readout = (const float*)d_in[11];
    float* out = (float*)d_out;
    (void)n_in;

    const int M  = in_sizes[0] / DMODEL;   // N*L = 32768
    const int Nb = out_size / DMODEL;      // 64
    const int L  = M / Nb;                 // 512

    float* gP;
    __nv_bfloat16 *gth, *gtl, *gwh, *gwl, *gqh, *gql, *gkh, *gkl, *gvh, *gvl;
    cudaGetSymbolAddress((void**)&gP, g_P);
    cudaGetSymbolAddress((void**)&gth, g_th);
    cudaGetSymbolAddress((void**)&gtl, g_tl);
    cudaGetSymbolAddress((void**)&gwh, g_wh);
    cudaGetSymbolAddress((void**)&gwl, g_wl);
    cudaGetSymbolAddress((void**)&gqh, g_qh);
    cudaGetSymbolAddress((void**)&gql, g_ql);
    cudaGetSymbolAddress((void**)&gkh, g_kh);
    cudaGetSymbolAddress((void**)&gkl, g_kl);
    cudaGetSymbolAddress((void**)&gvh, g_vh);
    cudaGetSymbolAddress((void**)&gvl, g_vl);

    // ---- pre-split inputs to bf16 hi/lo ----
    const int tok4 = M * DMODEL / 4;
    split_f32<<<(tok4 + 255) / 256, 256>>>(tokens, gth, gtl, tok4);
    const int w4 = WSZ / 4;
    split_f32<<<(w4 + 255) / 256, 256>>>(Wq, gwh + 0 * WSZ, gwl + 0 * WSZ, w4);
    split_f32<<<(w4 + 255) / 256, 256>>>(Wk, gwh + 1 * WSZ, gwl + 1 * WSZ, w4);
    split_f32<<<(w4 + 255) / 256, 256>>>(Wv, gwh + 2 * WSZ, gwl + 2 * WSZ, w4);
    split_f32<<<(w4 + 255) / 256, 256>>>(Wo, gwh + 3 * WSZ, gwl + 3 * WSZ, w4);

    cudaFuncSetAttribute(gemm_tc, cudaFuncAttributeMaxDynamicSharedMemorySize, G_SMEM);
    cudaFuncSetAttribute(gemm_tc_split, cudaFuncAttributeMaxDynamicSharedMemorySize, G_SMEM);
    dim3 gg(DMODEL / GBN, M / GBM);
    gemm_tc_split<<<gg, 256, G_SMEM>>>(gth, gtl, gwh + 0 * WSZ, gwl + 0 * WSZ, bq,
                                       SCALE, gqh, gql, M, DMODEL, DMODEL);
    gemm_tc_split<<<gg, 256, G_SMEM>>>(gth, gtl, gwh + 1 * WSZ, gwl + 1 * WSZ, bk,
                                       1.0f, gkh, gkl, M, DMODEL, DMODEL);
    gemm_tc_split<<<gg, 256, G_SMEM>>>(gth, gtl, gwh + 2 * WSZ, gwl + 2 * WSZ, bv,
                                       1.0f, gvh, gvl, M, DMODEL, DMODEL);

    cudaFuncSetAttribute(attn_tc, cudaFuncAttributeMaxDynamicSharedMemorySize,
                         A_SMEM_TOTAL);
    dim3 ag(L / 128, NHEAD, Nb);
    // attention writes split bf16 output into the token-split buffers (free now)
    attn_tc<<<ag, 256, A_SMEM_TOTAL>>>(gqh, gql, gkh, gkl, gvh, gvl, ts, maskp,
                                       gth, gtl, L);

    gemm_tc<<<gg, 256, G_SMEM>>>(gth, gtl, gwh + 3 * WSZ, gwl + 3 * WSZ, bo, maskp,
                                 gP, M, DMODEL, DMODEL);

    dim3 pg(NHEAD, Nb);
    pool_kernel<<<pg, 256>>>(gP, readout, maskp, out, L);
}

// round 10
// speedup vs baseline: 1.6848x; 1.0432x over previous
#include <cuda_runtime.h>
#include <cuda_bf16.h>
#include <math.h>
#include <stdint.h>

#define DMODEL 768
#define NHEAD  12
#define DH     64
#define TAU    300.0f
#define INV_TAU (1.0f / 300.0f)
#define NEGV   (-1e9f)
#define SCALE  0.125f   /* 1/sqrt(64) */

#define MAXM (64 * 512)
#define WSZ  (DMODEL * DMODEL)
#define LDQKV (3 * DMODEL)   /* 2304: row stride of combined QKV output */

// fp32 scratch: final projected+masked output (pool input)
__device__ float g_P[MAXM * DMODEL];
// bf16 hi/lo split scratch
__device__ __nv_bfloat16 g_th[MAXM * DMODEL];   // tokens split -> then attn-out split
__device__ __nv_bfloat16 g_tl[MAXM * DMODEL];
__device__ __nv_bfloat16 g_qkvh[MAXM * LDQKV];  // combined QKV projection (hi)
__device__ __nv_bfloat16 g_qkvl[MAXM * LDQKV];  // combined QKV projection (lo)
__device__ __nv_bfloat16 g_wh[4 * WSZ];         // Wq|Wk|Wv (combined) + Wo
__device__ __nv_bfloat16 g_wl[4 * WSZ];
__device__ float g_bias[LDQKV];                 // bq|bk|bv concatenated

// ===========================================================================
// helpers
// ===========================================================================
__device__ __forceinline__ uint32_t smem_u32(const void* p) {
    uint32_t a;
    asm("{ .reg .u64 t; cvta.to.shared.u64 t, %1; cvt.u32.u64 %0, t; }"
        : "=r"(a) : "l"(p));
    return a;
}

__device__ __forceinline__ void ldsm4(uint32_t* r, uint32_t addr) {
    asm volatile("ldmatrix.sync.aligned.m8n8.x4.shared.b16 {%0,%1,%2,%3}, [%4];"
                 : "=r"(r[0]), "=r"(r[1]), "=r"(r[2]), "=r"(r[3]) : "r"(addr));
}
__device__ __forceinline__ void ldsm4t(uint32_t* r, uint32_t addr) {
    asm volatile("ldmatrix.sync.aligned.m8n8.x4.trans.shared.b16 {%0,%1,%2,%3}, [%4];"
                 : "=r"(r[0]), "=r"(r[1]), "=r"(r[2]), "=r"(r[3]) : "r"(addr));
}

__device__ __forceinline__ void mma16816(float* c, const uint32_t* a,
                                         const uint32_t* b) {
    asm volatile(
        "mma.sync.aligned.m16n8k16.row.col.f32.bf16.bf16.f32 "
        "{%0,%1,%2,%3}, {%4,%5,%6,%7}, {%8,%9}, {%0,%1,%2,%3};"
        : "+f"(c[0]), "+f"(c[1]), "+f"(c[2]), "+f"(c[3])
        : "r"(a[0]), "r"(a[1]), "r"(a[2]), "r"(a[3]), "r"(b[0]), "r"(b[1]));
}

__device__ __forceinline__ void cp16(uint32_t dst, const void* src) {
    asm volatile("cp.async.cg.shared.global [%0], [%1], 16;"
                 :: "r"(dst), "l"(src));
}

__device__ __forceinline__ void split4(float4 v, uint2& h, uint2& l) {
    __nv_bfloat16 h0 = __float2bfloat16_rn(v.x);
    __nv_bfloat16 h1 = __float2bfloat16_rn(v.y);
    __nv_bfloat16 h2 = __float2bfloat16_rn(v.z);
    __nv_bfloat16 h3 = __float2bfloat16_rn(v.w);
    __nv_bfloat16 l0 = __float2bfloat16_rn(v.x - __bfloat162float(h0));
    __nv_bfloat16 l1 = __float2bfloat16_rn(v.y - __bfloat162float(h1));
    __nv_bfloat16 l2 = __float2bfloat16_rn(v.z - __bfloat162float(h2));
    __nv_bfloat16 l3 = __float2bfloat16_rn(v.w - __bfloat162float(h3));
    h.x = (uint32_t)__bfloat16_as_ushort(h0) | ((uint32_t)__bfloat16_as_ushort(h1) << 16);
    h.y = (uint32_t)__bfloat16_as_ushort(h2) | ((uint32_t)__bfloat16_as_ushort(h3) << 16);
    l.x = (uint32_t)__bfloat16_as_ushort(l0) | ((uint32_t)__bfloat16_as_ushort(l1) << 16);
    l.y = (uint32_t)__bfloat16_as_ushort(l2) | ((uint32_t)__bfloat16_as_ushort(l3) << 16);
}

__device__ __forceinline__ uint32_t pack_bf16(float a, float b) {
    __nv_bfloat162 t = __floats2bfloat162_rn(a, b);
    return *(uint32_t*)&t;
}
__device__ __forceinline__ void split2(float a, float b, uint32_t& h, uint32_t& l) {
    __nv_bfloat16 ha = __float2bfloat16_rn(a);
    __nv_bfloat16 hb = __float2bfloat16_rn(b);
    float la = a - __bfloat162float(ha);
    float lb = b - __bfloat162float(hb);
    h = (uint32_t)__bfloat16_as_ushort(ha) | ((uint32_t)__bfloat16_as_ushort(hb) << 16);
    l = pack_bf16(la, lb);
}

// ===========================================================================
// elementwise f32 -> bf16 hi/lo splits
// ===========================================================================
__global__ __launch_bounds__(256) void split_f32(
    const float* __restrict__ X, __nv_bfloat16* __restrict__ Xh,
    __nv_bfloat16* __restrict__ Xl, int n4)
{
    int i = blockIdx.x * blockDim.x + threadIdx.x;
    if (i < n4) {
        float4 v = ((const float4*)X)[i];
        uint2 h, l;
        split4(v, h, l);
        ((uint2*)Xh)[i] = h;
        ((uint2*)Xl)[i] = l;
    }
}

// fused 4-weight split: blockIdx.y selects the matrix
__global__ __launch_bounds__(256) void split_w(
    const float* __restrict__ W0, const float* __restrict__ W1,
    const float* __restrict__ W2, const float* __restrict__ W3,
    __nv_bfloat16* __restrict__ Xh, __nv_bfloat16* __restrict__ Xl, int n4)
{
    const int m = blockIdx.y;
    const float* X = (m == 0) ? W0 : (m == 1) ? W1 : (m == 2) ? W2 : W3;
    int i = blockIdx.x * blockDim.x + threadIdx.x;
    if (i < n4) {
        float4 v = ((const float4*)X)[i];
        uint2 h, l;
        split4(v, h, l);
        ((uint2*)(Xh + (size_t)m * WSZ))[i] = h;
        ((uint2*)(Xl + (size_t)m * WSZ))[i] = l;
    }
}

// ===========================================================================
// HMMA GEMM mainloop (cp.async 2-stage, pre-split bf16 inputs). Two kernels
// differing only in epilogue. __launch_bounds__(256, 2): 2 CTAs/SM.
// ===========================================================================
#define GBM 128
#define GBN 128
#define GBK 32
#define G_AH 0
#define G_AL 10240
#define G_BH 20480
#define G_BL 30720
#define G_STAGE 40960
#define G_BIAS  81920
#define G_SMEM  (81920 + 512)

#define GEMM_PROLOG                                                           \
    extern __shared__ char gsm[];                                             \
    const uint32_t sbase = smem_u32(gsm);                                     \
    float* bias_s = (float*)(gsm + G_BIAS);                                   \
    const int t = threadIdx.x;                                                \
    const int wid = t >> 5, lane = t & 31;                                    \
    const int n0 = blockIdx.x * GBN;                                          \
    const int m0 = blockIdx.y * GBM;                                          \
    if (t < GBN) bias_s[t] = bias[n0 + t];                                    \
    const int lr = t >> 1;                                                    \
    const int lcp = (t & 1) * 2;                                              \
    const __nv_bfloat16* srcAh = Ahg + (size_t)(m0 + lr) * K + lcp * 8;       \
    const __nv_bfloat16* srcAl = Alg + (size_t)(m0 + lr) * K + lcp * 8;       \
    const __nv_bfloat16* srcBh = Whg + (size_t)(n0 + lr) * K + lcp * 8;       \
    const __nv_bfloat16* srcBl = Wlg + (size_t)(n0 + lr) * K + lcp * 8;       \
    const uint32_t dst_row = sbase + (uint32_t)lr * 80 + (uint32_t)lcp * 16;  \
    const int NITER = K / GBK;

#define G_ISSUE(bufi, kc)                                                     \
    do {                                                                      \
        uint32_t d = dst_row + (bufi) * G_STAGE;                              \
        cp16(d + G_AH,      srcAh + (kc));                                    \
        cp16(d + G_AH + 16, srcAh + (kc) + 8);                                \
        cp16(d + G_AL,      srcAl + (kc));                                    \
        cp16(d + G_AL + 16, srcAl + (kc) + 8);                                \
        cp16(d + G_BH,      srcBh + (kc));                                    \
        cp16(d + G_BH + 16, srcBh + (kc) + 8);                                \
        cp16(d + G_BL,      srcBl + (kc));                                    \
        cp16(d + G_BL + 16, srcBl + (kc) + 8);                                \
    } while (0)

#define GEMM_MAINLOOP                                                         \
    G_ISSUE(0, 0);                                                            \
    asm volatile("cp.async.commit_group;" ::: "memory");                      \
    const int wm = wid >> 2;                                                  \
    const int wn = wid & 3;                                                   \
    const int a_row = lane & 15;                                              \
    const int a_chk = (lane >> 4) & 1;                                        \
    const int b_n   = (lane & 7) + ((lane >> 4) & 1) * 8;                     \
    const int b_chk = (lane >> 3) & 1;                                        \
    float acc[4][4][4];                                                       \
    _Pragma("unroll")                                                         \
    for (int mi = 0; mi < 4; mi++)                                            \
        _Pragma("unroll")                                                     \
        for (int ni = 0; ni < 4; ni++)                                        \
            _Pragma("unroll")                                                 \
            for (int j = 0; j < 4; j++) acc[mi][ni][j] = 0.0f;                \
    for (int it = 0; it < NITER; it++) {                                      \
        const int buf = it & 1;                                               \
        if (it + 1 < NITER) {                                                 \
            G_ISSUE(buf ^ 1, (it + 1) * GBK);                                 \
            asm volatile("cp.async.commit_group;" ::: "memory");              \
            asm volatile("cp.async.wait_group 1;" ::: "memory");              \
        } else {                                                              \
            asm volatile("cp.async.wait_group 0;" ::: "memory");              \
        }                                                                     \
        __syncthreads();                                                      \
        const uint32_t st = sbase + buf * G_STAGE;                            \
        const uint32_t ah_s = st + G_AH, al_s = st + G_AL;                    \
        const uint32_t bh_s = st + G_BH, bl_s = st + G_BL;                    \
        _Pragma("unroll")                                                     \
        for (int s = 0; s < 2; s++) {                                         \
            uint32_t bhf[8], blf[8];                                          \
            _Pragma("unroll")                                                 \
            for (int nt = 0; nt < 2; nt++) {                                  \
                uint32_t boff = (uint32_t)(wn * 32 + nt * 16 + b_n) * 80      \
                              + s * 32 + b_chk * 16;                          \
                ldsm4(bhf + nt * 4, bh_s + boff);                             \
                ldsm4(blf + nt * 4, bl_s + boff);                             \
            }                                                                 \
            _Pragma("unroll")                                                 \
            for (int mi = 0; mi < 4; mi++) {                                  \
                uint32_t aoff = (uint32_t)(wm * 64 + mi * 16 + a_row) * 80    \
                              + s * 32 + a_chk * 16;                          \
                uint32_t ahf[4], alf[4];                                      \
                ldsm4(ahf, ah_s + aoff);                                      \
                ldsm4(alf, al_s + aoff);                                      \
                _Pragma("unroll")                                             \
                for (int ni = 0; ni < 4; ni++) {                              \
                    mma16816(acc[mi][ni], ahf, bhf + ni * 2);                 \
                    mma16816(acc[mi][ni], ahf, blf + ni * 2);                 \
                    mma16816(acc[mi][ni], alf, bhf + ni * 2);                 \
                }                                                             \
            }                                                                 \
        }                                                                     \
        __syncthreads();                                                      \
    }

// fp32 output with mask (Wo projection)
__global__ __launch_bounds__(256, 2) void gemm_tc(
    const __nv_bfloat16* __restrict__ Ahg, const __nv_bfloat16* __restrict__ Alg,
    const __nv_bfloat16* __restrict__ Whg, const __nv_bfloat16* __restrict__ Wlg,
    const float* __restrict__ bias, const float* __restrict__ maskp,
    float* __restrict__ C, int M, int N, int K)
{
    GEMM_PROLOG
    GEMM_MAINLOOP

    const int r0 = lane >> 2;
    const int c0 = (lane & 3) * 2;
#pragma unroll
    for (int mi = 0; mi < 4; mi++) {
        int mA = m0 + wm * 64 + mi * 16 + r0;
        int mB = mA + 8;
        float mkA = maskp ? maskp[mA] : 1.0f;
        float mkB = maskp ? maskp[mB] : 1.0f;
#pragma unroll
        for (int ni = 0; ni < 4; ni++) {
            int n = wn * 32 + ni * 8 + c0;
            float b0 = bias_s[n], b1 = bias_s[n + 1];
            float2 vA, vB;
            vA.x = (acc[mi][ni][0] + b0) * mkA;
            vA.y = (acc[mi][ni][1] + b1) * mkA;
            vB.x = (acc[mi][ni][2] + b0) * mkB;
            vB.y = (acc[mi][ni][3] + b1) * mkB;
            *(float2*)&C[(size_t)mA * N + n0 + n] = vA;
            *(float2*)&C[(size_t)mB * N + n0 + n] = vB;
        }
    }
}

// bf16 hi/lo split output into combined [M x ldc] matrix; Q columns
// (n0 < qcols) get SCALE folded in.
__global__ __launch_bounds__(256, 2) void gemm_tc_split(
    const __nv_bfloat16* __restrict__ Ahg, const __nv_bfloat16* __restrict__ Alg,
    const __nv_bfloat16* __restrict__ Whg, const __nv_bfloat16* __restrict__ Wlg,
    const float* __restrict__ bias, int qcols, int ldc,
    __nv_bfloat16* __restrict__ Ch, __nv_bfloat16* __restrict__ Cl,
    int M, int K)
{
    GEMM_PROLOG
    GEMM_MAINLOOP

    const float oscale = (n0 < qcols) ? SCALE : 1.0f;
    const int r0 = lane >> 2;
    const int c0 = (lane & 3) * 2;
#pragma unroll
    for (int mi = 0; mi < 4; mi++) {
        int mA = m0 + wm * 64 + mi * 16 + r0;
        int mB = mA + 8;
#pragma unroll
        for (int ni = 0; ni < 4; ni++) {
            int n = wn * 32 + ni * 8 + c0;
            float b0 = bias_s[n], b1 = bias_s[n + 1];
            uint32_t h, l;
            split2((acc[mi][ni][0] + b0) * oscale, (acc[mi][ni][1] + b1) * oscale, h, l);
            *(uint32_t*)&Ch[(size_t)mA * ldc + n0 + n] = h;
            *(uint32_t*)&Cl[(size_t)mA * ldc + n0 + n] = l;
            split2((acc[mi][ni][2] + b0) * oscale, (acc[mi][ni][3] + b1) * oscale, h, l);
            *(uint32_t*)&Ch[(size_t)mB * ldc + n0 + n] = h;
            *(uint32_t*)&Cl[(size_t)mB * ldc + n0 + n] = l;
        }
    }
}

// ===========================================================================
// Tensor-core flash attention on pre-split bf16 Q/K/V (occupancy 2).
// Q/K/V are column slices of the combined [M x LDQKV] projection.
// ===========================================================================
#define APITCH 72          /* bf16 elems per smem row (144 B) */
#define A_QHO 0
#define A_QLO 18432
#define A_BUF0 36864
#define A_KHO 0
#define A_KLO 9216
#define A_VHO 18432
#define A_VLO 27648
#define A_TKO 36864
#define A_MKO 37120
#define A_BUFSZ 37888
#define A_SMEM_TOTAL (A_BUF0 + 2 * A_BUFSZ)   /* 112640 */

__global__ __launch_bounds__(256, 2) void attn_tc(
    const __nv_bfloat16* __restrict__ QKVh, const __nv_bfloat16* __restrict__ QKVl,
    const float* __restrict__ ts, const float* __restrict__ maskp,
    __nv_bfloat16* __restrict__ Oh_g, __nv_bfloat16* __restrict__ Ol_g, int L)
{
    extern __shared__ char smem[];
    const uint32_t sbase = smem_u32(smem);

    const int t = threadIdx.x, w = t >> 5, lane = t & 31;
    const int q0 = blockIdx.x * 128, h = blockIdx.y, n = blockIdx.z;
    // combined-projection base for this (batch, head); K at +DMODEL, V at +2*DMODEL
    const size_t kvbase = (size_t)n * L * LDQKV + (size_t)h * DH;
    const size_t obase  = (size_t)n * L * DMODEL + (size_t)h * DH;
    const int nchunk = L / 64;

    const __nv_bfloat16* Kh_g = QKVh + DMODEL;
    const __nv_bfloat16* Kl_g = QKVl + DMODEL;
    const __nv_bfloat16* Vh_g = QKVh + 2 * DMODEL;
    const __nv_bfloat16* Vl_g = QKVl + 2 * DMODEL;

#define A_ISSUE(bufi, cc)                                                     \
    do {                                                                      \
        const uint32_t bb = sbase + A_BUF0 + (bufi) * A_BUFSZ;                \
        const int kk0 = (cc) * 64;                                            \
        _Pragma("unroll")                                                     \
        for (int idx = t; idx < 512; idx += 256) {                            \
            int row = idx >> 3, ch = idx & 7;                                 \
            size_t g = kvbase + (size_t)(kk0 + row) * LDQKV + ch * 8;         \
            uint32_t doff = (uint32_t)row * 144 + ch * 16;                    \
            cp16(bb + A_KHO + doff, Kh_g + g);                                \
            cp16(bb + A_KLO + doff, Kl_g + g);                                \
            cp16(bb + A_VHO + doff, Vh_g + g);                                \
            cp16(bb + A_VLO + doff, Vl_g + g);                                \
        }                                                                     \
        if (t < 16)                                                           \
            cp16(bb + A_TKO + t * 16, ts + n * L + kk0 + t * 4);              \
        else if (t < 32)                                                      \
            cp16(bb + A_MKO + (t - 16) * 16, maskp + n * L + kk0 + (t - 16) * 4); \
    } while (0)

    // prologue: stream chunk 0 while loading Q
    A_ISSUE(0, 0);
    asm volatile("cp.async.commit_group;" ::: "memory");

    // ---- Q smem load (pre-scaled, pre-split) ----
    {
        __nv_bfloat16* Qh = (__nv_bfloat16*)(smem + A_QHO);
        __nv_bfloat16* Ql = (__nv_bfloat16*)(smem + A_QLO);
#pragma unroll
        for (int idx = t; idx < 1024; idx += 256) {
            int row = idx >> 3, ch = idx & 7;
            size_t g = kvbase + (size_t)(q0 + row) * LDQKV + ch * 8;
            *(uint4*)&Qh[row * APITCH + ch * 8] = *(const uint4*)(QKVh + g);
            *(uint4*)&Ql[row * APITCH + ch * 8] = *(const uint4*)(QKVl + g);
        }
    }
    __syncthreads();

    const int a_row = lane & 15, a_chk = (lane >> 4) & 1;
    const int r0 = lane >> 2, c2 = (lane & 3) * 2;
    const float tq0 = ts[n * L + q0 + w * 16 + r0];
    const float tq1 = ts[n * L + q0 + w * 16 + r0 + 8];

    float o[8][4];
#pragma unroll
    for (int i = 0; i < 8; i++)
#pragma unroll
        for (int j = 0; j < 4; j++) o[i][j] = 0.0f;
    float m0 = -1e30f, m1 = -1e30f, l0 = 0.0f, l1 = 0.0f;

    const int b_n = (lane & 7) + ((lane >> 4) & 1) * 8;
    const int b_chk = (lane >> 3) & 1;
    const int v_row = lane & 15;          // key row within k16
    const int v_col = (lane >> 4) * 8;    // d offset within d16 group

    for (int c = 0; c < nchunk; c++) {
        const int buf = c & 1;
        if (c + 1 < nchunk) {
            A_ISSUE(buf ^ 1, c + 1);
            asm volatile("cp.async.commit_group;" ::: "memory");
            asm volatile("cp.async.wait_group 1;" ::: "memory");
        } else {
            asm volatile("cp.async.wait_group 0;" ::: "memory");
        }
        __syncthreads();

        const uint32_t bb = sbase + A_BUF0 + buf * A_BUFSZ;
        const uint32_t kh_s = bb + A_KHO, kl_s = bb + A_KLO;
        const uint32_t vh_s = bb + A_VHO, vl_s = bb + A_VLO;
        const float* tks = (const float*)(smem + A_BUF0 + buf * A_BUFSZ + A_TKO);
        const float* mks = (const float*)(smem + A_BUF0 + buf * A_BUFSZ + A_MKO);

        // ---- S = Q K^T (3-term split; Q frags re-loaded per k-step) ----
        float S[8][4];
#pragma unroll
        for (int i = 0; i < 8; i++)
#pragma unroll
            for (int j = 0; j < 4; j++) S[i][j] = 0.0f;
#pragma unroll
        for (int ks = 0; ks < 4; ks++) {
            uint32_t qh4[4], ql4[4];
            uint32_t aoff = (uint32_t)(w * 16 + a_row) * 144 + ks * 32 + a_chk * 16;
            ldsm4(qh4, sbase + A_QHO + aoff);
            ldsm4(ql4, sbase + A_QLO + aoff);
#pragma unroll
            for (int g = 0; g < 4; g++) {
                uint32_t boff = (uint32_t)(g * 16 + b_n) * 144 + ks * 32 + b_chk * 16;
                uint32_t bh[4], bl[4];
                ldsm4(bh, kh_s + boff);
                ldsm4(bl, kl_s + boff);
#pragma unroll
                for (int ni = 0; ni < 2; ni++) {
                    mma16816(S[g * 2 + ni], qh4, bh + ni * 2);
                    mma16816(S[g * 2 + ni], qh4, bl + ni * 2);
                    mma16816(S[g * 2 + ni], ql4, bh + ni * 2);
                }
            }
        }

        // ---- bias + mask + online softmax ----
        float cm0 = -1e30f, cm1 = -1e30f;
#pragma unroll
        for (int nt = 0; nt < 8; nt++) {
#pragma unroll
            for (int j = 0; j < 2; j++) {
                int key = nt * 8 + c2 + j;
                float tk = tks[key];
                bool ok = mks[key] > 0.0f;
                float bA = -fabsf(tq0 - tk) * INV_TAU;
                float bB = -fabsf(tq1 - tk) * INV_TAU;
                S[nt][j]     = ok ? S[nt][j]     + bA : NEGV;
                S[nt][j + 2] = ok ? S[nt][j + 2] + bB : NEGV;
                cm0 = fmaxf(cm0, S[nt][j]);
                cm1 = fmaxf(cm1, S[nt][j + 2]);
            }
        }
#pragma unroll
        for (int off = 1; off <= 2; off <<= 1) {
            cm0 = fmaxf(cm0, __shfl_xor_sync(0xffffffffu, cm0, off));
            cm1 = fmaxf(cm1, __shfl_xor_sync(0xffffffffu, cm1, off));
        }
        float nm0 = fmaxf(m0, cm0), nm1 = fmaxf(m1, cm1);
        float cr0 = __expf(m0 - nm0), cr1 = __expf(m1 - nm1);
        m0 = nm0; m1 = nm1;

        float ps0 = 0.0f, ps1 = 0.0f;
#pragma unroll
        for (int nt = 0; nt < 8; nt++) {
            float p00 = __expf(S[nt][0] - nm0);
            float p01 = __expf(S[nt][1] - nm0);
            float p10 = __expf(S[nt][2] - nm1);
            float p11 = __expf(S[nt][3] - nm1);
            ps0 += p00 + p01; ps1 += p10 + p11;
            S[nt][0] = p00; S[nt][1] = p01; S[nt][2] = p10; S[nt][3] = p11;
        }
#pragma unroll
        for (int off = 1; off <= 2; off <<= 1) {
            ps0 += __shfl_xor_sync(0xffffffffu, ps0, off);
            ps1 += __shfl_xor_sync(0xffffffffu, ps1, off);
        }
        l0 = l0 * cr0 + ps0;
        l1 = l1 * cr1 + ps1;

#pragma unroll
        for (int i = 0; i < 8; i++) {
            o[i][0] *= cr0; o[i][1] *= cr0;
            o[i][2] *= cr1; o[i][3] *= cr1;
        }

        // ---- O += P V : V frags via ldmatrix.trans on [key][d] ----
#pragma unroll
        for (int kt = 0; kt < 4; kt++) {
            uint32_t pah[4], pal[4];
            split2(S[2 * kt][0],     S[2 * kt][1],     pah[0], pal[0]);
            split2(S[2 * kt][2],     S[2 * kt][3],     pah[1], pal[1]);
            split2(S[2 * kt + 1][0], S[2 * kt + 1][1], pah[2], pal[2]);
            split2(S[2 * kt + 1][2], S[2 * kt + 1][3], pah[3], pal[3]);
#pragma unroll
            for (int g = 0; g < 4; g++) {
                uint32_t voff = (uint32_t)(kt * 16 + v_row) * 144
                              + (uint32_t)(g * 16 + v_col) * 2;
                uint32_t bh[4], bl[4];
                ldsm4t(bh, vh_s + voff);
                ldsm4t(bl, vl_s + voff);
#pragma unroll
                for (int ni = 0; ni < 2; ni++) {
                    mma16816(o[g * 2 + ni], pah, bh + ni * 2);
                    mma16816(o[g * 2 + ni], pal, bh + ni * 2);
                    mma16816(o[g * 2 + ni], pah, bl + ni * 2);
                }
            }
        }
        __syncthreads();
    }

    // ---- normalize + split-store ----
    const float inv0 = 1.0f / l0, inv1 = 1.0f / l1;
    const int gr0 = q0 + w * 16 + r0, gr1 = gr0 + 8;
#pragma unroll
    for (int ntd = 0; ntd < 8; ntd++) {
        int d = ntd * 8 + c2;
        uint32_t hh, ll;
        split2(o[ntd][0] * inv0, o[ntd][1] * inv0, hh, ll);
        *(uint32_t*)&Oh_g[obase + (size_t)gr0 * DMODEL + d] = hh;
        *(uint32_t*)&Ol_g[obase + (size_t)gr0 * DMODEL + d] = ll;
        split2(o[ntd][2] * inv1, o[ntd][3] * inv1, hh, ll);
        *(uint32_t*)&Oh_g[obase + (size_t)gr1 * DMODEL + d] = hh;
        *(uint32_t*)&Ol_g[obase + (size_t)gr1 * DMODEL + d] = ll;
    }
}

// ---------------------------------------------------------------------------
// Readout pooling: one block per (head, batch). X = masked projected output.
// ---------------------------------------------------------------------------
__global__ __launch_bounds__(256) void pool_kernel(
    const float* __restrict__ X, const float* __restrict__ readout,
    const float* __restrict__ maskp, float* __restrict__ out, int L)
{
    __shared__ float s[512];
    __shared__ float qsh[64];
    __shared__ float red[8];
    __shared__ float part[8][64];
    const int h = blockIdx.x, n = blockIdx.y;
    const int t = threadIdx.x, w = t >> 5, lane = t & 31;
    if (t < 64) qsh[t] = readout[h * DH + t] * SCALE;
    __syncthreads();
    const size_t base = (size_t)n * L * DMODEL + (size_t)h * DH;

    for (int k = w; k < L; k += 8) {
        float d = X[base + (size_t)k * DMODEL + lane] * qsh[lane]
                + X[base + (size_t)k * DMODEL + lane + 32] * qsh[lane + 32];
#pragma unroll
        for (int o = 16; o > 0; o >>= 1) d += __shfl_xor_sync(0xffffffffu, d, o);
        if (lane == 0) s[k] = (maskp[n * L + k] > 0.f) ? d : NEGV;
    }
    __syncthreads();

    float lm = -1e30f;
    for (int k = t; k < L; k += 256) lm = fmaxf(lm, s[k]);
#pragma unroll
    for (int o = 16; o > 0; o >>= 1) lm = fmaxf(lm, __shfl_xor_sync(0xffffffffu, lm, o));
    if (lane == 0) red[w] = lm;
    __syncthreads();
    float gm = red[0];
#pragma unroll
    for (int i = 1; i < 8; i++) gm = fmaxf(gm, red[i]);
    __syncthreads();
    float ls = 0.f;
    for (int k = t; k < L; k += 256) { float p = expf(s[k] - gm); s[k] = p; ls += p; }
#pragma unroll
    for (int o = 16; o > 0; o >>= 1) ls += __shfl_xor_sync(0xffffffffu, ls, o);
    if (lane == 0) red[w] = ls;
    __syncthreads();
    float gs = 0.f;
#pragma unroll
    for (int i = 0; i < 8; i++) gs += red[i];
    float inv = 1.0f / gs;

    const int kb = w * (L / 8), ke = kb + (L / 8);
    float a0 = 0.f, a1 = 0.f;
    for (int k = kb; k < ke; k++) {
        float p = s[k];
        a0 = fmaf(p, X[base + (size_t)k * DMODEL + lane], a0);
        a1 = fmaf(p, X[base + (size_t)k * DMODEL + lane + 32], a1);
    }
    part[w][lane]      = a0;
    part[w][lane + 32] = a1;
    __syncthreads();
    if (t < 64) {
        float sum = 0.f;
#pragma unroll
        for (int i = 0; i < 8; i++) sum += part[i][t];
        out[(size_t)n * DMODEL + h * DH + t] = sum * inv;
    }
}

// ---------------------------------------------------------------------------
extern "C" void kernel_launch(void* const* d_in, const int* in_sizes, int n_in,
                              void* d_out, int out_size)
{
    const float* tokens  = (const float*)d_in[0];
    const float* ts      = (const float*)d_in[1];
    const float* maskp   = (const float*)d_in[2];
    const float* Wq      = (const float*)d_in[3];
    const float* bq      = (const float*)d_in[4];
    const float* Wk      = (const float*)d_in[5];
    const float* bk      = (const float*)d_in[6];
    const float* Wv      = (const float*)d_in[7];
    const float* bv      = (const float*)d_in[8];
    const float* Wo      = (const float*)d_in[9];
    const float* bo      = (const float*)d_in[10];
    const float* readout = (const float*)d_in[11];
    float* out = (float*)d_out;
    (void)n_in;

    const int M  = in_sizes[0] / DMODEL;   // N*L = 32768
    const int Nb = out_size / DMODEL;      // 64
    const int L  = M / Nb;                 // 512

    float *gP, *gbias;
    __nv_bfloat16 *gth, *gtl, *gwh, *gwl, *gqkvh, *gqkvl;
    cudaGetSymbolAddress((void**)&gP, g_P);
    cudaGetSymbolAddress((void**)&gth, g_th);
    cudaGetSymbolAddress((void**)&gtl, g_tl);
    cudaGetSymbolAddress((void**)&gwh, g_wh);
    cudaGetSymbolAddress((void**)&gwl, g_wl);
    cudaGetSymbolAddress((void**)&gqkvh, g_qkvh);
    cudaGetSymbolAddress((void**)&gqkvl, g_qkvl);
    cudaGetSymbolAddress((void**)&gbias, g_bias);

    // ---- concat QKV biases (async D2D, graph-capturable) ----
    cudaMemcpyAsync(gbias,              bq, DMODEL * sizeof(float), cudaMemcpyDeviceToDevice);
    cudaMemcpyAsync(gbias + DMODEL,     bk, DMODEL * sizeof(float), cudaMemcpyDeviceToDevice);
    cudaMemcpyAsync(gbias + 2 * DMODEL, bv, DMODEL * sizeof(float), cudaMemcpyDeviceToDevice);

    // ---- pre-split inputs to bf16 hi/lo ----
    const int tok4 = M * DMODEL / 4;
    split_f32<<<(tok4 + 255) / 256, 256>>>(tokens, gth, gtl, tok4);
    const int w4 = WSZ / 4;
    dim3 wg((w4 + 255) / 256, 4);
    split_w<<<wg, 256>>>(Wq, Wk, Wv, Wo, gwh, gwl, w4);

    cudaFuncSetAttribute(gemm_tc, cudaFuncAttributeMaxDynamicSharedMemorySize, G_SMEM);
    cudaFuncSetAttribute(gemm_tc_split, cudaFuncAttributeMaxDynamicSharedMemorySize, G_SMEM);

    // ---- fused QKV projection: one GEMM, N = 2304 ----
    dim3 gqkv(LDQKV / GBN, M / GBM);   // 18 x 256
    gemm_tc_split<<<gqkv, 256, G_SMEM>>>(gth, gtl, gwh, gwl, gbias,
                                         DMODEL, LDQKV, gqkvh, gqkvl, M, DMODEL);

    cudaFuncSetAttribute(attn_tc, cudaFuncAttributeMaxDynamicSharedMemorySize,
                         A_SMEM_TOTAL);
    dim3 ag(L / 128, NHEAD, Nb);
    // attention writes split bf16 output into the token-split buffers (free now)
    attn_tc<<<ag, 256, A_SMEM_TOTAL>>>(gqkvh, gqkvl, ts, maskp, gth, gtl, L);

    dim3 gg(DMODEL / GBN, M / GBM);
    gemm_tc<<<gg, 256, G_SMEM>>>(gth, gtl, gwh + 3 * WSZ, gwl + 3 * WSZ, bo, maskp,
                                 gP, M, DMODEL, DMODEL);

    dim3 pg(NHEAD, Nb);
    pool_kernel<<<pg, 256>>>(gP, readout, maskp, out, L);
}

// round 11
// speedup vs baseline: 1.7519x; 1.0399x over previous
#include <cuda_runtime.h>
#include <cuda_bf16.h>
#include <math.h>
#include <stdint.h>

#define DMODEL 768
#define NHEAD  12
#define DH     64
#define TAU    300.0f
#define INV_TAU (1.0f / 300.0f)
#define NEGV   (-1e9f)
#define SCALE  0.125f   /* 1/sqrt(64) */

#define MAXM (64 * 512)
#define WSZ  (DMODEL * DMODEL)
#define LDQKV (3 * DMODEL)   /* 2304 */
#define NBATCH 64

// fp32 attention output X (pool/proj input)
__device__ float g_X[MAXM * DMODEL];
// bf16 hi/lo split scratch
__device__ __nv_bfloat16 g_th[MAXM * DMODEL];   // tokens split
__device__ __nv_bfloat16 g_tl[MAXM * DMODEL];
__device__ __nv_bfloat16 g_qkvh[MAXM * LDQKV];
__device__ __nv_bfloat16 g_qkvl[MAXM * LDQKV];
__device__ __nv_bfloat16 g_wh[3 * WSZ];         // Wq|Wk|Wv combined
__device__ __nv_bfloat16 g_wl[3 * WSZ];
__device__ float g_bias[LDQKV];                 // bq|bk|bv
// pooling path scratch (all fp32)
__device__ float g_wt[NHEAD * DMODEL];          // w~ = SCALE * R_h . Wo
__device__ float g_c[NHEAD];
__device__ float g_S[MAXM * NHEAD];             // pool scores
__device__ float g_Y[NBATCH * NHEAD * DMODEL];  // P-weighted sums
__device__ float g_sw[NBATCH * NHEAD];          // sum of P*mask

// ===========================================================================
// helpers
// ===========================================================================
__device__ __forceinline__ uint32_t smem_u32(const void* p) {
    uint32_t a;
    asm("{ .reg .u64 t; cvta.to.shared.u64 t, %1; cvt.u32.u64 %0, t; }"
        : "=r"(a) : "l"(p));
    return a;
}

__device__ __forceinline__ void ldsm4(uint32_t* r, uint32_t addr) {
    asm volatile("ldmatrix.sync.aligned.m8n8.x4.shared.b16 {%0,%1,%2,%3}, [%4];"
                 : "=r"(r[0]), "=r"(r[1]), "=r"(r[2]), "=r"(r[3]) : "r"(addr));
}
__device__ __forceinline__ void ldsm4t(uint32_t* r, uint32_t addr) {
    asm volatile("ldmatrix.sync.aligned.m8n8.x4.trans.shared.b16 {%0,%1,%2,%3}, [%4];"
                 : "=r"(r[0]), "=r"(r[1]), "=r"(r[2]), "=r"(r[3]) : "r"(addr));
}

__device__ __forceinline__ void mma16816(float* c, const uint32_t* a,
                                         const uint32_t* b) {
    asm volatile(
        "mma.sync.aligned.m16n8k16.row.col.f32.bf16.bf16.f32 "
        "{%0,%1,%2,%3}, {%4,%5,%6,%7}, {%8,%9}, {%0,%1,%2,%3};"
        : "+f"(c[0]), "+f"(c[1]), "+f"(c[2]), "+f"(c[3])
        : "r"(a[0]), "r"(a[1]), "r"(a[2]), "r"(a[3]), "r"(b[0]), "r"(b[1]));
}

__device__ __forceinline__ void cp16(uint32_t dst, const void* src) {
    asm volatile("cp.async.cg.shared.global [%0], [%1], 16;"
                 :: "r"(dst), "l"(src));
}

__device__ __forceinline__ void split4(float4 v, uint2& h, uint2& l) {
    __nv_bfloat16 h0 = __float2bfloat16_rn(v.x);
    __nv_bfloat16 h1 = __float2bfloat16_rn(v.y);
    __nv_bfloat16 h2 = __float2bfloat16_rn(v.z);
    __nv_bfloat16 h3 = __float2bfloat16_rn(v.w);
    __nv_bfloat16 l0 = __float2bfloat16_rn(v.x - __bfloat162float(h0));
    __nv_bfloat16 l1 = __float2bfloat16_rn(v.y - __bfloat162float(h1));
    __nv_bfloat16 l2 = __float2bfloat16_rn(v.z - __bfloat162float(h2));
    __nv_bfloat16 l3 = __float2bfloat16_rn(v.w - __bfloat162float(h3));
    h.x = (uint32_t)__bfloat16_as_ushort(h0) | ((uint32_t)__bfloat16_as_ushort(h1) << 16);
    h.y = (uint32_t)__bfloat16_as_ushort(h2) | ((uint32_t)__bfloat16_as_ushort(h3) << 16);
    l.x = (uint32_t)__bfloat16_as_ushort(l0) | ((uint32_t)__bfloat16_as_ushort(l1) << 16);
    l.y = (uint32_t)__bfloat16_as_ushort(l2) | ((uint32_t)__bfloat16_as_ushort(l3) << 16);
}

__device__ __forceinline__ uint32_t pack_bf16(float a, float b) {
    __nv_bfloat162 t = __floats2bfloat162_rn(a, b);
    return *(uint32_t*)&t;
}
__device__ __forceinline__ void split2(float a, float b, uint32_t& h, uint32_t& l) {
    __nv_bfloat16 ha = __float2bfloat16_rn(a);
    __nv_bfloat16 hb = __float2bfloat16_rn(b);
    float la = a - __bfloat162float(ha);
    float lb = b - __bfloat162float(hb);
    h = (uint32_t)__bfloat16_as_ushort(ha) | ((uint32_t)__bfloat16_as_ushort(hb) << 16);
    l = pack_bf16(la, lb);
}

// ===========================================================================
// elementwise f32 -> bf16 hi/lo splits
// ===========================================================================
__global__ __launch_bounds__(256) void split_f32(
    const float* __restrict__ X, __nv_bfloat16* __restrict__ Xh,
    __nv_bfloat16* __restrict__ Xl, int n4)
{
    int i = blockIdx.x * blockDim.x + threadIdx.x;
    if (i < n4) {
        float4 v = ((const float4*)X)[i];
        uint2 h, l;
        split4(v, h, l);
        ((uint2*)Xh)[i] = h;
        ((uint2*)Xl)[i] = l;
    }
}

// fused 3-weight split (Wq|Wk|Wv): blockIdx.y selects the matrix
__global__ __launch_bounds__(256) void split_w(
    const float* __restrict__ W0, const float* __restrict__ W1,
    const float* __restrict__ W2,
    __nv_bfloat16* __restrict__ Xh, __nv_bfloat16* __restrict__ Xl, int n4)
{
    const int m = blockIdx.y;
    const float* X = (m == 0) ? W0 : (m == 1) ? W1 : W2;
    int i = blockIdx.x * blockDim.x + threadIdx.x;
    if (i < n4) {
        float4 v = ((const float4*)X)[i];
        uint2 h, l;
        split4(v, h, l);
        ((uint2*)(Xh + (size_t)m * WSZ))[i] = h;
        ((uint2*)(Xl + (size_t)m * WSZ))[i] = l;
    }
}

// ===========================================================================
// HMMA GEMM (cp.async 2-stage, pre-split bf16 inputs), occupancy 2.
// Single variant: bf16 split output into combined [M x ldc]; Q cols scaled.
// ===========================================================================
#define GBM 128
#define GBN 128
#define GBK 32
#define G_AH 0
#define G_AL 10240
#define G_BH 20480
#define G_BL 30720
#define G_STAGE 40960
#define G_BIAS  81920
#define G_SMEM  (81920 + 512)

__global__ __launch_bounds__(256, 2) void gemm_tc_split(
    const __nv_bfloat16* __restrict__ Ahg, const __nv_bfloat16* __restrict__ Alg,
    const __nv_bfloat16* __restrict__ Whg, const __nv_bfloat16* __restrict__ Wlg,
    const float* __restrict__ bias, int qcols, int ldc,
    __nv_bfloat16* __restrict__ Ch, __nv_bfloat16* __restrict__ Cl,
    int M, int K)
{
    extern __shared__ char gsm[];
    const uint32_t sbase = smem_u32(gsm);
    float* bias_s = (float*)(gsm + G_BIAS);
    const int t = threadIdx.x;
    const int wid = t >> 5, lane = t & 31;
    const int n0 = blockIdx.x * GBN;
    const int m0 = blockIdx.y * GBM;
    if (t < GBN) bias_s[t] = bias[n0 + t];
    const int lr = t >> 1;
    const int lcp = (t & 1) * 2;
    const __nv_bfloat16* srcAh = Ahg + (size_t)(m0 + lr) * K + lcp * 8;
    const __nv_bfloat16* srcAl = Alg + (size_t)(m0 + lr) * K + lcp * 8;
    const __nv_bfloat16* srcBh = Whg + (size_t)(n0 + lr) * K + lcp * 8;
    const __nv_bfloat16* srcBl = Wlg + (size_t)(n0 + lr) * K + lcp * 8;
    const uint32_t dst_row = sbase + (uint32_t)lr * 80 + (uint32_t)lcp * 16;
    const int NITER = K / GBK;

#define G_ISSUE(bufi, kc)                                                     \
    do {                                                                      \
        uint32_t d = dst_row + (bufi) * G_STAGE;                              \
        cp16(d + G_AH,      srcAh + (kc));                                    \
        cp16(d + G_AH + 16, srcAh + (kc) + 8);                                \
        cp16(d + G_AL,      srcAl + (kc));                                    \
        cp16(d + G_AL + 16, srcAl + (kc) + 8);                                \
        cp16(d + G_BH,      srcBh + (kc));                                    \
        cp16(d + G_BH + 16, srcBh + (kc) + 8);                                \
        cp16(d + G_BL,      srcBl + (kc));                                    \
        cp16(d + G_BL + 16, srcBl + (kc) + 8);                                \
    } while (0)

    G_ISSUE(0, 0);
    asm volatile("cp.async.commit_group;" ::: "memory");
    const int wm = wid >> 2;
    const int wn = wid & 3;
    const int a_row = lane & 15;
    const int a_chk = (lane >> 4) & 1;
    const int b_n   = (lane & 7) + ((lane >> 4) & 1) * 8;
    const int b_chk = (lane >> 3) & 1;
    float acc[4][4][4];
#pragma unroll
    for (int mi = 0; mi < 4; mi++)
#pragma unroll
        for (int ni = 0; ni < 4; ni++)
#pragma unroll
            for (int j = 0; j < 4; j++) acc[mi][ni][j] = 0.0f;

    for (int it = 0; it < NITER; it++) {
        const int buf = it & 1;
        if (it + 1 < NITER) {
            G_ISSUE(buf ^ 1, (it + 1) * GBK);
            asm volatile("cp.async.commit_group;" ::: "memory");
            asm volatile("cp.async.wait_group 1;" ::: "memory");
        } else {
            asm volatile("cp.async.wait_group 0;" ::: "memory");
        }
        __syncthreads();
        const uint32_t st = sbase + buf * G_STAGE;
        const uint32_t ah_s = st + G_AH, al_s = st + G_AL;
        const uint32_t bh_s = st + G_BH, bl_s = st + G_BL;
#pragma unroll
        for (int s = 0; s < 2; s++) {
            uint32_t bhf[8], blf[8];
#pragma unroll
            for (int nt = 0; nt < 2; nt++) {
                uint32_t boff = (uint32_t)(wn * 32 + nt * 16 + b_n) * 80
                              + s * 32 + b_chk * 16;
                ldsm4(bhf + nt * 4, bh_s + boff);
                ldsm4(blf + nt * 4, bl_s + boff);
            }
#pragma unroll
            for (int mi = 0; mi < 4; mi++) {
                uint32_t aoff = (uint32_t)(wm * 64 + mi * 16 + a_row) * 80
                              + s * 32 + a_chk * 16;
                uint32_t ahf[4], alf[4];
                ldsm4(ahf, ah_s + aoff);
                ldsm4(alf, al_s + aoff);
#pragma unroll
                for (int ni = 0; ni < 4; ni++) {
                    mma16816(acc[mi][ni], ahf, bhf + ni * 2);
                    mma16816(acc[mi][ni], ahf, blf + ni * 2);
                    mma16816(acc[mi][ni], alf, bhf + ni * 2);
                }
            }
        }
        __syncthreads();
    }

    const float oscale = (n0 < qcols) ? SCALE : 1.0f;
    const int r0 = lane >> 2;
    const int c0 = (lane & 3) * 2;
#pragma unroll
    for (int mi = 0; mi < 4; mi++) {
        int mA = m0 + wm * 64 + mi * 16 + r0;
        int mB = mA + 8;
#pragma unroll
        for (int ni = 0; ni < 4; ni++) {
            int n = wn * 32 + ni * 8 + c0;
            float b0 = bias_s[n], b1 = bias_s[n + 1];
            uint32_t h, l;
            split2((acc[mi][ni][0] + b0) * oscale, (acc[mi][ni][1] + b1) * oscale, h, l);
            *(uint32_t*)&Ch[(size_t)mA * ldc + n0 + n] = h;
            *(uint32_t*)&Cl[(size_t)mA * ldc + n0 + n] = l;
            split2((acc[mi][ni][2] + b0) * oscale, (acc[mi][ni][3] + b1) * oscale, h, l);
            *(uint32_t*)&Ch[(size_t)mB * ldc + n0 + n] = h;
            *(uint32_t*)&Cl[(size_t)mB * ldc + n0 + n] = l;
        }
    }
}

// ===========================================================================
// Tensor-core flash attention (occupancy 2); writes fp32 X output.
// ===========================================================================
#define APITCH 72
#define A_QHO 0
#define A_QLO 18432
#define A_BUF0 36864
#define A_KHO 0
#define A_KLO 9216
#define A_VHO 18432
#define A_VLO 27648
#define A_TKO 36864
#define A_MKO 37120
#define A_BUFSZ 37888
#define A_SMEM_TOTAL (A_BUF0 + 2 * A_BUFSZ)   /* 112640 */

__global__ __launch_bounds__(256, 2) void attn_tc(
    const __nv_bfloat16* __restrict__ QKVh, const __nv_bfloat16* __restrict__ QKVl,
    const float* __restrict__ ts, const float* __restrict__ maskp,
    float* __restrict__ Xout, int L)
{
    extern __shared__ char smem[];
    const uint32_t sbase = smem_u32(smem);

    const int t = threadIdx.x, w = t >> 5, lane = t & 31;
    const int q0 = blockIdx.x * 128, h = blockIdx.y, n = blockIdx.z;
    const size_t kvbase = (size_t)n * L * LDQKV + (size_t)h * DH;
    const size_t obase  = (size_t)n * L * DMODEL + (size_t)h * DH;
    const int nchunk = L / 64;

    const __nv_bfloat16* Kh_g = QKVh + DMODEL;
    const __nv_bfloat16* Kl_g = QKVl + DMODEL;
    const __nv_bfloat16* Vh_g = QKVh + 2 * DMODEL;
    const __nv_bfloat16* Vl_g = QKVl + 2 * DMODEL;

#define A_ISSUE(bufi, cc)                                                     \
    do {                                                                      \
        const uint32_t bb = sbase + A_BUF0 + (bufi) * A_BUFSZ;                \
        const int kk0 = (cc) * 64;                                            \
        _Pragma("unroll")                                                     \
        for (int idx = t; idx < 512; idx += 256) {                            \
            int row = idx >> 3, ch = idx & 7;                                 \
            size_t g = kvbase + (size_t)(kk0 + row) * LDQKV + ch * 8;         \
            uint32_t doff = (uint32_t)row * 144 + ch * 16;                    \
            cp16(bb + A_KHO + doff, Kh_g + g);                                \
            cp16(bb + A_KLO + doff, Kl_g + g);                                \
            cp16(bb + A_VHO + doff, Vh_g + g);                                \
            cp16(bb + A_VLO + doff, Vl_g + g);                                \
        }                                                                     \
        if (t < 16)                                                           \
            cp16(bb + A_TKO + t * 16, ts + n * L + kk0 + t * 4);              \
        else if (t < 32)                                                      \
            cp16(bb + A_MKO + (t - 16) * 16, maskp + n * L + kk0 + (t - 16) * 4); \
    } while (0)

    A_ISSUE(0, 0);
    asm volatile("cp.async.commit_group;" ::: "memory");

    {
        __nv_bfloat16* Qh = (__nv_bfloat16*)(smem + A_QHO);
        __nv_bfloat16* Ql = (__nv_bfloat16*)(smem + A_QLO);
#pragma unroll
        for (int idx = t; idx < 1024; idx += 256) {
            int row = idx >> 3, ch = idx & 7;
            size_t g = kvbase + (size_t)(q0 + row) * LDQKV + ch * 8;
            *(uint4*)&Qh[row * APITCH + ch * 8] = *(const uint4*)(QKVh + g);
            *(uint4*)&Ql[row * APITCH + ch * 8] = *(const uint4*)(QKVl + g);
        }
    }
    __syncthreads();

    const int a_row = lane & 15, a_chk = (lane >> 4) & 1;
    const int r0 = lane >> 2, c2 = (lane & 3) * 2;
    const float tq0 = ts[n * L + q0 + w * 16 + r0];
    const float tq1 = ts[n * L + q0 + w * 16 + r0 + 8];

    float o[8][4];
#pragma unroll
    for (int i = 0; i < 8; i++)
#pragma unroll
        for (int j = 0; j < 4; j++) o[i][j] = 0.0f;
    float m0 = -1e30f, m1 = -1e30f, l0 = 0.0f, l1 = 0.0f;

    const int b_n = (lane & 7) + ((lane >> 4) & 1) * 8;
    const int b_chk = (lane >> 3) & 1;
    const int v_row = lane & 15;
    const int v_col = (lane >> 4) * 8;

    for (int c = 0; c < nchunk; c++) {
        const int buf = c & 1;
        if (c + 1 < nchunk) {
            A_ISSUE(buf ^ 1, c + 1);
            asm volatile("cp.async.commit_group;" ::: "memory");
            asm volatile("cp.async.wait_group 1;" ::: "memory");
        } else {
            asm volatile("cp.async.wait_group 0;" ::: "memory");
        }
        __syncthreads();

        const uint32_t bb = sbase + A_BUF0 + buf * A_BUFSZ;
        const uint32_t kh_s = bb + A_KHO, kl_s = bb + A_KLO;
        const uint32_t vh_s = bb + A_VHO, vl_s = bb + A_VLO;
        const float* tks = (const float*)(smem + A_BUF0 + buf * A_BUFSZ + A_TKO);
        const float* mks = (const float*)(smem + A_BUF0 + buf * A_BUFSZ + A_MKO);

        float S[8][4];
#pragma unroll
        for (int i = 0; i < 8; i++)
#pragma unroll
            for (int j = 0; j < 4; j++) S[i][j] = 0.0f;
#pragma unroll
        for (int ks = 0; ks < 4; ks++) {
            uint32_t qh4[4], ql4[4];
            uint32_t aoff = (uint32_t)(w * 16 + a_row) * 144 + ks * 32 + a_chk * 16;
            ldsm4(qh4, sbase + A_QHO + aoff);
            ldsm4(ql4, sbase + A_QLO + aoff);
#pragma unroll
            for (int g = 0; g < 4; g++) {
                uint32_t boff = (uint32_t)(g * 16 + b_n) * 144 + ks * 32 + b_chk * 16;
                uint32_t bh[4], bl[4];
                ldsm4(bh, kh_s + boff);
                ldsm4(bl, kl_s + boff);
#pragma unroll
                for (int ni = 0; ni < 2; ni++) {
                    mma16816(S[g * 2 + ni], qh4, bh + ni * 2);
                    mma16816(S[g * 2 + ni], qh4, bl + ni * 2);
                    mma16816(S[g * 2 + ni], ql4, bh + ni * 2);
                }
            }
        }

        float cm0 = -1e30f, cm1 = -1e30f;
#pragma unroll
        for (int nt = 0; nt < 8; nt++) {
#pragma unroll
            for (int j = 0; j < 2; j++) {
                int key = nt * 8 + c2 + j;
                float tk = tks[key];
                bool ok = mks[key] > 0.0f;
                float bA = -fabsf(tq0 - tk) * INV_TAU;
                float bB = -fabsf(tq1 - tk) * INV_TAU;
                S[nt][j]     = ok ? S[nt][j]     + bA : NEGV;
                S[nt][j + 2] = ok ? S[nt][j + 2] + bB : NEGV;
                cm0 = fmaxf(cm0, S[nt][j]);
                cm1 = fmaxf(cm1, S[nt][j + 2]);
            }
        }
#pragma unroll
        for (int off = 1; off <= 2; off <<= 1) {
            cm0 = fmaxf(cm0, __shfl_xor_sync(0xffffffffu, cm0, off));
            cm1 = fmaxf(cm1, __shfl_xor_sync(0xffffffffu, cm1, off));
        }
        float nm0 = fmaxf(m0, cm0), nm1 = fmaxf(m1, cm1);
        float cr0 = __expf(m0 - nm0), cr1 = __expf(m1 - nm1);
        m0 = nm0; m1 = nm1;

        float ps0 = 0.0f, ps1 = 0.0f;
#pragma unroll
        for (int nt = 0; nt < 8; nt++) {
            float p00 = __expf(S[nt][0] - nm0);
            float p01 = __expf(S[nt][1] - nm0);
            float p10 = __expf(S[nt][2] - nm1);
            float p11 = __expf(S[nt][3] - nm1);
            ps0 += p00 + p01; ps1 += p10 + p11;
            S[nt][0] = p00; S[nt][1] = p01; S[nt][2] = p10; S[nt][3] = p11;
        }
#pragma unroll
        for (int off = 1; off <= 2; off <<= 1) {
            ps0 += __shfl_xor_sync(0xffffffffu, ps0, off);
            ps1 += __shfl_xor_sync(0xffffffffu, ps1, off);
        }
        l0 = l0 * cr0 + ps0;
        l1 = l1 * cr1 + ps1;

#pragma unroll
        for (int i = 0; i < 8; i++) {
            o[i][0] *= cr0; o[i][1] *= cr0;
            o[i][2] *= cr1; o[i][3] *= cr1;
        }

#pragma unroll
        for (int kt = 0; kt < 4; kt++) {
            uint32_t pah[4], pal[4];
            split2(S[2 * kt][0],     S[2 * kt][1],     pah[0], pal[0]);
            split2(S[2 * kt][2],     S[2 * kt][3],     pah[1], pal[1]);
            split2(S[2 * kt + 1][0], S[2 * kt + 1][1], pah[2], pal[2]);
            split2(S[2 * kt + 1][2], S[2 * kt + 1][3], pah[3], pal[3]);
#pragma unroll
            for (int g = 0; g < 4; g++) {
                uint32_t voff = (uint32_t)(kt * 16 + v_row) * 144
                              + (uint32_t)(g * 16 + v_col) * 2;
                uint32_t bh[4], bl[4];
                ldsm4t(bh, vh_s + voff);
                ldsm4t(bl, vl_s + voff);
#pragma unroll
                for (int ni = 0; ni < 2; ni++) {
                    mma16816(o[g * 2 + ni], pah, bh + ni * 2);
                    mma16816(o[g * 2 + ni], pal, bh + ni * 2);
                    mma16816(o[g * 2 + ni], pah, bl + ni * 2);
                }
            }
        }
        __syncthreads();
    }

    // ---- normalize + fp32 store ----
    const float inv0 = 1.0f / l0, inv1 = 1.0f / l1;
    const int gr0 = q0 + w * 16 + r0, gr1 = gr0 + 8;
#pragma unroll
    for (int ntd = 0; ntd < 8; ntd++) {
        int d = ntd * 8 + c2;
        *(float2*)&Xout[obase + (size_t)gr0 * DMODEL + d] =
            make_float2(o[ntd][0] * inv0, o[ntd][1] * inv0);
        *(float2*)&Xout[obase + (size_t)gr1 * DMODEL + d] =
            make_float2(o[ntd][2] * inv1, o[ntd][3] * inv1);
    }
}

// ===========================================================================
// Pooling path (Wo projection folded through, all fp32)
// ===========================================================================
// w~[h][e] = SCALE * sum_d R[h,d] * Wo[h*64+d, e];  c[h] = SCALE * R_h . bo_h
__global__ __launch_bounds__(256) void wtilde_kernel(
    const float* __restrict__ Wo, const float* __restrict__ readout,
    const float* __restrict__ bo, float* __restrict__ wt, float* __restrict__ cvec)
{
    __shared__ float r[64];
    const int h = blockIdx.x, t = threadIdx.x;
    if (t < 64) r[t] = readout[h * DH + t] * SCALE;
    __syncthreads();
    for (int e = t; e < DMODEL; e += 256) {
        float acc = 0.0f;
#pragma unroll 8
        for (int d = 0; d < DH; d++)
            acc = fmaf(r[d], Wo[(size_t)(h * DH + d) * DMODEL + e], acc);
        wt[h * DMODEL + e] = acc;
    }
    if (t == 0) {
        float c = 0.0f;
        for (int d = 0; d < DH; d++) c = fmaf(r[d], bo[h * DH + d], c);
        cvec[h] = c;
    }
}

// scores S[row][h] = mask>0 ? mask*(X_row . w~_h + c_h) : NEG
__global__ __launch_bounds__(256) void score_kernel(
    const float* __restrict__ X, const float* __restrict__ wt,
    const float* __restrict__ cvec, const float* __restrict__ maskp,
    float* __restrict__ S, int M)
{
    __shared__ float wts[NHEAD * DMODEL];
    __shared__ float cs[NHEAD];
    const int t = threadIdx.x, w = t >> 5, lane = t & 31;
    for (int i = t; i < NHEAD * DMODEL; i += 256) wts[i] = wt[i];
    if (t < NHEAD) cs[t] = cvec[t];
    __syncthreads();

    const int stride = gridDim.x * 8;
    for (int row = blockIdx.x * 8 + w; row < M; row += stride) {
        float acc[NHEAD];
#pragma unroll
        for (int h = 0; h < NHEAD; h++) acc[h] = 0.0f;
        const float* xr = X + (size_t)row * DMODEL;
#pragma unroll 4
        for (int i = 0; i < DMODEL / 32; i++) {
            float x = xr[lane + 32 * i];
#pragma unroll
            for (int h = 0; h < NHEAD; h++)
                acc[h] = fmaf(x, wts[h * DMODEL + lane + 32 * i], acc[h]);
        }
#pragma unroll
        for (int off = 16; off > 0; off >>= 1)
#pragma unroll
            for (int h = 0; h < NHEAD; h++)
                acc[h] += __shfl_xor_sync(0xffffffffu, acc[h], off);
        if (lane < NHEAD) {
            // lane h holds its own reduced value only on lane 0; gather via shfl
        }
        if (lane == 0) {
            float mk = maskp[row];
#pragma unroll
            for (int h = 0; h < NHEAD; h++)
                S[(size_t)row * NHEAD + h] = (mk > 0.0f) ? mk * (acc[h] + cs[h]) : NEGV;
        }
    }
}

// per-batch: softmax over keys per head, then Y[h][e] = sum_k P*mask*X
__global__ __launch_bounds__(256) void pool_fused(
    const float* __restrict__ X, const float* __restrict__ S,
    const float* __restrict__ maskp, float* __restrict__ Y,
    float* __restrict__ SW, int L)
{
    __shared__ __align__(16) float sp[512 * NHEAD];
    __shared__ float msk[512];
    __shared__ float swsh[NHEAD];
    const int n = blockIdx.x;
    const int t = threadIdx.x, w = t >> 5, lane = t & 31;

    for (int i = t; i < L * NHEAD; i += 256) sp[i] = S[(size_t)n * L * NHEAD + i];
    for (int i = t; i < L; i += 256) msk[i] = maskp[n * L + i];
    __syncthreads();

    for (int h = w; h < NHEAD; h += 8) {
        float m = -1e30f;
        for (int k = lane; k < L; k += 32) m = fmaxf(m, sp[k * NHEAD + h]);
#pragma unroll
        for (int off = 16; off > 0; off >>= 1)
            m = fmaxf(m, __shfl_xor_sync(0xffffffffu, m, off));
        float se = 0.0f, swr = 0.0f;
        for (int k = lane; k < L; k += 32) {
            float p = __expf(sp[k * NHEAD + h] - m);
            se += p;
            swr += p * msk[k];
        }
#pragma unroll
        for (int off = 16; off > 0; off >>= 1) {
            se  += __shfl_xor_sync(0xffffffffu, se, off);
            swr += __shfl_xor_sync(0xffffffffu, swr, off);
        }
        float inv = 1.0f / se;
        for (int k = lane; k < L; k += 32)
            sp[k * NHEAD + h] = __expf(sp[k * NHEAD + h] - m) * inv * msk[k];
        if (lane == 0) swsh[h] = swr * inv;
    }
    __syncthreads();

    // Y accumulation: thread owns e = {t, t+256, t+512} for all 12 heads
    float acc[NHEAD][3];
#pragma unroll
    for (int h = 0; h < NHEAD; h++)
#pragma unroll
        for (int j = 0; j < 3; j++) acc[h][j] = 0.0f;
    const float* Xn = X + (size_t)n * L * DMODEL;
    for (int k = 0; k < L; k++) {
        const float* pr = &sp[k * NHEAD];
        float4 pa = *(const float4*)pr;
        float4 pb = *(const float4*)(pr + 4);
        float4 pc = *(const float4*)(pr + 8);
        float p[NHEAD] = {pa.x, pa.y, pa.z, pa.w, pb.x, pb.y, pb.z, pb.w,
                          pc.x, pc.y, pc.z, pc.w};
        float x0 = Xn[(size_t)k * DMODEL + t];
        float x1 = Xn[(size_t)k * DMODEL + t + 256];
        float x2 = Xn[(size_t)k * DMODEL + t + 512];
#pragma unroll
        for (int h = 0; h < NHEAD; h++) {
            acc[h][0] = fmaf(p[h], x0, acc[h][0]);
            acc[h][1] = fmaf(p[h], x1, acc[h][1]);
            acc[h][2] = fmaf(p[h], x2, acc[h][2]);
        }
    }
#pragma unroll
    for (int h = 0; h < NHEAD; h++) {
        float* yr = Y + ((size_t)n * NHEAD + h) * DMODEL;
        yr[t]       = acc[h][0];
        yr[t + 256] = acc[h][1];
        yr[t + 512] = acc[h][2];
    }
    if (t < NHEAD) SW[n * NHEAD + t] = swsh[t];
}

// pooled[n][d] = sum_e Wo[d,e] * Y[n,h(d),e] + bo[d]*sw[n,h(d)]
__global__ __launch_bounds__(256) void proj_out(
    const float* __restrict__ Y, const float* __restrict__ SW,
    const float* __restrict__ Wo, const float* __restrict__ bo,
    float* __restrict__ out)
{
    __shared__ __align__(16) float ys[NHEAD * DMODEL];
    __shared__ float sws[NHEAD];
    const int n = blockIdx.x, t = threadIdx.x;
    for (int i = t; i < NHEAD * DMODEL; i += 256) ys[i] = Y[(size_t)n * NHEAD * DMODEL + i];
    if (t < NHEAD) sws[t] = SW[n * NHEAD + t];
    __syncthreads();
#pragma unroll
    for (int j = 0; j < 3; j++) {
        int d = t + j * 256;
        int h = d >> 6;
        const float* wr = Wo + (size_t)d * DMODEL;
        const float* yr = ys + h * DMODEL;
        float acc = 0.0f;
#pragma unroll 4
        for (int e = 0; e < DMODEL; e += 4) {
            float4 wv = *(const float4*)&wr[e];
            acc = fmaf(wv.x, yr[e],     acc);
            acc = fmaf(wv.y, yr[e + 1], acc);
            acc = fmaf(wv.z, yr[e + 2], acc);
            acc = fmaf(wv.w, yr[e + 3], acc);
        }
        out[(size_t)n * DMODEL + d] = acc + bo[d] * sws[h];
    }
}

// ---------------------------------------------------------------------------
extern "C" void kernel_launch(void* const* d_in, const int* in_sizes, int n_in,
                              void* d_out, int out_size)
{
    const float* tokens  = (const float*)d_in[0];
    const float* ts      = (const float*)d_in[1];
    const float* maskp   = (const float*)d_in[2];
    const float* Wq      = (const float*)d_in[3];
    const float* bq      = (const float*)d_in[4];
    const float* Wk      = (const float*)d_in[5];
    const float* bk      = (const float*)d_in[6];
    const float* Wv      = (const float*)d_in[7];
    const float* bv      = (const float*)d_in[8];
    const float* Wo      = (const float*)d_in[9];
    const float* bo      = (const float*)d_in[10];
    const float* readout = (const float*)d_in[11];
    float* out = (float*)d_out;
    (void)n_in;

    const int M  = in_sizes[0] / DMODEL;   // 32768
    const int Nb = out_size / DMODEL;      // 64
    const int L  = M / Nb;                 // 512

    float *gX, *gbias, *gwt, *gc, *gS, *gY, *gsw;
    __nv_bfloat16 *gth, *gtl, *gwh, *gwl, *gqkvh, *gqkvl;
    cudaGetSymbolAddress((void**)&gX, g_X);
    cudaGetSymbolAddress((void**)&gth, g_th);
    cudaGetSymbolAddress((void**)&gtl, g_tl);
    cudaGetSymbolAddress((void**)&gwh, g_wh);
    cudaGetSymbolAddress((void**)&gwl, g_wl);
    cudaGetSymbolAddress((void**)&gqkvh, g_qkvh);
    cudaGetSymbolAddress((void**)&gqkvl, g_qkvl);
    cudaGetSymbolAddress((void**)&gbias, g_bias);
    cudaGetSymbolAddress((void**)&gwt, g_wt);
    cudaGetSymbolAddress((void**)&gc, g_c);
    cudaGetSymbolAddress((void**)&gS, g_S);
    cudaGetSymbolAddress((void**)&gY, g_Y);
    cudaGetSymbolAddress((void**)&gsw, g_sw);

    // concat QKV biases
    cudaMemcpyAsync(gbias,              bq, DMODEL * sizeof(float), cudaMemcpyDeviceToDevice);
    cudaMemcpyAsync(gbias + DMODEL,     bk, DMODEL * sizeof(float), cudaMemcpyDeviceToDevice);
    cudaMemcpyAsync(gbias + 2 * DMODEL, bv, DMODEL * sizeof(float), cudaMemcpyDeviceToDevice);

    // pre-split tokens + QKV weights
    const int tok4 = M * DMODEL / 4;
    split_f32<<<(tok4 + 255) / 256, 256>>>(tokens, gth, gtl, tok4);
    const int w4 = WSZ / 4;
    dim3 wg((w4 + 255) / 256, 3);
    split_w<<<wg, 256>>>(Wq, Wk, Wv, gwh, gwl, w4);

    // pooling precompute (independent of GEMMs)
    wtilde_kernel<<<NHEAD, 256>>>(Wo, readout, bo, gwt, gc);

    cudaFuncSetAttribute(gemm_tc_split, cudaFuncAttributeMaxDynamicSharedMemorySize, G_SMEM);
    dim3 gqkv(LDQKV / GBN, M / GBM);
    gemm_tc_split<<<gqkv, 256, G_SMEM>>>(gth, gtl, gwh, gwl, gbias,
                                         DMODEL, LDQKV, gqkvh, gqkvl, M, DMODEL);

    cudaFuncSetAttribute(attn_tc, cudaFuncAttributeMaxDynamicSharedMemorySize,
                         A_SMEM_TOTAL);
    dim3 ag(L / 128, NHEAD, Nb);
    attn_tc<<<ag, 256, A_SMEM_TOTAL>>>(gqkvh, gqkvl, ts, maskp, gX, L);

    // pooling path (Wo folded)
    score_kernel<<<512, 256>>>(gX, gwt, gc, maskp, gS, M);
    pool_fused<<<Nb, 256>>>(gX, gS, maskp, gY, gsw, L);
    proj_out<<<Nb, 256>>>(gY, gsw, Wo, bo, out);
}

// round 12
// speedup vs baseline: 1.9055x; 1.0876x over previous
#include <cuda_runtime.h>
#include <cuda_bf16.h>
#include <math.h>
#include <stdint.h>

#define DMODEL 768
#define NHEAD  12
#define DH     64
#define TAU    300.0f
#define INV_TAU (1.0f / 300.0f)
#define NEGV   (-1e9f)
#define SCALE  0.125f   /* 1/sqrt(64) */

#define MAXM (64 * 512)
#define WSZ  (DMODEL * DMODEL)
#define LDQKV (3 * DMODEL)   /* 2304 */
#define NBATCH 64

// fp32 attention output X (pool/proj input)
__device__ float g_X[MAXM * DMODEL];
// bf16 hi/lo split scratch
__device__ __nv_bfloat16 g_th[MAXM * DMODEL];
__device__ __nv_bfloat16 g_tl[MAXM * DMODEL];
__device__ __nv_bfloat16 g_qkvh[MAXM * LDQKV];
__device__ __nv_bfloat16 g_qkvl[MAXM * LDQKV];
__device__ __nv_bfloat16 g_wh[3 * WSZ];
__device__ __nv_bfloat16 g_wl[3 * WSZ];
__device__ float g_bias[LDQKV];
// pooling path scratch (all fp32)
__device__ float g_wt[NHEAD * DMODEL];
__device__ float g_c[NHEAD];
__device__ float g_S[MAXM * NHEAD];             // scores -> probabilities (in place)
__device__ float g_Y[NBATCH * NHEAD * DMODEL];
__device__ float g_sw[NBATCH * NHEAD];

// ===========================================================================
// helpers
// ===========================================================================
__device__ __forceinline__ uint32_t smem_u32(const void* p) {
    uint32_t a;
    asm("{ .reg .u64 t; cvta.to.shared.u64 t, %1; cvt.u32.u64 %0, t; }"
        : "=r"(a) : "l"(p));
    return a;
}

__device__ __forceinline__ void ldsm4(uint32_t* r, uint32_t addr) {
    asm volatile("ldmatrix.sync.aligned.m8n8.x4.shared.b16 {%0,%1,%2,%3}, [%4];"
                 : "=r"(r[0]), "=r"(r[1]), "=r"(r[2]), "=r"(r[3]) : "r"(addr));
}
__device__ __forceinline__ void ldsm4t(uint32_t* r, uint32_t addr) {
    asm volatile("ldmatrix.sync.aligned.m8n8.x4.trans.shared.b16 {%0,%1,%2,%3}, [%4];"
                 : "=r"(r[0]), "=r"(r[1]), "=r"(r[2]), "=r"(r[3]) : "r"(addr));
}

__device__ __forceinline__ void mma16816(float* c, const uint32_t* a,
                                         const uint32_t* b) {
    asm volatile(
        "mma.sync.aligned.m16n8k16.row.col.f32.bf16.bf16.f32 "
        "{%0,%1,%2,%3}, {%4,%5,%6,%7}, {%8,%9}, {%0,%1,%2,%3};"
        : "+f"(c[0]), "+f"(c[1]), "+f"(c[2]), "+f"(c[3])
        : "r"(a[0]), "r"(a[1]), "r"(a[2]), "r"(a[3]), "r"(b[0]), "r"(b[1]));
}

__device__ __forceinline__ void cp16(uint32_t dst, const void* src) {
    asm volatile("cp.async.cg.shared.global [%0], [%1], 16;"
                 :: "r"(dst), "l"(src));
}

__device__ __forceinline__ void split4(float4 v, uint2& h, uint2& l) {
    __nv_bfloat16 h0 = __float2bfloat16_rn(v.x);
    __nv_bfloat16 h1 = __float2bfloat16_rn(v.y);
    __nv_bfloat16 h2 = __float2bfloat16_rn(v.z);
    __nv_bfloat16 h3 = __float2bfloat16_rn(v.w);
    __nv_bfloat16 l0 = __float2bfloat16_rn(v.x - __bfloat162float(h0));
    __nv_bfloat16 l1 = __float2bfloat16_rn(v.y - __bfloat162float(h1));
    __nv_bfloat16 l2 = __float2bfloat16_rn(v.z - __bfloat162float(h2));
    __nv_bfloat16 l3 = __float2bfloat16_rn(v.w - __bfloat162float(h3));
    h.x = (uint32_t)__bfloat16_as_ushort(h0) | ((uint32_t)__bfloat16_as_ushort(h1) << 16);
    h.y = (uint32_t)__bfloat16_as_ushort(h2) | ((uint32_t)__bfloat16_as_ushort(h3) << 16);
    l.x = (uint32_t)__bfloat16_as_ushort(l0) | ((uint32_t)__bfloat16_as_ushort(l1) << 16);
    l.y = (uint32_t)__bfloat16_as_ushort(l2) | ((uint32_t)__bfloat16_as_ushort(l3) << 16);
}

__device__ __forceinline__ uint32_t pack_bf16(float a, float b) {
    __nv_bfloat162 t = __floats2bfloat162_rn(a, b);
    return *(uint32_t*)&t;
}
__device__ __forceinline__ void split2(float a, float b, uint32_t& h, uint32_t& l) {
    __nv_bfloat16 ha = __float2bfloat16_rn(a);
    __nv_bfloat16 hb = __float2bfloat16_rn(b);
    float la = a - __bfloat162float(ha);
    float lb = b - __bfloat162float(hb);
    h = (uint32_t)__bfloat16_as_ushort(ha) | ((uint32_t)__bfloat16_as_ushort(hb) << 16);
    l = pack_bf16(la, lb);
}

// ===========================================================================
// elementwise f32 -> bf16 hi/lo splits
// ===========================================================================
__global__ __launch_bounds__(256) void split_f32(
    const float* __restrict__ X, __nv_bfloat16* __restrict__ Xh,
    __nv_bfloat16* __restrict__ Xl, int n4)
{
    int i = blockIdx.x * blockDim.x + threadIdx.x;
    if (i < n4) {
        float4 v = ((const float4*)X)[i];
        uint2 h, l;
        split4(v, h, l);
        ((uint2*)Xh)[i] = h;
        ((uint2*)Xl)[i] = l;
    }
}

__global__ __launch_bounds__(256) void split_w(
    const float* __restrict__ W0, const float* __restrict__ W1,
    const float* __restrict__ W2,
    __nv_bfloat16* __restrict__ Xh, __nv_bfloat16* __restrict__ Xl, int n4)
{
    const int m = blockIdx.y;
    const float* X = (m == 0) ? W0 : (m == 1) ? W1 : W2;
    int i = blockIdx.x * blockDim.x + threadIdx.x;
    if (i < n4) {
        float4 v = ((const float4*)X)[i];
        uint2 h, l;
        split4(v, h, l);
        ((uint2*)(Xh + (size_t)m * WSZ))[i] = h;
        ((uint2*)(Xl + (size_t)m * WSZ))[i] = l;
    }
}

// ===========================================================================
// HMMA GEMM (cp.async 2-stage, pre-split bf16 inputs), occupancy 2.
// ===========================================================================
#define GBM 128
#define GBN 128
#define GBK 32
#define G_AH 0
#define G_AL 10240
#define G_BH 20480
#define G_BL 30720
#define G_STAGE 40960
#define G_BIAS  81920
#define G_SMEM  (81920 + 512)

__global__ __launch_bounds__(256, 2) void gemm_tc_split(
    const __nv_bfloat16* __restrict__ Ahg, const __nv_bfloat16* __restrict__ Alg,
    const __nv_bfloat16* __restrict__ Whg, const __nv_bfloat16* __restrict__ Wlg,
    const float* __restrict__ bias, int qcols, int ldc,
    __nv_bfloat16* __restrict__ Ch, __nv_bfloat16* __restrict__ Cl,
    int M, int K)
{
    extern __shared__ char gsm[];
    const uint32_t sbase = smem_u32(gsm);
    float* bias_s = (float*)(gsm + G_BIAS);
    const int t = threadIdx.x;
    const int wid = t >> 5, lane = t & 31;
    const int n0 = blockIdx.x * GBN;
    const int m0 = blockIdx.y * GBM;
    if (t < GBN) bias_s[t] = bias[n0 + t];
    const int lr = t >> 1;
    const int lcp = (t & 1) * 2;
    const __nv_bfloat16* srcAh = Ahg + (size_t)(m0 + lr) * K + lcp * 8;
    const __nv_bfloat16* srcAl = Alg + (size_t)(m0 + lr) * K + lcp * 8;
    const __nv_bfloat16* srcBh = Whg + (size_t)(n0 + lr) * K + lcp * 8;
    const __nv_bfloat16* srcBl = Wlg + (size_t)(n0 + lr) * K + lcp * 8;
    const uint32_t dst_row = sbase + (uint32_t)lr * 80 + (uint32_t)lcp * 16;
    const int NITER = K / GBK;

#define G_ISSUE(bufi, kc)                                                     \
    do {                                                                      \
        uint32_t d = dst_row + (bufi) * G_STAGE;                              \
        cp16(d + G_AH,      srcAh + (kc));                                    \
        cp16(d + G_AH + 16, srcAh + (kc) + 8);                                \
        cp16(d + G_AL,      srcAl + (kc));                                    \
        cp16(d + G_AL + 16, srcAl + (kc) + 8);                                \
        cp16(d + G_BH,      srcBh + (kc));                                    \
        cp16(d + G_BH + 16, srcBh + (kc) + 8);                                \
        cp16(d + G_BL,      srcBl + (kc));                                    \
        cp16(d + G_BL + 16, srcBl + (kc) + 8);                                \
    } while (0)

    G_ISSUE(0, 0);
    asm volatile("cp.async.commit_group;" ::: "memory");
    const int wm = wid >> 2;
    const int wn = wid & 3;
    const int a_row = lane & 15;
    const int a_chk = (lane >> 4) & 1;
    const int b_n   = (lane & 7) + ((lane >> 4) & 1) * 8;
    const int b_chk = (lane >> 3) & 1;
    float acc[4][4][4];
#pragma unroll
    for (int mi = 0; mi < 4; mi++)
#pragma unroll
        for (int ni = 0; ni < 4; ni++)
#pragma unroll
            for (int j = 0; j < 4; j++) acc[mi][ni][j] = 0.0f;

    for (int it = 0; it < NITER; it++) {
        const int buf = it & 1;
        if (it + 1 < NITER) {
            G_ISSUE(buf ^ 1, (it + 1) * GBK);
            asm volatile("cp.async.commit_group;" ::: "memory");
            asm volatile("cp.async.wait_group 1;" ::: "memory");
        } else {
            asm volatile("cp.async.wait_group 0;" ::: "memory");
        }
        __syncthreads();
        const uint32_t st = sbase + buf * G_STAGE;
        const uint32_t ah_s = st + G_AH, al_s = st + G_AL;
        const uint32_t bh_s = st + G_BH, bl_s = st + G_BL;
#pragma unroll
        for (int s = 0; s < 2; s++) {
            uint32_t bhf[8], blf[8];
#pragma unroll
            for (int nt = 0; nt < 2; nt++) {
                uint32_t boff = (uint32_t)(wn * 32 + nt * 16 + b_n) * 80
                              + s * 32 + b_chk * 16;
                ldsm4(bhf + nt * 4, bh_s + boff);
                ldsm4(blf + nt * 4, bl_s + boff);
            }
#pragma unroll
            for (int mi = 0; mi < 4; mi++) {
                uint32_t aoff = (uint32_t)(wm * 64 + mi * 16 + a_row) * 80
                              + s * 32 + a_chk * 16;
                uint32_t ahf[4], alf[4];
                ldsm4(ahf, ah_s + aoff);
                ldsm4(alf, al_s + aoff);
#pragma unroll
                for (int ni = 0; ni < 4; ni++) {
                    mma16816(acc[mi][ni], ahf, bhf + ni * 2);
                    mma16816(acc[mi][ni], ahf, blf + ni * 2);
                    mma16816(acc[mi][ni], alf, bhf + ni * 2);
                }
            }
        }
        __syncthreads();
    }

    const float oscale = (n0 < qcols) ? SCALE : 1.0f;
    const int r0 = lane >> 2;
    const int c0 = (lane & 3) * 2;
#pragma unroll
    for (int mi = 0; mi < 4; mi++) {
        int mA = m0 + wm * 64 + mi * 16 + r0;
        int mB = mA + 8;
#pragma unroll
        for (int ni = 0; ni < 4; ni++) {
            int n = wn * 32 + ni * 8 + c0;
            float b0 = bias_s[n], b1 = bias_s[n + 1];
            uint32_t h, l;
            split2((acc[mi][ni][0] + b0) * oscale, (acc[mi][ni][1] + b1) * oscale, h, l);
            *(uint32_t*)&Ch[(size_t)mA * ldc + n0 + n] = h;
            *(uint32_t*)&Cl[(size_t)mA * ldc + n0 + n] = l;
            split2((acc[mi][ni][2] + b0) * oscale, (acc[mi][ni][3] + b1) * oscale, h, l);
            *(uint32_t*)&Ch[(size_t)mB * ldc + n0 + n] = h;
            *(uint32_t*)&Cl[(size_t)mB * ldc + n0 + n] = l;
        }
    }
}

// ===========================================================================
// Tensor-core flash attention (occupancy 2); writes fp32 X output.
// ===========================================================================
#define APITCH 72
#define A_QHO 0
#define A_QLO 18432
#define A_BUF0 36864
#define A_KHO 0
#define A_KLO 9216
#define A_VHO 18432
#define A_VLO 27648
#define A_TKO 36864
#define A_MKO 37120
#define A_BUFSZ 37888
#define A_SMEM_TOTAL (A_BUF0 + 2 * A_BUFSZ)   /* 112640 */

__global__ __launch_bounds__(256, 2) void attn_tc(
    const __nv_bfloat16* __restrict__ QKVh, const __nv_bfloat16* __restrict__ QKVl,
    const float* __restrict__ ts, const float* __restrict__ maskp,
    float* __restrict__ Xout, int L)
{
    extern __shared__ char smem[];
    const uint32_t sbase = smem_u32(smem);

    const int t = threadIdx.x, w = t >> 5, lane = t & 31;
    const int q0 = blockIdx.x * 128, h = blockIdx.y, n = blockIdx.z;
    const size_t kvbase = (size_t)n * L * LDQKV + (size_t)h * DH;
    const size_t obase  = (size_t)n * L * DMODEL + (size_t)h * DH;
    const int nchunk = L / 64;

    const __nv_bfloat16* Kh_g = QKVh + DMODEL;
    const __nv_bfloat16* Kl_g = QKVl + DMODEL;
    const __nv_bfloat16* Vh_g = QKVh + 2 * DMODEL;
    const __nv_bfloat16* Vl_g = QKVl + 2 * DMODEL;

#define A_ISSUE(bufi, cc)                                                     \
    do {                                                                      \
        const uint32_t bb = sbase + A_BUF0 + (bufi) * A_BUFSZ;                \
        const int kk0 = (cc) * 64;                                            \
        _Pragma("unroll")                                                     \
        for (int idx = t; idx < 512; idx += 256) {                            \
            int row = idx >> 3, ch = idx & 7;                                 \
            size_t g = kvbase + (size_t)(kk0 + row) * LDQKV + ch * 8;         \
            uint32_t doff = (uint32_t)row * 144 + ch * 16;                    \
            cp16(bb + A_KHO + doff, Kh_g + g);                                \
            cp16(bb + A_KLO + doff, Kl_g + g);                                \
            cp16(bb + A_VHO + doff, Vh_g + g);                                \
            cp16(bb + A_VLO + doff, Vl_g + g);                                \
        }                                                                     \
        if (t < 16)                                                           \
            cp16(bb + A_TKO + t * 16, ts + n * L + kk0 + t * 4);              \
        else if (t < 32)                                                      \
            cp16(bb + A_MKO + (t - 16) * 16, maskp + n * L + kk0 + (t - 16) * 4); \
    } while (0)

    A_ISSUE(0, 0);
    asm volatile("cp.async.commit_group;" ::: "memory");

    {
        __nv_bfloat16* Qh = (__nv_bfloat16*)(smem + A_QHO);
        __nv_bfloat16* Ql = (__nv_bfloat16*)(smem + A_QLO);
#pragma unroll
        for (int idx = t; idx < 1024; idx += 256) {
            int row = idx >> 3, ch = idx & 7;
            size_t g = kvbase + (size_t)(q0 + row) * LDQKV + ch * 8;
            *(uint4*)&Qh[row * APITCH + ch * 8] = *(const uint4*)(QKVh + g);
            *(uint4*)&Ql[row * APITCH + ch * 8] = *(const uint4*)(QKVl + g);
        }
    }
    __syncthreads();

    const int a_row = lane & 15, a_chk = (lane >> 4) & 1;
    const int r0 = lane >> 2, c2 = (lane & 3) * 2;
    const float tq0 = ts[n * L + q0 + w * 16 + r0];
    const float tq1 = ts[n * L + q0 + w * 16 + r0 + 8];

    float o[8][4];
#pragma unroll
    for (int i = 0; i < 8; i++)
#pragma unroll
        for (int j = 0; j < 4; j++) o[i][j] = 0.0f;
    float m0 = -1e30f, m1 = -1e30f, l0 = 0.0f, l1 = 0.0f;

    const int b_n = (lane & 7) + ((lane >> 4) & 1) * 8;
    const int b_chk = (lane >> 3) & 1;
    const int v_row = lane & 15;
    const int v_col = (lane >> 4) * 8;

    for (int c = 0; c < nchunk; c++) {
        const int buf = c & 1;
        if (c + 1 < nchunk) {
            A_ISSUE(buf ^ 1, c + 1);
            asm volatile("cp.async.commit_group;" ::: "memory");
            asm volatile("cp.async.wait_group 1;" ::: "memory");
        } else {
            asm volatile("cp.async.wait_group 0;" ::: "memory");
        }
        __syncthreads();

        const uint32_t bb = sbase + A_BUF0 + buf * A_BUFSZ;
        const uint32_t kh_s = bb + A_KHO, kl_s = bb + A_KLO;
        const uint32_t vh_s = bb + A_VHO, vl_s = bb + A_VLO;
        const float* tks = (const float*)(smem + A_BUF0 + buf * A_BUFSZ + A_TKO);
        const float* mks = (const float*)(smem + A_BUF0 + buf * A_BUFSZ + A_MKO);

        float S[8][4];
#pragma unroll
        for (int i = 0; i < 8; i++)
#pragma unroll
            for (int j = 0; j < 4; j++) S[i][j] = 0.0f;
#pragma unroll
        for (int ks = 0; ks < 4; ks++) {
            uint32_t qh4[4], ql4[4];
            uint32_t aoff = (uint32_t)(w * 16 + a_row) * 144 + ks * 32 + a_chk * 16;
            ldsm4(qh4, sbase + A_QHO + aoff);
            ldsm4(ql4, sbase + A_QLO + aoff);
#pragma unroll
            for (int g = 0; g < 4; g++) {
                uint32_t boff = (uint32_t)(g * 16 + b_n) * 144 + ks * 32 + b_chk * 16;
                uint32_t bh[4], bl[4];
                ldsm4(bh, kh_s + boff);
                ldsm4(bl, kl_s + boff);
#pragma unroll
                for (int ni = 0; ni < 2; ni++) {
                    mma16816(S[g * 2 + ni], qh4, bh + ni * 2);
                    mma16816(S[g * 2 + ni], qh4, bl + ni * 2);
                    mma16816(S[g * 2 + ni], ql4, bh + ni * 2);
                }
            }
        }

        float cm0 = -1e30f, cm1 = -1e30f;
#pragma unroll
        for (int nt = 0; nt < 8; nt++) {
#pragma unroll
            for (int j = 0; j < 2; j++) {
                int key = nt * 8 + c2 + j;
                float tk = tks[key];
                bool ok = mks[key] > 0.0f;
                float bA = -fabsf(tq0 - tk) * INV_TAU;
                float bB = -fabsf(tq1 - tk) * INV_TAU;
                S[nt][j]     = ok ? S[nt][j]     + bA : NEGV;
                S[nt][j + 2] = ok ? S[nt][j + 2] + bB : NEGV;
                cm0 = fmaxf(cm0, S[nt][j]);
                cm1 = fmaxf(cm1, S[nt][j + 2]);
            }
        }
#pragma unroll
        for (int off = 1; off <= 2; off <<= 1) {
            cm0 = fmaxf(cm0, __shfl_xor_sync(0xffffffffu, cm0, off));
            cm1 = fmaxf(cm1, __shfl_xor_sync(0xffffffffu, cm1, off));
        }
        float nm0 = fmaxf(m0, cm0), nm1 = fmaxf(m1, cm1);
        float cr0 = __expf(m0 - nm0), cr1 = __expf(m1 - nm1);
        m0 = nm0; m1 = nm1;

        float ps0 = 0.0f, ps1 = 0.0f;
#pragma unroll
        for (int nt = 0; nt < 8; nt++) {
            float p00 = __expf(S[nt][0] - nm0);
            float p01 = __expf(S[nt][1] - nm0);
            float p10 = __expf(S[nt][2] - nm1);
            float p11 = __expf(S[nt][3] - nm1);
            ps0 += p00 + p01; ps1 += p10 + p11;
            S[nt][0] = p00; S[nt][1] = p01; S[nt][2] = p10; S[nt][3] = p11;
        }
#pragma unroll
        for (int off = 1; off <= 2; off <<= 1) {
            ps0 += __shfl_xor_sync(0xffffffffu, ps0, off);
            ps1 += __shfl_xor_sync(0xffffffffu, ps1, off);
        }
        l0 = l0 * cr0 + ps0;
        l1 = l1 * cr1 + ps1;

#pragma unroll
        for (int i = 0; i < 8; i++) {
            o[i][0] *= cr0; o[i][1] *= cr0;
            o[i][2] *= cr1; o[i][3] *= cr1;
        }

#pragma unroll
        for (int kt = 0; kt < 4; kt++) {
            uint32_t pah[4], pal[4];
            split2(S[2 * kt][0],     S[2 * kt][1],     pah[0], pal[0]);
            split2(S[2 * kt][2],     S[2 * kt][3],     pah[1], pal[1]);
            split2(S[2 * kt + 1][0], S[2 * kt + 1][1], pah[2], pal[2]);
            split2(S[2 * kt + 1][2], S[2 * kt + 1][3], pah[3], pal[3]);
#pragma unroll
            for (int g = 0; g < 4; g++) {
                uint32_t voff = (uint32_t)(kt * 16 + v_row) * 144
                              + (uint32_t)(g * 16 + v_col) * 2;
                uint32_t bh[4], bl[4];
                ldsm4t(bh, vh_s + voff);
                ldsm4t(bl, vl_s + voff);
#pragma unroll
                for (int ni = 0; ni < 2; ni++) {
                    mma16816(o[g * 2 + ni], pah, bh + ni * 2);
                    mma16816(o[g * 2 + ni], pal, bh + ni * 2);
                    mma16816(o[g * 2 + ni], pah, bl + ni * 2);
                }
            }
        }
        __syncthreads();
    }

    const float inv0 = 1.0f / l0, inv1 = 1.0f / l1;
    const int gr0 = q0 + w * 16 + r0, gr1 = gr0 + 8;
#pragma unroll
    for (int ntd = 0; ntd < 8; ntd++) {
        int d = ntd * 8 + c2;
        *(float2*)&Xout[obase + (size_t)gr0 * DMODEL + d] =
            make_float2(o[ntd][0] * inv0, o[ntd][1] * inv0);
        *(float2*)&Xout[obase + (size_t)gr1 * DMODEL + d] =
            make_float2(o[ntd][2] * inv1, o[ntd][3] * inv1);
    }
}

// ===========================================================================
// Pooling path (Wo projection folded through, all fp32)
// ===========================================================================
__global__ __launch_bounds__(256) void wtilde_kernel(
    const float* __restrict__ Wo, const float* __restrict__ readout,
    const float* __restrict__ bo, float* __restrict__ wt, float* __restrict__ cvec)
{
    __shared__ float r[64];
    const int h = blockIdx.x, t = threadIdx.x;
    if (t < 64) r[t] = readout[h * DH + t] * SCALE;
    __syncthreads();
    for (int e = t; e < DMODEL; e += 256) {
        float acc = 0.0f;
#pragma unroll 8
        for (int d = 0; d < DH; d++)
            acc = fmaf(r[d], Wo[(size_t)(h * DH + d) * DMODEL + e], acc);
        wt[h * DMODEL + e] = acc;
    }
    if (t == 0) {
        float c = 0.0f;
        for (int d = 0; d < DH; d++) c = fmaf(r[d], bo[h * DH + d], c);
        cvec[h] = c;
    }
}

__global__ __launch_bounds__(256) void score_kernel(
    const float* __restrict__ X, const float* __restrict__ wt,
    const float* __restrict__ cvec, const float* __restrict__ maskp,
    float* __restrict__ S, int M)
{
    __shared__ float wts[NHEAD * DMODEL];
    __shared__ float cs[NHEAD];
    const int t = threadIdx.x, w = t >> 5, lane = t & 31;
    for (int i = t; i < NHEAD * DMODEL; i += 256) wts[i] = wt[i];
    if (t < NHEAD) cs[t] = cvec[t];
    __syncthreads();

    const int stride = gridDim.x * 8;
    for (int row = blockIdx.x * 8 + w; row < M; row += stride) {
        float acc[NHEAD];
#pragma unroll
        for (int h = 0; h < NHEAD; h++) acc[h] = 0.0f;
        const float* xr = X + (size_t)row * DMODEL;
#pragma unroll 4
        for (int i = 0; i < DMODEL / 32; i++) {
            float x = xr[lane + 32 * i];
#pragma unroll
            for (int h = 0; h < NHEAD; h++)
                acc[h] = fmaf(x, wts[h * DMODEL + lane + 32 * i], acc[h]);
        }
#pragma unroll
        for (int off = 16; off > 0; off >>= 1)
#pragma unroll
            for (int h = 0; h < NHEAD; h++)
                acc[h] += __shfl_xor_sync(0xffffffffu, acc[h], off);
        if (lane == 0) {
            float mk = maskp[row];
#pragma unroll
            for (int h = 0; h < NHEAD; h++)
                S[(size_t)row * NHEAD + h] = (mk > 0.0f) ? mk * (acc[h] + cs[h]) : NEGV;
        }
    }
}

// per-batch softmax over keys per head; P written back in place; sw out.
__global__ __launch_bounds__(256) void pool_softmax(
    float* __restrict__ S, const float* __restrict__ maskp,
    float* __restrict__ SW, int L)
{
    __shared__ __align__(16) float sp[512 * NHEAD];
    __shared__ float msk[512];
    const int n = blockIdx.x;
    const int t = threadIdx.x, w = t >> 5, lane = t & 31;

    for (int i = t; i < L * NHEAD; i += 256) sp[i] = S[(size_t)n * L * NHEAD + i];
    for (int i = t; i < L; i += 256) msk[i] = maskp[n * L + i];
    __syncthreads();

    for (int h = w; h < NHEAD; h += 8) {
        float m = -1e30f;
        for (int k = lane; k < L; k += 32) m = fmaxf(m, sp[k * NHEAD + h]);
#pragma unroll
        for (int off = 16; off > 0; off >>= 1)
            m = fmaxf(m, __shfl_xor_sync(0xffffffffu, m, off));
        float se = 0.0f, swr = 0.0f;
        for (int k = lane; k < L; k += 32) {
            float p = __expf(sp[k * NHEAD + h] - m);
            se += p;
            swr += p * msk[k];
        }
#pragma unroll
        for (int off = 16; off > 0; off >>= 1) {
            se  += __shfl_xor_sync(0xffffffffu, se, off);
            swr += __shfl_xor_sync(0xffffffffu, swr, off);
        }
        float inv = 1.0f / se;
        for (int k = lane; k < L; k += 32)
            sp[k * NHEAD + h] = __expf(sp[k * NHEAD + h] - m) * inv * msk[k];
        if (lane == 0) SW[n * NHEAD + h] = swr * inv;
    }
    __syncthreads();
    for (int i = t; i < L * NHEAD; i += 256) S[(size_t)n * L * NHEAD + i] = sp[i];
}

// Y[n,h,e0:e0+128]: grid (Nb, 6); thread = (k-group, e); k split 2 ways.
__global__ __launch_bounds__(256) void pool_y(
    const float* __restrict__ X, const float* __restrict__ P,
    float* __restrict__ Y, int L)
{
    __shared__ __align__(16) float sp[512 * NHEAD];
    __shared__ float red[NHEAD][128];
    const int n = blockIdx.x, eb = blockIdx.y;
    const int t = threadIdx.x;
    const int kg = t >> 7;            // 0 or 1
    const int e  = eb * 128 + (t & 127);

    for (int i = t; i < L * NHEAD; i += 256) sp[i] = P[(size_t)n * L * NHEAD + i];
    __syncthreads();

    float acc[NHEAD];
#pragma unroll
    for (int h = 0; h < NHEAD; h++) acc[h] = 0.0f;
    const float* Xn = X + (size_t)n * L * DMODEL + e;
    for (int k = kg; k < L; k += 2) {
        float x = Xn[(size_t)k * DMODEL];
        const float* pr = &sp[k * NHEAD];
        float4 pa = *(const float4*)pr;
        float4 pb = *(const float4*)(pr + 4);
        float4 pc = *(const float4*)(pr + 8);
        acc[0]  = fmaf(pa.x, x, acc[0]);
        acc[1]  = fmaf(pa.y, x, acc[1]);
        acc[2]  = fmaf(pa.z, x, acc[2]);
        acc[3]  = fmaf(pa.w, x, acc[3]);
        acc[4]  = fmaf(pb.x, x, acc[4]);
        acc[5]  = fmaf(pb.y, x, acc[5]);
        acc[6]  = fmaf(pb.z, x, acc[6]);
        acc[7]  = fmaf(pb.w, x, acc[7]);
        acc[8]  = fmaf(pc.x, x, acc[8]);
        acc[9]  = fmaf(pc.y, x, acc[9]);
        acc[10] = fmaf(pc.z, x, acc[10]);
        acc[11] = fmaf(pc.w, x, acc[11]);
    }
    // reduce the two k-groups
    if (kg == 1) {
#pragma unroll
        for (int h = 0; h < NHEAD; h++) red[h][t & 127] = acc[h];
    }
    __syncthreads();
    if (kg == 0) {
#pragma unroll
        for (int h = 0; h < NHEAD; h++) {
            float v = acc[h] + red[h][t & 127];
            Y[((size_t)n * NHEAD + h) * DMODEL + e] = v;
        }
    }
}

// pooled[n][d] = sum_e Wo[d,e] * Y[n,h(d),e] + bo[d]*sw[n,h(d)]; grid (Nb,3)
__global__ __launch_bounds__(256) void proj_out(
    const float* __restrict__ Y, const float* __restrict__ SW,
    const float* __restrict__ Wo, const float* __restrict__ bo,
    float* __restrict__ out)
{
    __shared__ __align__(16) float ys[4 * DMODEL];   // 4 heads per d-range of 256
    __shared__ float sws[NHEAD];
    const int n = blockIdx.x, db = blockIdx.y;
    const int t = threadIdx.x;
    const int d = db * 256 + t;
    const int h0 = db * 4;           // heads h0..h0+3 cover this d-range
    for (int i = t; i < 4 * DMODEL; i += 256)
        ys[i] = Y[((size_t)n * NHEAD + h0) * DMODEL + i];
    if (t < NHEAD) sws[t] = SW[n * NHEAD + t];
    __syncthreads();

    const int h = d >> 6;
    const float* wr = Wo + (size_t)d * DMODEL;
    const float* yr = ys + (h - h0) * DMODEL;
    float acc = 0.0f;
#pragma unroll 4
    for (int e = 0; e < DMODEL; e += 4) {
        float4 wv = *(const float4*)&wr[e];
        acc = fmaf(wv.x, yr[e],     acc);
        acc = fmaf(wv.y, yr[e + 1], acc);
        acc = fmaf(wv.z, yr[e + 2], acc);
        acc = fmaf(wv.w, yr[e + 3], acc);
    }
    out[(size_t)n * DMODEL + d] = acc + bo[d] * sws[h];
}

// ---------------------------------------------------------------------------
extern "C" void kernel_launch(void* const* d_in, const int* in_sizes, int n_in,
                              void* d_out, int out_size)
{
    const float* tokens  = (const float*)d_in[0];
    const float* ts      = (const float*)d_in[1];
    const float* maskp   = (const float*)d_in[2];
    const float* Wq      = (const float*)d_in[3];
    const float* bq      = (const float*)d_in[4];
    const float* Wk      = (const float*)d_in[5];
    const float* bk      = (const float*)d_in[6];
    const float* Wv      = (const float*)d_in[7];
    const float* bv      = (const float*)d_in[8];
    const float* Wo      = (const float*)d_in[9];
    const float* bo      = (const float*)d_in[10];
    const float* readout = (const float*)d_in[11];
    float* out = (float*)d_out;
    (void)n_in;

    const int M  = in_sizes[0] / DMODEL;   // 32768
    const int Nb = out_size / DMODEL;      // 64
    const int L  = M / Nb;                 // 512

    float *gX, *gbias, *gwt, *gc, *gS, *gY, *gsw;
    __nv_bfloat16 *gth, *gtl, *gwh, *gwl, *gqkvh, *gqkvl;
    cudaGetSymbolAddress((void**)&gX, g_X);
    cudaGetSymbolAddress((void**)&gth, g_th);
    cudaGetSymbolAddress((void**)&gtl, g_tl);
    cudaGetSymbolAddress((void**)&gwh, g_wh);
    cudaGetSymbolAddress((void**)&gwl, g_wl);
    cudaGetSymbolAddress((void**)&gqkvh, g_qkvh);
    cudaGetSymbolAddress((void**)&gqkvl, g_qkvl);
    cudaGetSymbolAddress((void**)&gbias, g_bias);
    cudaGetSymbolAddress((void**)&gwt, g_wt);
    cudaGetSymbolAddress((void**)&gc, g_c);
    cudaGetSymbolAddress((void**)&gS, g_S);
    cudaGetSymbolAddress((void**)&gY, g_Y);
    cudaGetSymbolAddress((void**)&gsw, g_sw);

    cudaMemcpyAsync(gbias,              bq, DMODEL * sizeof(float), cudaMemcpyDeviceToDevice);
    cudaMemcpyAsync(gbias + DMODEL,     bk, DMODEL * sizeof(float), cudaMemcpyDeviceToDevice);
    cudaMemcpyAsync(gbias + 2 * DMODEL, bv, DMODEL * sizeof(float), cudaMemcpyDeviceToDevice);

    const int tok4 = M * DMODEL / 4;
    split_f32<<<(tok4 + 255) / 256, 256>>>(tokens, gth, gtl, tok4);
    const int w4 = WSZ / 4;
    dim3 wg((w4 + 255) / 256, 3);
    split_w<<<wg, 256>>>(Wq, Wk, Wv, gwh, gwl, w4);

    wtilde_kernel<<<NHEAD, 256>>>(Wo, readout, bo, gwt, gc);

    cudaFuncSetAttribute(gemm_tc_split, cudaFuncAttributeMaxDynamicSharedMemorySize, G_SMEM);
    dim3 gqkv(LDQKV / GBN, M / GBM);
    gemm_tc_split<<<gqkv, 256, G_SMEM>>>(gth, gtl, gwh, gwl, gbias,
                                         DMODEL, LDQKV, gqkvh, gqkvl, M, DMODEL);

    cudaFuncSetAttribute(attn_tc, cudaFuncAttributeMaxDynamicSharedMemorySize,
                         A_SMEM_TOTAL);
    dim3 ag(L / 128, NHEAD, Nb);
    attn_tc<<<ag, 256, A_SMEM_TOTAL>>>(gqkvh, gqkvl, ts, maskp, gX, L);

    score_kernel<<<512, 256>>>(gX, gwt, gc, maskp, gS, M);
    pool_softmax<<<Nb, 256>>>(gS, maskp, gsw, L);
    dim3 yg(Nb, DMODEL / 128);
    pool_y<<<yg, 256>>>(gX, gS, gY, L);
    dim3 pgo(Nb, 3);
    proj_out<<<pgo, 256>>>(gY, gsw, Wo, bo, out);
}